// round 1
// baseline (speedup 1.0000x reference)
#include <cuda_runtime.h>
#include <math.h>
#include <stdint.h>

#define Bv 4
#define Sv 2048
#define Fv 128
#define Hv 4
#define Dv 128
#define HDv 512
#define OUTv 128
#define BHv 16
#define NSv (BHv*Sv)   /* 32768 rows (b,h,s) */
#define NEG 0.01f

// ---- device scratch (allocation-free rule: __device__ globals) ----
__device__ float g_hp[NSv*Dv];        // hp[b,h,s,d]
__device__ float g_ctx[Bv*Sv*HDv];    // ctx[b,s,h*D+d]
__device__ float g_e1[NSv];
__device__ float g_e2[NSv];
__device__ float g_An[NSv];
__device__ float g_Bn[NSv];
__device__ float g_th[NSv];
__device__ float g_E2p[NSv];
__device__ float g_E2n[NSv];
__device__ int   g_masked[Bv*Sv];

// ---------------------------------------------------------------
// K0: decode mask buffer (dtype-robust: u8 vs i32 detected by byte sum)
// ---------------------------------------------------------------
__global__ void k_mask(const void* mraw) {
    __shared__ int ssum[256];
    __shared__ int fmt;
    const unsigned char* mb = (const unsigned char*)mraw;
    int tid = threadIdx.x;
    int s = 0;
    for (int i = tid; i < Bv*Sv; i += 256) s += mb[i];
    ssum[tid] = s;
    __syncthreads();
    for (int st = 128; st > 0; st >>= 1) {
        if (tid < st) ssum[tid] += ssum[tid + st];
        __syncthreads();
    }
    if (tid == 0) fmt = (ssum[0] > (Bv*Sv*5/16)) ? 1 : 0;  // ~4096 (u8) vs ~1024 (i32)
    __syncthreads();
    if (fmt) {
        for (int i = tid; i < Bv*Sv; i += 256) g_masked[i] = (mb[i] != 0);
    } else {
        const int* mi = (const int*)mraw;
        for (int i = tid; i < Bv*Sv; i += 256) g_masked[i] = (mi[i] != 0);
    }
}

// ---------------------------------------------------------------
// K1: hp = h @ W_w^T + W_b, written as hp[b,h,s,d]
// C[M=8192, N=512], K=128. 64x64 tiles, 256 threads, 4x4 micro.
// ---------------------------------------------------------------
__global__ __launch_bounds__(256) void k_gemm1(const float* __restrict__ A,
                                               const float* __restrict__ W,
                                               const float* __restrict__ bias) {
    __shared__ float As[64][129];
    __shared__ float Ws[64][129];
    const int m0 = blockIdx.x * 64;
    const int n0 = blockIdx.y * 64;
    const int tid = threadIdx.x;

    for (int i = tid; i < 64*32; i += 256) {      // 2048 float4 per tile
        int r = i >> 5, c4 = (i & 31) << 2;
        float4 va = *(const float4*)(A + (size_t)(m0+r)*Fv + c4);
        As[r][c4+0]=va.x; As[r][c4+1]=va.y; As[r][c4+2]=va.z; As[r][c4+3]=va.w;
        float4 vw = *(const float4*)(W + (size_t)(n0+r)*Fv + c4);
        Ws[r][c4+0]=vw.x; Ws[r][c4+1]=vw.y; Ws[r][c4+2]=vw.z; Ws[r][c4+3]=vw.w;
    }
    __syncthreads();

    const int tm = tid >> 4, tn = tid & 15;
    const int mm = tm << 2, nn = tn << 2;
    float acc[4][4] = {};
    #pragma unroll 4
    for (int k = 0; k < Fv; k++) {
        float a0=As[mm+0][k], a1=As[mm+1][k], a2=As[mm+2][k], a3=As[mm+3][k];
        float b0=Ws[nn+0][k], b1=Ws[nn+1][k], b2=Ws[nn+2][k], b3=Ws[nn+3][k];
        acc[0][0]+=a0*b0; acc[0][1]+=a0*b1; acc[0][2]+=a0*b2; acc[0][3]+=a0*b3;
        acc[1][0]+=a1*b0; acc[1][1]+=a1*b1; acc[1][2]+=a1*b2; acc[1][3]+=a1*b3;
        acc[2][0]+=a2*b0; acc[2][1]+=a2*b1; acc[2][2]+=a2*b2; acc[2][3]+=a2*b3;
        acc[3][0]+=a3*b0; acc[3][1]+=a3*b1; acc[3][2]+=a3*b2; acc[3][3]+=a3*b3;
    }
    #pragma unroll
    for (int i = 0; i < 4; i++) {
        int m = m0 + mm + i;
        int bb = m >> 11, s = m & (Sv-1);
        #pragma unroll
        for (int j = 0; j < 4; j++) {
            int n = n0 + nn + j;
            int h = n >> 7, d = n & (Dv-1);
            g_hp[(((size_t)(bb*Hv + h))*Sv + s)*Dv + d] = acc[i][j] + bias[n];
        }
    }
}

// ---------------------------------------------------------------
// K2a: e1,e2 per row (warp per row)
// ---------------------------------------------------------------
__global__ __launch_bounds__(256) void k_e12(const float* __restrict__ aw) {
    int row  = blockIdx.x * 8 + (threadIdx.x >> 5);
    int lane = threadIdx.x & 31;
    float4 v  = *(const float4*)(g_hp + (size_t)row*Dv + lane*4);
    float4 w1 = *(const float4*)(aw + lane*4);
    float4 w2 = *(const float4*)(aw + Dv + lane*4);
    float s1 = v.x*w1.x + v.y*w1.y + v.z*w1.z + v.w*w1.w;
    float s2 = v.x*w2.x + v.y*w2.y + v.z*w2.z + v.w*w2.w;
    #pragma unroll
    for (int o = 16; o; o >>= 1) {
        s1 += __shfl_xor_sync(0xffffffffu, s1, o);
        s2 += __shfl_xor_sync(0xffffffffu, s2, o);
    }
    if (lane == 0) { g_e1[row] = s1; g_e2[row] = s2; }
}

// ---------------------------------------------------------------
// K2b: per (b,h): exp tables, bitonic sort of e2, prefix/suffix sums,
//      per-row rowsum via binary search -> pre-normalized An, Bn.
// ---------------------------------------------------------------
__global__ __launch_bounds__(1024) void k_prep(const float* __restrict__ ab_p) {
    __shared__ float key[Sv];
    __shared__ float v1[Sv];
    __shared__ float v2[Sv];
    __shared__ float pren[Sv+1];
    __shared__ float sufp[Sv+1];
    __shared__ float red[1024];
    __shared__ float ch1[64], ch2[64];

    const int bh = blockIdx.x;
    const int b  = bh >> 2;
    const int tid = threadIdx.x;
    const float ab = ab_p[0];

    float lmax = -1e30f;
    for (int j = tid; j < Sv; j += 1024) {
        float e2 = g_e2[bh*Sv + j];
        int msk = g_masked[b*Sv + j];
        float ep = msk ? 0.f : expf(e2);
        float en = msk ? 0.f : expf(NEG*e2);
        g_E2p[bh*Sv + j] = ep;
        g_E2n[bh*Sv + j] = en;
        key[j] = e2; v1[j] = ep; v2[j] = en;
        if (!msk && e2 > lmax) lmax = e2;
    }
    red[tid] = lmax;
    __syncthreads();
    for (int st = 512; st; st >>= 1) {
        if (tid < st) red[tid] = fmaxf(red[tid], red[tid+st]);
        __syncthreads();
    }
    const float M2 = red[0];
    __syncthreads();

    // bitonic sort ascending by key (masked entries carry 0 values; position irrelevant)
    for (int k = 2; k <= Sv; k <<= 1) {
        for (int j = k >> 1; j > 0; j >>= 1) {
            for (int i = tid; i < Sv; i += 1024) {
                int ixj = i ^ j;
                if (ixj > i) {
                    bool up = ((i & k) == 0);
                    float ki = key[i], kj = key[ixj];
                    if ((ki > kj) == up) {
                        key[i] = kj; key[ixj] = ki;
                        float t;
                        t = v1[i]; v1[i] = v1[ixj]; v1[ixj] = t;
                        t = v2[i]; v2[i] = v2[ixj]; v2[ixj] = t;
                    }
                }
            }
            __syncthreads();
        }
    }

    // two-level scans: pren = exclusive prefix of v2, sufp = inclusive suffix of v1
    if (tid < 64) {
        int base = tid * 32;
        float s1 = 0.f, s2 = 0.f;
        for (int t = 0; t < 32; t++) { s1 += v1[base+t]; s2 += v2[base+t]; }
        ch1[tid] = s1; ch2[tid] = s2;
    }
    __syncthreads();
    if (tid == 0) {
        float r = 0.f;
        for (int c = 0; c < 64; c++) { float t = ch2[c]; ch2[c] = r; r += t; }
        pren[Sv] = r;
        r = 0.f;
        for (int c = 63; c >= 0; c--) { float t = ch1[c]; ch1[c] = r; r += t; }
    }
    __syncthreads();
    if (tid < 64) {
        int base = tid * 32;
        float run = ch2[tid];
        for (int t = 0; t < 32; t++) { pren[base+t] = run; run += v2[base+t]; }
        float runs = ch1[tid];
        for (int t = 31; t >= 0; t--) { runs += v1[base+t]; sufp[base+t] = runs; }
    }
    if (tid == 0) sufp[Sv] = 0.f;
    __syncthreads();

    for (int i = tid; i < Sv; i += 1024) {
        float e1 = g_e1[bh*Sv + i];
        float eb = e1 + ab;
        float pre = eb + M2;
        float m = (pre > 0.f) ? pre : NEG*pre;      // exact row max (lrelu monotone)
        float th = -eb;
        float A  = expf(eb - m);
        float Bc = expf(NEG*eb - m);
        int lo = 0, hi = Sv;
        while (lo < hi) {                            // first idx with key > th
            int mid = (lo + hi) >> 1;
            if (key[mid] <= th) lo = mid + 1; else hi = mid;
        }
        float rowsum = A*sufp[lo] + Bc*pren[lo];
        float inv = 1.0f / rowsum;
        g_An[bh*Sv + i] = A * inv;
        g_Bn[bh*Sv + i] = Bc * inv;
        g_th[bh*Sv + i] = th;
    }
}

// ---------------------------------------------------------------
// K3: fused attn-write + ctx accumulation. Block = 64 i-rows of one (b,h).
// Loops j in tiles of 32; p computed once, written normalized, FMA'd.
// ---------------------------------------------------------------
__global__ __launch_bounds__(256) void k_attn(float* __restrict__ attn_out) {
    __shared__ float hps[32][128];   // 16 KB
    __shared__ float ps[64][32];     //  8 KB
    __shared__ float sAn[64], sBn[64], sTh[64];
    __shared__ float se2[32], sEp[32], sEn[32];

    const int bh = blockIdx.y;
    const int i0 = blockIdx.x * 64;
    const int tid = threadIdx.x;
    const int rowbase = bh*Sv + i0;

    if (tid < 64) {
        sAn[tid] = g_An[rowbase + tid];
        sBn[tid] = g_Bn[rowbase + tid];
        sTh[tid] = g_th[rowbase + tid];
    }
    const int td = tid & 31;   // col group: cols td*4 .. td*4+3
    const int ti = tid >> 5;   // row group: rows ti*8 .. ti*8+7
    float acc[8][4] = {};
    float* attn_row = attn_out + (size_t)rowbase * Sv;

    for (int jt = 0; jt < Sv; jt += 32) {
        const float* hpsrc = g_hp + ((size_t)bh*Sv + jt)*Dv;
        #pragma unroll
        for (int q = 0; q < 4; q++) {
            int idx = tid + q*256;          // 1024 float4 = 32x128
            int r = idx >> 5, c4 = (idx & 31) << 2;
            *(float4*)&hps[r][c4] = *(const float4*)(hpsrc + (size_t)r*Dv + c4);
        }
        if (tid < 32) {
            se2[tid] = g_e2[bh*Sv + jt + tid];
            sEp[tid] = g_E2p[bh*Sv + jt + tid];
            sEn[tid] = g_E2n[bh*Sv + jt + tid];
        }
        __syncthreads();

        #pragma unroll
        for (int q = 0; q < 8; q++) {
            int idx = tid + q*256;          // 2048 = 64x32
            int r = idx >> 5, j = idx & 31;
            float p = (se2[j] > sTh[r]) ? sAn[r]*sEp[j] : sBn[r]*sEn[j];
            ps[r][j] = p;
            attn_row[(size_t)r*Sv + jt + j] = p;   // already normalized
        }
        __syncthreads();

        #pragma unroll
        for (int j = 0; j < 32; j++) {
            float4 hv = *(const float4*)&hps[j][td*4];
            #pragma unroll
            for (int rr = 0; rr < 8; rr++) {
                float p = ps[ti*8 + rr][j];
                acc[rr][0] += p*hv.x; acc[rr][1] += p*hv.y;
                acc[rr][2] += p*hv.z; acc[rr][3] += p*hv.w;
            }
        }
        __syncthreads();
    }

    const int b = bh >> 2, h = bh & 3;
    #pragma unroll
    for (int rr = 0; rr < 8; rr++) {
        int i = i0 + ti*8 + rr;
        float4 v = make_float4(acc[rr][0], acc[rr][1], acc[rr][2], acc[rr][3]);
        *(float4*)(g_ctx + ((size_t)(b*Sv + i))*HDv + h*Dv + td*4) = v;
    }
}

// ---------------------------------------------------------------
// K4: out = relu(ctx @ out_w^T + out_b). M=8192, N=128, K=512.
// ---------------------------------------------------------------
__global__ __launch_bounds__(256) void k_gemm2(const float* __restrict__ W,
                                               const float* __restrict__ bias,
                                               float* __restrict__ out) {
    __shared__ float As[64][65];
    __shared__ float Ws[64][65];
    const int m0 = blockIdx.x * 64;
    const int n0 = blockIdx.y * 64;
    const int tid = threadIdx.x;
    const int tm = tid >> 4, tn = tid & 15;
    const int mm = tm << 2, nn = tn << 2;
    float acc[4][4] = {};

    for (int kk = 0; kk < HDv; kk += 64) {
        for (int i = tid; i < 64*16; i += 256) {    // 1024 float4 per tile
            int r = i >> 4, c4 = (i & 15) << 2;
            float4 va = *(const float4*)(g_ctx + (size_t)(m0+r)*HDv + kk + c4);
            As[r][c4+0]=va.x; As[r][c4+1]=va.y; As[r][c4+2]=va.z; As[r][c4+3]=va.w;
            float4 vw = *(const float4*)(W + (size_t)(n0+r)*HDv + kk + c4);
            Ws[r][c4+0]=vw.x; Ws[r][c4+1]=vw.y; Ws[r][c4+2]=vw.z; Ws[r][c4+3]=vw.w;
        }
        __syncthreads();
        #pragma unroll 4
        for (int k = 0; k < 64; k++) {
            float a0=As[mm+0][k], a1=As[mm+1][k], a2=As[mm+2][k], a3=As[mm+3][k];
            float b0=Ws[nn+0][k], b1=Ws[nn+1][k], b2=Ws[nn+2][k], b3=Ws[nn+3][k];
            acc[0][0]+=a0*b0; acc[0][1]+=a0*b1; acc[0][2]+=a0*b2; acc[0][3]+=a0*b3;
            acc[1][0]+=a1*b0; acc[1][1]+=a1*b1; acc[1][2]+=a1*b2; acc[1][3]+=a1*b3;
            acc[2][0]+=a2*b0; acc[2][1]+=a2*b1; acc[2][2]+=a2*b2; acc[2][3]+=a2*b3;
            acc[3][0]+=a3*b0; acc[3][1]+=a3*b1; acc[3][2]+=a3*b2; acc[3][3]+=a3*b3;
        }
        __syncthreads();
    }
    #pragma unroll
    for (int i = 0; i < 4; i++) {
        int m = m0 + mm + i;
        #pragma unroll
        for (int j = 0; j < 4; j++) {
            int n = n0 + nn + j;
            float v = acc[i][j] + bias[n];
            out[(size_t)m*OUTv + n] = v > 0.f ? v : 0.f;
        }
    }
}

// ---------------------------------------------------------------
extern "C" void kernel_launch(void* const* d_in, const int* in_sizes, int n_in,
                              void* d_out, int out_size) {
    const float* h     = (const float*)d_in[0];
    const void*  mask  = d_in[1];
    const float* W_w   = (const float*)d_in[2];
    const float* W_b   = (const float*)d_in[3];
    const float* a_w   = (const float*)d_in[4];
    const float* a_b   = (const float*)d_in[5];
    const float* out_w = (const float*)d_in[6];
    const float* out_b = (const float*)d_in[7];

    float* out  = (float*)d_out;
    float* attn = out + (size_t)Bv*Sv*OUTv;

    k_mask <<<1, 256>>>(mask);
    k_gemm1<<<dim3(128, 8), 256>>>(h, W_w, W_b);
    k_e12  <<<NSv/8, 256>>>(a_w);
    k_prep <<<BHv, 1024>>>(a_b);
    k_attn <<<dim3(Sv/64, BHv), 256>>>(attn);
    k_gemm2<<<dim3(128, 2), 256>>>(out_w, out_b, out);
}

// round 3
// speedup vs baseline: 1.2883x; 1.2883x over previous
#include <cuda_runtime.h>
#include <cuda_bf16.h>
#include <math.h>
#include <stdint.h>

#define Bv 4
#define Sv 2048
#define Fv 128
#define Hv 4
#define Dv 128
#define HDv 512
#define OUTv 128
#define BHv 16
#define NSv (BHv*Sv)
#define NEG 0.01f
#define LDT 40   /* padded bf16 row stride for ldmatrix tiles */

// ---- device scratch ----
__device__ float g_hp[NSv*Dv];
__device__ float g_ctx[Bv*Sv*HDv];
__device__ float g_e1[NSv];
__device__ float g_e2[NSv];
__device__ float g_An[NSv];
__device__ float g_Bn[NSv];
__device__ float g_th[NSv];
__device__ float g_E2p[NSv];
__device__ float g_E2n[NSv];
__device__ int   g_masked[Bv*Sv];
// hp transposed+chunked: [bh][s/32][d][s%32], bf16 hi/lo
__device__ __nv_bfloat16 g_hpT_hi[BHv*Dv*Sv];
__device__ __nv_bfloat16 g_hpT_lo[BHv*Dv*Sv];

__device__ __forceinline__ uint32_t smem_u32(const void* p) {
    uint32_t a;
    asm("{ .reg .u64 t; cvta.to.shared.u64 t, %1; cvt.u32.u64 %0, t; }" : "=r"(a) : "l"(p));
    return a;
}
#define LDMX4(r0,r1,r2,r3,addr) \
    asm volatile("ldmatrix.sync.aligned.m8n8.x4.shared.b16 {%0,%1,%2,%3}, [%4];" \
        : "=r"(r0),"=r"(r1),"=r"(r2),"=r"(r3) : "r"(addr))
#define MMA16816(c,a0,a1,a2,a3,b0,b1) \
    asm volatile("mma.sync.aligned.m16n8k16.row.col.f32.bf16.bf16.f32 " \
        "{%0,%1,%2,%3}, {%4,%5,%6,%7}, {%8,%9}, {%0,%1,%2,%3};" \
        : "+f"((c)[0]),"+f"((c)[1]),"+f"((c)[2]),"+f"((c)[3]) \
        : "r"(a0),"r"(a1),"r"(a2),"r"(a3), "r"(b0),"r"(b1))

// ---------------------------------------------------------------
// K0: decode mask buffer (u8 vs i32 by byte sum)
// ---------------------------------------------------------------
__global__ void k_mask(const void* mraw) {
    __shared__ int ssum[256];
    __shared__ int fmt;
    const unsigned char* mb = (const unsigned char*)mraw;
    int tid = threadIdx.x;
    int s = 0;
    for (int i = tid; i < Bv*Sv; i += 256) s += mb[i];
    ssum[tid] = s;
    __syncthreads();
    for (int st = 128; st > 0; st >>= 1) {
        if (tid < st) ssum[tid] += ssum[tid + st];
        __syncthreads();
    }
    if (tid == 0) fmt = (ssum[0] > (Bv*Sv*5/16)) ? 1 : 0;
    __syncthreads();
    if (fmt) {
        for (int i = tid; i < Bv*Sv; i += 256) g_masked[i] = (mb[i] != 0);
    } else {
        const int* mi = (const int*)mraw;
        for (int i = tid; i < Bv*Sv; i += 256) g_masked[i] = (mi[i] != 0);
    }
}

// ---------------------------------------------------------------
// K1: hp = h @ W_w^T + W_b  -> g_hp[b,h,s,d] f32 + hpT hi/lo chunked
// ---------------------------------------------------------------
__global__ __launch_bounds__(256) void k_gemm1(const float* __restrict__ A,
                                               const float* __restrict__ W,
                                               const float* __restrict__ bias) {
    __shared__ float As[64][129];
    __shared__ float Ws[64][129];
    const int m0 = blockIdx.x * 64;
    const int n0 = blockIdx.y * 64;
    const int tid = threadIdx.x;

    for (int i = tid; i < 64*32; i += 256) {
        int r = i >> 5, c4 = (i & 31) << 2;
        float4 va = *(const float4*)(A + (size_t)(m0+r)*Fv + c4);
        As[r][c4+0]=va.x; As[r][c4+1]=va.y; As[r][c4+2]=va.z; As[r][c4+3]=va.w;
        float4 vw = *(const float4*)(W + (size_t)(n0+r)*Fv + c4);
        Ws[r][c4+0]=vw.x; Ws[r][c4+1]=vw.y; Ws[r][c4+2]=vw.z; Ws[r][c4+3]=vw.w;
    }
    __syncthreads();

    const int tm = tid >> 4, tn = tid & 15;
    const int mm = tm << 2, nn = tn << 2;
    float acc[4][4] = {};
    #pragma unroll 4
    for (int k = 0; k < Fv; k++) {
        float a0=As[mm+0][k], a1=As[mm+1][k], a2=As[mm+2][k], a3=As[mm+3][k];
        float b0=Ws[nn+0][k], b1=Ws[nn+1][k], b2=Ws[nn+2][k], b3=Ws[nn+3][k];
        acc[0][0]+=a0*b0; acc[0][1]+=a0*b1; acc[0][2]+=a0*b2; acc[0][3]+=a0*b3;
        acc[1][0]+=a1*b0; acc[1][1]+=a1*b1; acc[1][2]+=a1*b2; acc[1][3]+=a1*b3;
        acc[2][0]+=a2*b0; acc[2][1]+=a2*b1; acc[2][2]+=a2*b2; acc[2][3]+=a2*b3;
        acc[3][0]+=a3*b0; acc[3][1]+=a3*b1; acc[3][2]+=a3*b2; acc[3][3]+=a3*b3;
    }
    #pragma unroll
    for (int i = 0; i < 4; i++) {
        int m = m0 + mm + i;
        int bb = m >> 11, s = m & (Sv-1);
        #pragma unroll
        for (int j = 0; j < 4; j++) {
            int n = n0 + nn + j;
            int h = n >> 7, d = n & (Dv-1);
            float v = acc[i][j] + bias[n];
            int bh = bb*Hv + h;
            g_hp[(((size_t)bh)*Sv + s)*Dv + d] = v;
            __nv_bfloat16 hi = __float2bfloat16_rn(v);
            __nv_bfloat16 lo = __float2bfloat16_rn(v - __bfloat162float(hi));
            size_t tix = (((size_t)bh*(Sv/32) + (s>>5))*Dv + d)*32 + (s&31);
            g_hpT_hi[tix] = hi;
            g_hpT_lo[tix] = lo;
        }
    }
}

// ---------------------------------------------------------------
// K2a: e1,e2 per row + exp tables
// ---------------------------------------------------------------
__global__ __launch_bounds__(256) void k_e12(const float* __restrict__ aw) {
    int row  = blockIdx.x * 8 + (threadIdx.x >> 5);
    int lane = threadIdx.x & 31;
    float4 v  = *(const float4*)(g_hp + (size_t)row*Dv + lane*4);
    float4 w1 = *(const float4*)(aw + lane*4);
    float4 w2 = *(const float4*)(aw + Dv + lane*4);
    float s1 = v.x*w1.x + v.y*w1.y + v.z*w1.z + v.w*w1.w;
    float s2 = v.x*w2.x + v.y*w2.y + v.z*w2.z + v.w*w2.w;
    #pragma unroll
    for (int o = 16; o; o >>= 1) {
        s1 += __shfl_xor_sync(0xffffffffu, s1, o);
        s2 += __shfl_xor_sync(0xffffffffu, s2, o);
    }
    if (lane == 0) {
        g_e1[row] = s1; g_e2[row] = s2;
        int b = row >> 13, s = row & (Sv-1);
        int msk = g_masked[b*Sv + s];
        g_E2p[row] = msk ? 0.f : expf(s2);
        g_E2n[row] = msk ? 0.f : expf(NEG*s2);
    }
}

// ---------------------------------------------------------------
// K2b: per (b,h): key-only bitonic sort, exp post-sort, scans,
//      per-row binary search -> normalized An,Bn.
// ---------------------------------------------------------------
__global__ __launch_bounds__(1024) void k_prep(const float* __restrict__ ab_p) {
    __shared__ float key[Sv];
    __shared__ float v1[Sv];
    __shared__ float v2[Sv];
    __shared__ float pren[Sv+1];
    __shared__ float sufp[Sv+1];
    __shared__ float ch1[64], ch2[64];

    const int bh = blockIdx.x;
    const int b  = bh >> 2;
    const int tid = threadIdx.x;
    const float ab = ab_p[0];

    for (int j = tid; j < Sv; j += 1024) {
        float e2 = g_e2[bh*Sv + j];
        key[j] = g_masked[b*Sv + j] ? -1e30f : e2;
    }
    __syncthreads();

    for (int k = 2; k <= Sv; k <<= 1) {
        for (int j = k >> 1; j > 0; j >>= 1) {
            #pragma unroll 2
            for (int i = tid; i < Sv; i += 1024) {
                int ixj = i ^ j;
                if (ixj > i) {
                    bool up = ((i & k) == 0);
                    float ki = key[i], kj = key[ixj];
                    if ((ki > kj) == up) { key[i] = kj; key[ixj] = ki; }
                }
            }
            __syncthreads();
        }
    }

    const float M2 = key[Sv-1];
    for (int j = tid; j < Sv; j += 1024) {
        float kk = key[j];
        v1[j] = expf(kk);
        v2[j] = expf(NEG*kk);
    }
    __syncthreads();

    if (tid < 64) {
        int base = tid * 32;
        float s1 = 0.f, s2 = 0.f;
        for (int t = 0; t < 32; t++) { s1 += v1[base+t]; s2 += v2[base+t]; }
        ch1[tid] = s1; ch2[tid] = s2;
    }
    __syncthreads();
    if (tid == 0) {
        float r = 0.f;
        for (int c = 0; c < 64; c++) { float t = ch2[c]; ch2[c] = r; r += t; }
        pren[Sv] = r;
        r = 0.f;
        for (int c = 63; c >= 0; c--) { float t = ch1[c]; ch1[c] = r; r += t; }
    }
    __syncthreads();
    if (tid < 64) {
        int base = tid * 32;
        float run = ch2[tid];
        for (int t = 0; t < 32; t++) { pren[base+t] = run; run += v2[base+t]; }
        float runs = ch1[tid];
        for (int t = 31; t >= 0; t--) { runs += v1[base+t]; sufp[base+t] = runs; }
    }
    if (tid == 0) sufp[Sv] = 0.f;
    __syncthreads();

    for (int i = tid; i < Sv; i += 1024) {
        float e1 = g_e1[bh*Sv + i];
        float eb = e1 + ab;
        float pre = eb + M2;
        float m = (pre > 0.f) ? pre : NEG*pre;
        float th = -eb;
        float A  = expf(eb - m);
        float Bc = expf(NEG*eb - m);
        int lo = 0, hi = Sv;
        while (lo < hi) {
            int mid = (lo + hi) >> 1;
            if (key[mid] <= th) lo = mid + 1; else hi = mid;
        }
        float rowsum = A*sufp[lo] + Bc*pren[lo];
        float inv = 1.0f / rowsum;
        g_An[bh*Sv + i] = A * inv;
        g_Bn[bh*Sv + i] = Bc * inv;
        g_th[bh*Sv + i] = th;
    }
}

// ---------------------------------------------------------------
// K3: mma.sync bf16 3-split fused attn-write + ctx.
// Block = 128 i-rows x D=128 of one (b,h). 8 warps, each 16 rows.
// ---------------------------------------------------------------
__global__ __launch_bounds__(256) void k_attn(float* __restrict__ attn_out) {
    __shared__ __nv_bfloat16 Ahi[128][LDT];
    __shared__ __nv_bfloat16 Alo[128][LDT];
    __shared__ __nv_bfloat16 Bhi[128][LDT];
    __shared__ __nv_bfloat16 Blo[128][LDT];
    __shared__ float sTh[128], sAn[128], sBn[128];

    const int bh = blockIdx.y;
    const int i0 = blockIdx.x * 128;
    const int tid = threadIdx.x;
    const int w = tid >> 5;
    const int lane = tid & 31;

    if (tid < 128) {
        sTh[tid] = g_th[bh*Sv + i0 + tid];
        sAn[tid] = g_An[bh*Sv + i0 + tid];
        sBn[tid] = g_Bn[bh*Sv + i0 + tid];
    }
    __syncthreads();

    // p-compute assignment: rows prow0..prow0+7, col pair j0,j0+1
    const int prow0 = (tid >> 4) * 8;
    const int j0 = (tid & 15) * 2;
    float th[8], An[8], Bn[8];
    #pragma unroll
    for (int rr = 0; rr < 8; rr++) {
        th[rr] = sTh[prow0+rr]; An[rr] = sAn[prow0+rr]; Bn[rr] = sBn[prow0+rr];
    }

    // ldmatrix source addresses
    const uint32_t aAddrHi = smem_u32(&Ahi[w*16 + (lane & 15)][(lane >> 4) * 8]);
    const uint32_t aAddrLo = smem_u32(&Alo[w*16 + (lane & 15)][(lane >> 4) * 8]);
    const int brow = (lane & 7) + ((lane >> 4) << 3);
    const int bcol = ((lane >> 3) & 1) * 8;

    float c[16][4] = {};
    float* attn_base = attn_out + ((size_t)(bh*Sv + i0)) * Sv;

    #pragma unroll 1
    for (int jt = 0; jt < Sv; jt += 32) {
        __syncthreads();   // previous MMA phase done with smem

        // ---- load hp hi/lo tile (contiguous 8KB each) ----
        {
            const size_t cb = (((size_t)bh*(Sv/32) + (jt>>5)) * Dv) * 32;
            #pragma unroll
            for (int q = 0; q < 2; q++) {
                int cidx = tid + q*256;        // 512 chunks of 16B
                int d = cidx >> 2, s8 = (cidx & 3) * 8;
                *(uint4*)&Bhi[d][s8] = *(const uint4*)(g_hpT_hi + cb + d*32 + s8);
                *(uint4*)&Blo[d][s8] = *(const uint4*)(g_hpT_lo + cb + d*32 + s8);
            }
        }

        // ---- compute P, write attn fp32 + smem bf16 hi/lo ----
        {
            float2 e2v = *(const float2*)(g_e2  + bh*Sv + jt + j0);
            float2 epv = *(const float2*)(g_E2p + bh*Sv + jt + j0);
            float2 env = *(const float2*)(g_E2n + bh*Sv + jt + j0);
            #pragma unroll
            for (int rr = 0; rr < 8; rr++) {
                int r = prow0 + rr;
                float p0 = (e2v.x > th[rr]) ? An[rr]*epv.x : Bn[rr]*env.x;
                float p1 = (e2v.y > th[rr]) ? An[rr]*epv.y : Bn[rr]*env.y;
                *(float2*)(attn_base + (size_t)r*Sv + jt + j0) = make_float2(p0, p1);
                __nv_bfloat16 h0 = __float2bfloat16_rn(p0);
                __nv_bfloat16 h1 = __float2bfloat16_rn(p1);
                __nv_bfloat16 l0 = __float2bfloat16_rn(p0 - __bfloat162float(h0));
                __nv_bfloat16 l1 = __float2bfloat16_rn(p1 - __bfloat162float(h1));
                *(uint32_t*)&Ahi[r][j0] = ((uint32_t)__bfloat16_as_ushort(h1) << 16) | __bfloat16_as_ushort(h0);
                *(uint32_t*)&Alo[r][j0] = ((uint32_t)__bfloat16_as_ushort(l1) << 16) | __bfloat16_as_ushort(l0);
            }
        }
        __syncthreads();

        // ---- MMA phase: 2 k-steps x 8 ntile-pairs x 3 splits ----
        #pragma unroll
        for (int ks = 0; ks < 2; ks++) {
            uint32_t ah0,ah1,ah2,ah3, al0,al1,al2,al3;
            LDMX4(ah0,ah1,ah2,ah3, aAddrHi + ks*32);   // 16 bf16 cols = 32B
            LDMX4(al0,al1,al2,al3, aAddrLo + ks*32);
            #pragma unroll
            for (int np = 0; np < 8; np++) {
                uint32_t bh0,bh1,bh2,bh3, bl0,bl1,bl2,bl3;
                uint32_t ba = smem_u32(&Bhi[np*16 + brow][ks*16 + bcol]);
                uint32_t bb = smem_u32(&Blo[np*16 + brow][ks*16 + bcol]);
                LDMX4(bh0,bh1,bh2,bh3, ba);
                LDMX4(bl0,bl1,bl2,bl3, bb);
                MMA16816(c[np*2],   ah0,ah1,ah2,ah3, bh0,bh1);
                MMA16816(c[np*2],   al0,al1,al2,al3, bh0,bh1);
                MMA16816(c[np*2],   ah0,ah1,ah2,ah3, bl0,bl1);
                MMA16816(c[np*2+1], ah0,ah1,ah2,ah3, bh2,bh3);
                MMA16816(c[np*2+1], al0,al1,al2,al3, bh2,bh3);
                MMA16816(c[np*2+1], ah0,ah1,ah2,ah3, bl2,bl3);
            }
        }
    }

    // ---- epilogue: C frags -> g_ctx ----
    {
        const int b = bh >> 2, h = bh & 3;
        const int g = lane >> 2, tg = lane & 3;
        const int i = i0 + w*16 + g;
        #pragma unroll
        for (int nt = 0; nt < 16; nt++) {
            int d = nt*8 + tg*2;
            float* p0 = g_ctx + ((size_t)(b*Sv + i))*HDv + h*Dv + d;
            p0[0] = c[nt][0]; p0[1] = c[nt][1];
            float* p1 = g_ctx + ((size_t)(b*Sv + i + 8))*HDv + h*Dv + d;
            p1[0] = c[nt][2]; p1[1] = c[nt][3];
        }
    }
}

// ---------------------------------------------------------------
// K4: out = relu(ctx @ out_w^T + out_b)
// ---------------------------------------------------------------
__global__ __launch_bounds__(256) void k_gemm2(const float* __restrict__ W,
                                               const float* __restrict__ bias,
                                               float* __restrict__ out) {
    __shared__ float As[64][65];
    __shared__ float Ws[64][65];
    const int m0 = blockIdx.x * 64;
    const int n0 = blockIdx.y * 64;
    const int tid = threadIdx.x;
    const int tm = tid >> 4, tn = tid & 15;
    const int mm = tm << 2, nn = tn << 2;
    float acc[4][4] = {};

    for (int kk = 0; kk < HDv; kk += 64) {
        for (int i = tid; i < 64*16; i += 256) {
            int r = i >> 4, c4 = (i & 15) << 2;
            float4 va = *(const float4*)(g_ctx + (size_t)(m0+r)*HDv + kk + c4);
            As[r][c4+0]=va.x; As[r][c4+1]=va.y; As[r][c4+2]=va.z; As[r][c4+3]=va.w;
            float4 vw = *(const float4*)(W + (size_t)(n0+r)*HDv + kk + c4);
            Ws[r][c4+0]=vw.x; Ws[r][c4+1]=vw.y; Ws[r][c4+2]=vw.z; Ws[r][c4+3]=vw.w;
        }
        __syncthreads();
        #pragma unroll 4
        for (int k = 0; k < 64; k++) {
            float a0=As[mm+0][k], a1=As[mm+1][k], a2=As[mm+2][k], a3=As[mm+3][k];
            float b0=Ws[nn+0][k], b1=Ws[nn+1][k], b2=Ws[nn+2][k], b3=Ws[nn+3][k];
            acc[0][0]+=a0*b0; acc[0][1]+=a0*b1; acc[0][2]+=a0*b2; acc[0][3]+=a0*b3;
            acc[1][0]+=a1*b0; acc[1][1]+=a1*b1; acc[1][2]+=a1*b2; acc[1][3]+=a1*b3;
            acc[2][0]+=a2*b0; acc[2][1]+=a2*b1; acc[2][2]+=a2*b2; acc[2][3]+=a2*b3;
            acc[3][0]+=a3*b0; acc[3][1]+=a3*b1; acc[3][2]+=a3*b2; acc[3][3]+=a3*b3;
        }
        __syncthreads();
    }
    #pragma unroll
    for (int i = 0; i < 4; i++) {
        int m = m0 + mm + i;
        #pragma unroll
        for (int j = 0; j < 4; j++) {
            int n = n0 + nn + j;
            float v = acc[i][j] + bias[n];
            out[(size_t)m*OUTv + n] = v > 0.f ? v : 0.f;
        }
    }
}

// ---------------------------------------------------------------
extern "C" void kernel_launch(void* const* d_in, const int* in_sizes, int n_in,
                              void* d_out, int out_size) {
    const float* h     = (const float*)d_in[0];
    const void*  mask  = d_in[1];
    const float* W_w   = (const float*)d_in[2];
    const float* W_b   = (const float*)d_in[3];
    const float* a_w   = (const float*)d_in[4];
    const float* a_b   = (const float*)d_in[5];
    const float* out_w = (const float*)d_in[6];
    const float* out_b = (const float*)d_in[7];

    float* out  = (float*)d_out;
    float* attn = out + (size_t)Bv*Sv*OUTv;

    k_mask <<<1, 256>>>(mask);
    k_gemm1<<<dim3(128, 8), 256>>>(h, W_w, W_b);
    k_e12  <<<NSv/8, 256>>>(a_w);
    k_prep <<<BHv, 1024>>>(a_b);
    k_attn <<<dim3(Sv/128, BHv), 256>>>(attn);
    k_gemm2<<<dim3(128, 2), 256>>>(out_w, out_b, out);
}

// round 4
// speedup vs baseline: 1.5993x; 1.2414x over previous
#include <cuda_runtime.h>
#include <cuda_bf16.h>
#include <math.h>
#include <stdint.h>

#define Bv 4
#define Sv 2048
#define Fv 128
#define Hv 4
#define Dv 128
#define HDv 512
#define OUTv 128
#define BHv 16
#define NSv (BHv*Sv)
#define NEG 0.01f

// ---- device scratch ----
__device__ float g_hp[NSv*Dv];
__device__ float g_ctx[Bv*Sv*HDv];
__device__ float g_e1[NSv];
__device__ float g_e2[NSv];
__device__ float g_An[NSv];
__device__ float g_Bn[NSv];
__device__ float g_th[NSv];
__device__ float g_E2p[NSv];
__device__ float g_E2n[NSv];
__device__ int   g_masked[Bv*Sv];
// hp transposed+chunked: [bh][s/32][d][s%32], bf16 hi/lo
__device__ __nv_bfloat16 g_hpT_hi[BHv*Dv*Sv];
__device__ __nv_bfloat16 g_hpT_lo[BHv*Dv*Sv];

__device__ __forceinline__ uint32_t smem_u32(const void* p) {
    uint32_t a;
    asm("{ .reg .u64 t; cvta.to.shared.u64 t, %1; cvt.u32.u64 %0, t; }" : "=r"(a) : "l"(p));
    return a;
}
#define LDMX4(r0,r1,r2,r3,addr) \
    asm volatile("ldmatrix.sync.aligned.m8n8.x4.shared.b16 {%0,%1,%2,%3}, [%4];" \
        : "=r"(r0),"=r"(r1),"=r"(r2),"=r"(r3) : "r"(addr))
#define MMA16816(c,a0,a1,a2,a3,b0,b1) \
    asm volatile("mma.sync.aligned.m16n8k16.row.col.f32.bf16.bf16.f32 " \
        "{%0,%1,%2,%3}, {%4,%5,%6,%7}, {%8,%9}, {%0,%1,%2,%3};" \
        : "+f"((c)[0]),"+f"((c)[1]),"+f"((c)[2]),"+f"((c)[3]) \
        : "r"(a0),"r"(a1),"r"(a2),"r"(a3), "r"(b0),"r"(b1))
#define CP16(dst, src) \
    asm volatile("cp.async.cg.shared.global [%0], [%1], 16;" :: "r"(dst), "l"(src) : "memory")
#define CP_COMMIT() asm volatile("cp.async.commit_group;" ::: "memory")
#define CP_WAIT1()  asm volatile("cp.async.wait_group 1;" ::: "memory")
#define CP_WAIT0()  asm volatile("cp.async.wait_group 0;" ::: "memory")

// ---------------------------------------------------------------
// K0: decode mask buffer (u8 vs i32 by byte sum)
// ---------------------------------------------------------------
__global__ void k_mask(const void* mraw) {
    __shared__ int ssum[256];
    __shared__ int fmt;
    const unsigned char* mb = (const unsigned char*)mraw;
    int tid = threadIdx.x;
    int s = 0;
    for (int i = tid; i < Bv*Sv; i += 256) s += mb[i];
    ssum[tid] = s;
    __syncthreads();
    for (int st = 128; st > 0; st >>= 1) {
        if (tid < st) ssum[tid] += ssum[tid + st];
        __syncthreads();
    }
    if (tid == 0) fmt = (ssum[0] > (Bv*Sv*5/16)) ? 1 : 0;
    __syncthreads();
    if (fmt) {
        for (int i = tid; i < Bv*Sv; i += 256) g_masked[i] = (mb[i] != 0);
    } else {
        const int* mi = (const int*)mraw;
        for (int i = tid; i < Bv*Sv; i += 256) g_masked[i] = (mi[i] != 0);
    }
}

// ---------------------------------------------------------------
// K1: hp = h @ W_w^T + W_b  -> g_hp[b,h,s,d] f32 + hpT hi/lo chunked
// ---------------------------------------------------------------
__global__ __launch_bounds__(256) void k_gemm1(const float* __restrict__ A,
                                               const float* __restrict__ W,
                                               const float* __restrict__ bias) {
    __shared__ float As[64][129];
    __shared__ float Ws[64][129];
    const int m0 = blockIdx.x * 64;
    const int n0 = blockIdx.y * 64;
    const int tid = threadIdx.x;

    for (int i = tid; i < 64*32; i += 256) {
        int r = i >> 5, c4 = (i & 31) << 2;
        float4 va = *(const float4*)(A + (size_t)(m0+r)*Fv + c4);
        As[r][c4+0]=va.x; As[r][c4+1]=va.y; As[r][c4+2]=va.z; As[r][c4+3]=va.w;
        float4 vw = *(const float4*)(W + (size_t)(n0+r)*Fv + c4);
        Ws[r][c4+0]=vw.x; Ws[r][c4+1]=vw.y; Ws[r][c4+2]=vw.z; Ws[r][c4+3]=vw.w;
    }
    __syncthreads();

    const int tm = tid >> 4, tn = tid & 15;
    const int mm = tm << 2, nn = tn << 2;
    float acc[4][4] = {};
    #pragma unroll 4
    for (int k = 0; k < Fv; k++) {
        float a0=As[mm+0][k], a1=As[mm+1][k], a2=As[mm+2][k], a3=As[mm+3][k];
        float b0=Ws[nn+0][k], b1=Ws[nn+1][k], b2=Ws[nn+2][k], b3=Ws[nn+3][k];
        acc[0][0]+=a0*b0; acc[0][1]+=a0*b1; acc[0][2]+=a0*b2; acc[0][3]+=a0*b3;
        acc[1][0]+=a1*b0; acc[1][1]+=a1*b1; acc[1][2]+=a1*b2; acc[1][3]+=a1*b3;
        acc[2][0]+=a2*b0; acc[2][1]+=a2*b1; acc[2][2]+=a2*b2; acc[2][3]+=a2*b3;
        acc[3][0]+=a3*b0; acc[3][1]+=a3*b1; acc[3][2]+=a3*b2; acc[3][3]+=a3*b3;
    }
    #pragma unroll
    for (int i = 0; i < 4; i++) {
        int m = m0 + mm + i;
        int bb = m >> 11, s = m & (Sv-1);
        #pragma unroll
        for (int j = 0; j < 4; j++) {
            int n = n0 + nn + j;
            int h = n >> 7, d = n & (Dv-1);
            float v = acc[i][j] + bias[n];
            int bh = bb*Hv + h;
            g_hp[(((size_t)bh)*Sv + s)*Dv + d] = v;
            __nv_bfloat16 hi = __float2bfloat16_rn(v);
            __nv_bfloat16 lo = __float2bfloat16_rn(v - __bfloat162float(hi));
            size_t tix = (((size_t)bh*(Sv/32) + (s>>5))*Dv + d)*32 + (s&31);
            g_hpT_hi[tix] = hi;
            g_hpT_lo[tix] = lo;
        }
    }
}

// ---------------------------------------------------------------
// K2a: e1,e2 per row + exp tables
// ---------------------------------------------------------------
__global__ __launch_bounds__(256) void k_e12(const float* __restrict__ aw) {
    int row  = blockIdx.x * 8 + (threadIdx.x >> 5);
    int lane = threadIdx.x & 31;
    float4 v  = *(const float4*)(g_hp + (size_t)row*Dv + lane*4);
    float4 w1 = *(const float4*)(aw + lane*4);
    float4 w2 = *(const float4*)(aw + Dv + lane*4);
    float s1 = v.x*w1.x + v.y*w1.y + v.z*w1.z + v.w*w1.w;
    float s2 = v.x*w2.x + v.y*w2.y + v.z*w2.z + v.w*w2.w;
    #pragma unroll
    for (int o = 16; o; o >>= 1) {
        s1 += __shfl_xor_sync(0xffffffffu, s1, o);
        s2 += __shfl_xor_sync(0xffffffffu, s2, o);
    }
    if (lane == 0) {
        g_e1[row] = s1; g_e2[row] = s2;
        int b = row >> 13, s = row & (Sv-1);
        int msk = g_masked[b*Sv + s];
        g_E2p[row] = msk ? 0.f : expf(s2);
        g_E2n[row] = msk ? 0.f : expf(NEG*s2);
    }
}

// ---------------------------------------------------------------
// K2b: per (b,h): key-only bitonic sort, exp post-sort, scans,
//      per-row binary search -> normalized An,Bn.
// ---------------------------------------------------------------
__global__ __launch_bounds__(1024) void k_prep(const float* __restrict__ ab_p) {
    __shared__ float key[Sv];
    __shared__ float v1[Sv];
    __shared__ float v2[Sv];
    __shared__ float pren[Sv+1];
    __shared__ float sufp[Sv+1];
    __shared__ float ch1[64], ch2[64];

    const int bh = blockIdx.x;
    const int b  = bh >> 2;
    const int tid = threadIdx.x;
    const float ab = ab_p[0];

    for (int j = tid; j < Sv; j += 1024) {
        float e2 = g_e2[bh*Sv + j];
        key[j] = g_masked[b*Sv + j] ? -1e30f : e2;
    }
    __syncthreads();

    for (int k = 2; k <= Sv; k <<= 1) {
        for (int j = k >> 1; j > 0; j >>= 1) {
            #pragma unroll 2
            for (int i = tid; i < Sv; i += 1024) {
                int ixj = i ^ j;
                if (ixj > i) {
                    bool up = ((i & k) == 0);
                    float ki = key[i], kj = key[ixj];
                    if ((ki > kj) == up) { key[i] = kj; key[ixj] = ki; }
                }
            }
            __syncthreads();
        }
    }

    const float M2 = key[Sv-1];
    for (int j = tid; j < Sv; j += 1024) {
        float kk = key[j];
        v1[j] = expf(kk);
        v2[j] = expf(NEG*kk);
    }
    __syncthreads();

    if (tid < 64) {
        int base = tid * 32;
        float s1 = 0.f, s2 = 0.f;
        for (int t = 0; t < 32; t++) { s1 += v1[base+t]; s2 += v2[base+t]; }
        ch1[tid] = s1; ch2[tid] = s2;
    }
    __syncthreads();
    if (tid == 0) {
        float r = 0.f;
        for (int c = 0; c < 64; c++) { float t = ch2[c]; ch2[c] = r; r += t; }
        pren[Sv] = r;
        r = 0.f;
        for (int c = 63; c >= 0; c--) { float t = ch1[c]; ch1[c] = r; r += t; }
    }
    __syncthreads();
    if (tid < 64) {
        int base = tid * 32;
        float run = ch2[tid];
        for (int t = 0; t < 32; t++) { pren[base+t] = run; run += v2[base+t]; }
        float runs = ch1[tid];
        for (int t = 31; t >= 0; t--) { runs += v1[base+t]; sufp[base+t] = runs; }
    }
    if (tid == 0) sufp[Sv] = 0.f;
    __syncthreads();

    for (int i = tid; i < Sv; i += 1024) {
        float e1 = g_e1[bh*Sv + i];
        float eb = e1 + ab;
        float pre = eb + M2;
        float m = (pre > 0.f) ? pre : NEG*pre;
        float th = -eb;
        float A  = expf(eb - m);
        float Bc = expf(NEG*eb - m);
        int lo = 0, hi = Sv;
        while (lo < hi) {
            int mid = (lo + hi) >> 1;
            if (key[mid] <= th) lo = mid + 1; else hi = mid;
        }
        float rowsum = A*sufp[lo] + Bc*pren[lo];
        float inv = 1.0f / rowsum;
        g_An[bh*Sv + i] = A * inv;
        g_Bn[bh*Sv + i] = Bc * inv;
        g_th[bh*Sv + i] = th;
    }
}

// ---------------------------------------------------------------
// K3: mma.sync bf16 3-split, pipelined. Block = 128 i x 128 d of one (b,h).
// 8 warps as 4(M=32) x 2(N=64). KT=64. cp.async double-buffered B,
// double-buffered A(P). Dynamic smem 145.5 KB.
// ---------------------------------------------------------------
#define KT 64
#define LDB 144                      /* bytes per row (72 bf16) */
#define ASZ (128*LDB)                /* 18432 B per (buf,part) tile */
#define OFF_A(q,p) ((uint32_t)(((q)*2+(p))*ASZ))
#define OFF_B(q,p) ((uint32_t)(73728 + ((q)*2+(p))*ASZ))
#define OFF_CONST  147456u
#define ATTN_SMEM  (147456 + 1536)

extern __shared__ __align__(128) unsigned char dynsmem[];

__device__ __forceinline__ void fill_B(int bh, int jt, uint32_t sb, int q, int tid) {
    const int c0 = jt >> 5;
    const size_t base_hi = ((size_t)bh*(Sv/32) + c0) * Dv * 32;
    #pragma unroll
    for (int t = 0; t < 4; t++) {
        int cidx = tid + t*256;                 // 1024 chunks of 16B (hi)
        int d  = cidx >> 3;
        int jc = (cidx >> 2) & 1;
        int s8 = (cidx & 3) * 8;
        uint32_t dst = sb + OFF_B(q,0) + (uint32_t)(d*LDB + (jc*32 + s8)*2);
        CP16(dst, g_hpT_hi + base_hi + ((size_t)jc*Dv + d)*32 + s8);
    }
    #pragma unroll
    for (int t = 0; t < 4; t++) {
        int cidx = tid + t*256;                 // lo
        int d  = cidx >> 3;
        int jc = (cidx >> 2) & 1;
        int s8 = (cidx & 3) * 8;
        uint32_t dst = sb + OFF_B(q,1) + (uint32_t)(d*LDB + (jc*32 + s8)*2);
        CP16(dst, g_hpT_lo + base_hi + ((size_t)jc*Dv + d)*32 + s8);
    }
}

__global__ __launch_bounds__(256, 1) void k_attn(float* __restrict__ attn_out) {
    const int bh = blockIdx.y;
    const int i0 = blockIdx.x * 128;
    const int tid = threadIdx.x;
    const int w = tid >> 5;
    const int lane = tid & 31;
    const uint32_t sb = smem_u32(dynsmem);

    float* sTh = (float*)(dynsmem + OFF_CONST);
    float* sAn = sTh + 128;
    float* sBn = sAn + 128;

    if (tid < 128) {
        sTh[tid] = g_th[bh*Sv + i0 + tid];
        sAn[tid] = g_An[bh*Sv + i0 + tid];
        sBn[tid] = g_Bn[bh*Sv + i0 + tid];
    }
    fill_B(bh, 0, sb, 0, tid);
    CP_COMMIT();
    __syncthreads();

    // p-phase mapping: warp rg handles rows rg*16..+15, lane j-pair
    const int rg = w;
    const int j0 = lane * 2;
    // MMA mapping: warp (wm, wn)
    const int wm = w >> 1, wn = w & 1;
    const uint32_t aoff = (uint32_t)((wm*32 + (lane & 15))*LDB + ((lane >> 4)*8)*2);
    const uint32_t boff = (uint32_t)(((lane & 7) + ((lane >> 4) << 3))*LDB + (((lane >> 3) & 1)*8)*2);

    float c[2][8][4] = {};
    float* attn_base = attn_out + ((size_t)(bh*Sv + i0)) * Sv;

    #pragma unroll 1
    for (int iter = 0; iter < Sv/KT; iter++) {
        const int q = iter & 1;
        const int jt = iter * KT;

        if (iter < Sv/KT - 1) { fill_B(bh, jt + KT, sb, q^1, tid); CP_COMMIT(); }

        // ---- p-phase into A[q] (+ attn gmem write) ----
        {
            float2 e2v = *(const float2*)(g_e2  + bh*Sv + jt + j0);
            float2 epv = *(const float2*)(g_E2p + bh*Sv + jt + j0);
            float2 env = *(const float2*)(g_E2n + bh*Sv + jt + j0);
            unsigned char* Aqh = dynsmem + OFF_A(q,0);
            unsigned char* Aql = dynsmem + OFF_A(q,1);
            #pragma unroll
            for (int rr = 0; rr < 16; rr++) {
                int r = rg*16 + rr;
                float th = sTh[r], An = sAn[r], Bn = sBn[r];
                float p0 = (e2v.x > th) ? An*epv.x : Bn*env.x;
                float p1 = (e2v.y > th) ? An*epv.y : Bn*env.y;
                *(float2*)(attn_base + (size_t)r*Sv + jt + j0) = make_float2(p0, p1);
                __nv_bfloat16 h0 = __float2bfloat16_rn(p0);
                __nv_bfloat16 h1 = __float2bfloat16_rn(p1);
                __nv_bfloat16 l0 = __float2bfloat16_rn(p0 - __bfloat162float(h0));
                __nv_bfloat16 l1 = __float2bfloat16_rn(p1 - __bfloat162float(h1));
                uint32_t whi = ((uint32_t)__bfloat16_as_ushort(h1) << 16) | __bfloat16_as_ushort(h0);
                uint32_t wlo = ((uint32_t)__bfloat16_as_ushort(l1) << 16) | __bfloat16_as_ushort(l0);
                *(uint32_t*)(Aqh + r*LDB + j0*2) = whi;
                *(uint32_t*)(Aql + r*LDB + j0*2) = wlo;
            }
        }

        if (iter < Sv/KT - 1) { CP_WAIT1(); } else { CP_WAIT0(); }
        __syncthreads();

        // ---- MMA phase on A[q], B[q] ----
        #pragma unroll
        for (int ks = 0; ks < 4; ks++) {
            uint32_t ah[2][4], al[2][4];
            #pragma unroll
            for (int mt = 0; mt < 2; mt++) {
                LDMX4(ah[mt][0],ah[mt][1],ah[mt][2],ah[mt][3],
                      sb + OFF_A(q,0) + aoff + mt*16*LDB + ks*32);
                LDMX4(al[mt][0],al[mt][1],al[mt][2],al[mt][3],
                      sb + OFF_A(q,1) + aoff + mt*16*LDB + ks*32);
            }
            #pragma unroll
            for (int nt = 0; nt < 4; nt++) {
                uint32_t bh0,bh1,bh2,bh3, bl0,bl1,bl2,bl3;
                uint32_t bt = (uint32_t)((wn*64 + nt*16)*LDB + ks*32);
                LDMX4(bh0,bh1,bh2,bh3, sb + OFF_B(q,0) + boff + bt);
                LDMX4(bl0,bl1,bl2,bl3, sb + OFF_B(q,1) + boff + bt);
                #pragma unroll
                for (int mt = 0; mt < 2; mt++) {
                    MMA16816(c[mt][nt*2],   ah[mt][0],ah[mt][1],ah[mt][2],ah[mt][3], bh0,bh1);
                    MMA16816(c[mt][nt*2],   al[mt][0],al[mt][1],al[mt][2],al[mt][3], bh0,bh1);
                    MMA16816(c[mt][nt*2],   ah[mt][0],ah[mt][1],ah[mt][2],ah[mt][3], bl0,bl1);
                    MMA16816(c[mt][nt*2+1], ah[mt][0],ah[mt][1],ah[mt][2],ah[mt][3], bh2,bh3);
                    MMA16816(c[mt][nt*2+1], al[mt][0],al[mt][1],al[mt][2],al[mt][3], bh2,bh3);
                    MMA16816(c[mt][nt*2+1], ah[mt][0],ah[mt][1],ah[mt][2],ah[mt][3], bl2,bl3);
                }
            }
        }
        __syncthreads();
    }

    // ---- epilogue: C frags -> g_ctx ----
    {
        const int b = bh >> 2, hh = bh & 3;
        const int g = lane >> 2, tg = lane & 3;
        #pragma unroll
        for (int mt = 0; mt < 2; mt++) {
            int ibase = i0 + wm*32 + mt*16;
            #pragma unroll
            for (int ntt = 0; ntt < 8; ntt++) {
                int d = wn*64 + ntt*8 + tg*2;
                float* p0 = g_ctx + ((size_t)(b*Sv + ibase + g))*HDv + hh*Dv + d;
                p0[0] = c[mt][ntt][0]; p0[1] = c[mt][ntt][1];
                float* p1 = g_ctx + ((size_t)(b*Sv + ibase + g + 8))*HDv + hh*Dv + d;
                p1[0] = c[mt][ntt][2]; p1[1] = c[mt][ntt][3];
            }
        }
    }
}

// ---------------------------------------------------------------
// K4: out = relu(ctx @ out_w^T + out_b)
// ---------------------------------------------------------------
__global__ __launch_bounds__(256) void k_gemm2(const float* __restrict__ W,
                                               const float* __restrict__ bias,
                                               float* __restrict__ out) {
    __shared__ float As[64][65];
    __shared__ float Ws[64][65];
    const int m0 = blockIdx.x * 64;
    const int n0 = blockIdx.y * 64;
    const int tid = threadIdx.x;
    const int tm = tid >> 4, tn = tid & 15;
    const int mm = tm << 2, nn = tn << 2;
    float acc[4][4] = {};

    for (int kk = 0; kk < HDv; kk += 64) {
        for (int i = tid; i < 64*16; i += 256) {
            int r = i >> 4, c4 = (i & 15) << 2;
            float4 va = *(const float4*)(g_ctx + (size_t)(m0+r)*HDv + kk + c4);
            As[r][c4+0]=va.x; As[r][c4+1]=va.y; As[r][c4+2]=va.z; As[r][c4+3]=va.w;
            float4 vw = *(const float4*)(W + (size_t)(n0+r)*HDv + kk + c4);
            Ws[r][c4+0]=vw.x; Ws[r][c4+1]=vw.y; Ws[r][c4+2]=vw.z; Ws[r][c4+3]=vw.w;
        }
        __syncthreads();
        #pragma unroll 4
        for (int k = 0; k < 64; k++) {
            float a0=As[mm+0][k], a1=As[mm+1][k], a2=As[mm+2][k], a3=As[mm+3][k];
            float b0=Ws[nn+0][k], b1=Ws[nn+1][k], b2=Ws[nn+2][k], b3=Ws[nn+3][k];
            acc[0][0]+=a0*b0; acc[0][1]+=a0*b1; acc[0][2]+=a0*b2; acc[0][3]+=a0*b3;
            acc[1][0]+=a1*b0; acc[1][1]+=a1*b1; acc[1][2]+=a1*b2; acc[1][3]+=a1*b3;
            acc[2][0]+=a2*b0; acc[2][1]+=a2*b1; acc[2][2]+=a2*b2; acc[2][3]+=a2*b3;
            acc[3][0]+=a3*b0; acc[3][1]+=a3*b1; acc[3][2]+=a3*b2; acc[3][3]+=a3*b3;
        }
        __syncthreads();
    }
    #pragma unroll
    for (int i = 0; i < 4; i++) {
        int m = m0 + mm + i;
        #pragma unroll
        for (int j = 0; j < 4; j++) {
            int n = n0 + nn + j;
            float v = acc[i][j] + bias[n];
            out[(size_t)m*OUTv + n] = v > 0.f ? v : 0.f;
        }
    }
}

// ---------------------------------------------------------------
extern "C" void kernel_launch(void* const* d_in, const int* in_sizes, int n_in,
                              void* d_out, int out_size) {
    const float* h     = (const float*)d_in[0];
    const void*  mask  = d_in[1];
    const float* W_w   = (const float*)d_in[2];
    const float* W_b   = (const float*)d_in[3];
    const float* a_w   = (const float*)d_in[4];
    const float* a_b   = (const float*)d_in[5];
    const float* out_w = (const float*)d_in[6];
    const float* out_b = (const float*)d_in[7];

    float* out  = (float*)d_out;
    float* attn = out + (size_t)Bv*Sv*OUTv;

    static int attr_set = 0;
    if (!attr_set) {
        cudaFuncSetAttribute(k_attn, cudaFuncAttributeMaxDynamicSharedMemorySize, ATTN_SMEM);
        attr_set = 1;
    }

    k_mask <<<1, 256>>>(mask);
    k_gemm1<<<dim3(128, 8), 256>>>(h, W_w, W_b);
    k_e12  <<<NSv/8, 256>>>(a_w);
    k_prep <<<BHv, 1024>>>(a_b);
    k_attn <<<dim3(Sv/128, BHv), 256, ATTN_SMEM>>>(attn);
    k_gemm2<<<dim3(128, 2), 256>>>(out_w, out_b, out);
}

// round 5
// speedup vs baseline: 1.9133x; 1.1964x over previous
#include <cuda_runtime.h>
#include <cuda_bf16.h>
#include <math.h>
#include <stdint.h>

#define Bv 4
#define Sv 2048
#define Fv 128
#define Hv 4
#define Dv 128
#define HDv 512
#define OUTv 128
#define BHv 16
#define NSv (BHv*Sv)
#define NEG 0.01f

// ---- device scratch ----
__device__ float g_hp[NSv*Dv];
__device__ float g_ctx[Bv*Sv*HDv];
__device__ float g_e1[NSv];
__device__ float g_e2[NSv];
__device__ float g_An[NSv];
__device__ float g_Bn[NSv];
__device__ float g_th[NSv];
__device__ float g_E2p[NSv];
__device__ float g_E2n[NSv];
__device__ int   g_masked[Bv*Sv];
// hp transposed+chunked: [bh][s/32][d][s%32], bf16 hi/lo
__device__ __nv_bfloat16 g_hpT_hi[BHv*Dv*Sv];
__device__ __nv_bfloat16 g_hpT_lo[BHv*Dv*Sv];

__device__ __forceinline__ uint32_t smem_u32(const void* p) {
    uint32_t a;
    asm("{ .reg .u64 t; cvta.to.shared.u64 t, %1; cvt.u32.u64 %0, t; }" : "=r"(a) : "l"(p));
    return a;
}
#define LDMX4(r0,r1,r2,r3,addr) \
    asm volatile("ldmatrix.sync.aligned.m8n8.x4.shared.b16 {%0,%1,%2,%3}, [%4];" \
        : "=r"(r0),"=r"(r1),"=r"(r2),"=r"(r3) : "r"(addr))
#define MMA16816(c,a0,a1,a2,a3,b0,b1) \
    asm volatile("mma.sync.aligned.m16n8k16.row.col.f32.bf16.bf16.f32 " \
        "{%0,%1,%2,%3}, {%4,%5,%6,%7}, {%8,%9}, {%0,%1,%2,%3};" \
        : "+f"((c)[0]),"+f"((c)[1]),"+f"((c)[2]),"+f"((c)[3]) \
        : "r"(a0),"r"(a1),"r"(a2),"r"(a3), "r"(b0),"r"(b1))
#define CP16(dst, src) \
    asm volatile("cp.async.cg.shared.global [%0], [%1], 16;" :: "r"(dst), "l"(src) : "memory")
#define CP_COMMIT() asm volatile("cp.async.commit_group;" ::: "memory")
#define CP_WAIT0()  asm volatile("cp.async.wait_group 0;" ::: "memory")

// ---------------------------------------------------------------
// K0: decode mask buffer (u8 vs i32 by byte sum)
// ---------------------------------------------------------------
__global__ void k_mask(const void* mraw) {
    __shared__ int ssum[256];
    __shared__ int fmt;
    const unsigned char* mb = (const unsigned char*)mraw;
    int tid = threadIdx.x;
    int s = 0;
    for (int i = tid; i < Bv*Sv; i += 256) s += mb[i];
    ssum[tid] = s;
    __syncthreads();
    for (int st = 128; st > 0; st >>= 1) {
        if (tid < st) ssum[tid] += ssum[tid + st];
        __syncthreads();
    }
    if (tid == 0) fmt = (ssum[0] > (Bv*Sv*5/16)) ? 1 : 0;
    __syncthreads();
    if (fmt) {
        for (int i = tid; i < Bv*Sv; i += 256) g_masked[i] = (mb[i] != 0);
    } else {
        const int* mi = (const int*)mraw;
        for (int i = tid; i < Bv*Sv; i += 256) g_masked[i] = (mi[i] != 0);
    }
}

// ---------------------------------------------------------------
// K1: hp = h @ W_w^T + W_b -> g_hp f32 + hpT hi/lo (staged, coalesced)
// ---------------------------------------------------------------
__global__ __launch_bounds__(256) void k_gemm1(const float* __restrict__ A,
                                               const float* __restrict__ W,
                                               const float* __restrict__ bias) {
    __shared__ float As[64][129];
    __shared__ float Ws[64][129];
    const int m0 = blockIdx.x * 64;
    const int n0 = blockIdx.y * 64;
    const int tid = threadIdx.x;

    for (int i = tid; i < 64*32; i += 256) {
        int r = i >> 5, c4 = (i & 31) << 2;
        float4 va = *(const float4*)(A + (size_t)(m0+r)*Fv + c4);
        As[r][c4+0]=va.x; As[r][c4+1]=va.y; As[r][c4+2]=va.z; As[r][c4+3]=va.w;
        float4 vw = *(const float4*)(W + (size_t)(n0+r)*Fv + c4);
        Ws[r][c4+0]=vw.x; Ws[r][c4+1]=vw.y; Ws[r][c4+2]=vw.z; Ws[r][c4+3]=vw.w;
    }
    __syncthreads();

    const int tm = tid >> 4, tn = tid & 15;
    const int mm = tm << 2, nn = tn << 2;
    float acc[4][4] = {};
    #pragma unroll 4
    for (int k = 0; k < Fv; k++) {
        float a0=As[mm+0][k], a1=As[mm+1][k], a2=As[mm+2][k], a3=As[mm+3][k];
        float b0=Ws[nn+0][k], b1=Ws[nn+1][k], b2=Ws[nn+2][k], b3=Ws[nn+3][k];
        acc[0][0]+=a0*b0; acc[0][1]+=a0*b1; acc[0][2]+=a0*b2; acc[0][3]+=a0*b3;
        acc[1][0]+=a1*b0; acc[1][1]+=a1*b1; acc[1][2]+=a1*b2; acc[1][3]+=a1*b3;
        acc[2][0]+=a2*b0; acc[2][1]+=a2*b1; acc[2][2]+=a2*b2; acc[2][3]+=a2*b3;
        acc[3][0]+=a3*b0; acc[3][1]+=a3*b1; acc[3][2]+=a3*b2; acc[3][3]+=a3*b3;
    }

    const int bb = m0 >> 11;            // batch (block spans one b)
    const int s0 = m0 & (Sv-1);
    const int hh = n0 >> 7;             // head (block spans one h)
    const int d0 = n0 & (Dv-1);
    const int bh = bb*Hv + hh;

    __syncthreads();   // done reading As/Ws; reuse as bf16 staging
    __nv_bfloat16* stHi = (__nv_bfloat16*)&As[0][0];   // [2 sc][64 d][32 s]
    __nv_bfloat16* stLo = (__nv_bfloat16*)&Ws[0][0];

    #pragma unroll
    for (int i = 0; i < 4; i++) {
        int sl = mm + i;
        int s  = s0 + sl;
        #pragma unroll
        for (int j = 0; j < 4; j++) {
            int dl = nn + j;
            float v = acc[i][j] + bias[n0 + dl];
            g_hp[(((size_t)bh)*Sv + s)*Dv + d0 + dl] = v;
            __nv_bfloat16 hi = __float2bfloat16_rn(v);
            __nv_bfloat16 lo = __float2bfloat16_rn(v - __bfloat162float(hi));
            int st = ((sl >> 5)*64 + dl)*32 + (sl & 31);
            stHi[st] = hi;
            stLo[st] = lo;
        }
    }
    __syncthreads();

    // coalesced out: 1024 chunks of 16B
    #pragma unroll
    for (int t = 0; t < 4; t++) {
        int c = tid + t*256;
        int part = c >> 9;
        int sc   = (c >> 8) & 1;
        int r    = c & 255;
        int dl   = r >> 2;
        int s8   = (r & 3) << 3;
        const __nv_bfloat16* src = (part ? stLo : stHi) + (sc*64 + dl)*32 + s8;
        __nv_bfloat16* dst = (part ? g_hpT_lo : g_hpT_hi)
            + (((size_t)bh*(Sv/32) + (s0 >> 5) + sc)*Dv + d0 + dl)*32 + s8;
        *(uint4*)dst = *(const uint4*)src;
    }
}

// ---------------------------------------------------------------
// K2a: e1,e2 per row + exp tables
// ---------------------------------------------------------------
__global__ __launch_bounds__(256) void k_e12(const float* __restrict__ aw) {
    int row  = blockIdx.x * 8 + (threadIdx.x >> 5);
    int lane = threadIdx.x & 31;
    float4 v  = *(const float4*)(g_hp + (size_t)row*Dv + lane*4);
    float4 w1 = *(const float4*)(aw + lane*4);
    float4 w2 = *(const float4*)(aw + Dv + lane*4);
    float s1 = v.x*w1.x + v.y*w1.y + v.z*w1.z + v.w*w1.w;
    float s2 = v.x*w2.x + v.y*w2.y + v.z*w2.z + v.w*w2.w;
    #pragma unroll
    for (int o = 16; o; o >>= 1) {
        s1 += __shfl_xor_sync(0xffffffffu, s1, o);
        s2 += __shfl_xor_sync(0xffffffffu, s2, o);
    }
    if (lane == 0) {
        g_e1[row] = s1; g_e2[row] = s2;
        int b = row >> 13, s = row & (Sv-1);
        int msk = g_masked[b*Sv + s];
        g_E2p[row] = msk ? 0.f : expf(s2);
        g_E2n[row] = msk ? 0.f : expf(NEG*s2);
    }
}

// ---------------------------------------------------------------
// K2b: per (b,h) softmax prep (key-only bitonic sort + scans + bsearch)
// ---------------------------------------------------------------
__global__ __launch_bounds__(1024) void k_prep(const float* __restrict__ ab_p) {
    __shared__ float key[Sv];
    __shared__ float v1[Sv];
    __shared__ float v2[Sv];
    __shared__ float pren[Sv+1];
    __shared__ float sufp[Sv+1];
    __shared__ float ch1[64], ch2[64];

    const int bh = blockIdx.x;
    const int b  = bh >> 2;
    const int tid = threadIdx.x;
    const float ab = ab_p[0];

    for (int j = tid; j < Sv; j += 1024) {
        float e2 = g_e2[bh*Sv + j];
        key[j] = g_masked[b*Sv + j] ? -1e30f : e2;
    }
    __syncthreads();

    for (int k = 2; k <= Sv; k <<= 1) {
        for (int j = k >> 1; j > 0; j >>= 1) {
            #pragma unroll 2
            for (int i = tid; i < Sv; i += 1024) {
                int ixj = i ^ j;
                if (ixj > i) {
                    bool up = ((i & k) == 0);
                    float ki = key[i], kj = key[ixj];
                    if ((ki > kj) == up) { key[i] = kj; key[ixj] = ki; }
                }
            }
            __syncthreads();
        }
    }

    const float M2 = key[Sv-1];
    for (int j = tid; j < Sv; j += 1024) {
        float kk = key[j];
        v1[j] = expf(kk);
        v2[j] = expf(NEG*kk);
    }
    __syncthreads();

    if (tid < 64) {
        int base = tid * 32;
        float s1 = 0.f, s2 = 0.f;
        for (int t = 0; t < 32; t++) { s1 += v1[base+t]; s2 += v2[base+t]; }
        ch1[tid] = s1; ch2[tid] = s2;
    }
    __syncthreads();
    if (tid == 0) {
        float r = 0.f;
        for (int c = 0; c < 64; c++) { float t = ch2[c]; ch2[c] = r; r += t; }
        pren[Sv] = r;
        r = 0.f;
        for (int c = 63; c >= 0; c--) { float t = ch1[c]; ch1[c] = r; r += t; }
    }
    __syncthreads();
    if (tid < 64) {
        int base = tid * 32;
        float run = ch2[tid];
        for (int t = 0; t < 32; t++) { pren[base+t] = run; run += v2[base+t]; }
        float runs = ch1[tid];
        for (int t = 31; t >= 0; t--) { runs += v1[base+t]; sufp[base+t] = runs; }
    }
    if (tid == 0) sufp[Sv] = 0.f;
    __syncthreads();

    for (int i = tid; i < Sv; i += 1024) {
        float e1 = g_e1[bh*Sv + i];
        float eb = e1 + ab;
        float pre = eb + M2;
        float m = (pre > 0.f) ? pre : NEG*pre;
        float th = -eb;
        float A  = expf(eb - m);
        float Bc = expf(NEG*eb - m);
        int lo = 0, hi = Sv;
        while (lo < hi) {
            int mid = (lo + hi) >> 1;
            if (key[mid] <= th) lo = mid + 1; else hi = mid;
        }
        float rowsum = A*sufp[lo] + Bc*pren[lo];
        float inv = 1.0f / rowsum;
        g_An[bh*Sv + i] = A * inv;
        g_Bn[bh*Sv + i] = Bc * inv;
        g_th[bh*Sv + i] = th;
    }
}

// ---------------------------------------------------------------
// K3: mma.sync bf16 3-split, single-wave, single-sync pipeline.
// Block = 256 i x 128 d of one (b,h); 512 threads, 16 warps (4x4).
// A(P) double-buffered (p-phase for iter+1 interleaves with MMA(iter)).
// B double-buffered via cp.async. smem 219 KB.
// ---------------------------------------------------------------
#define KT 64
#define LDB 144                       /* bytes per 64-bf16 row */
#define A_TSZ (256*LDB)               /* 36864 */
#define B_TSZ (128*LDB)               /* 18432 */
#define OFF_A(q,p) ((uint32_t)(((q)*2+(p))*A_TSZ))
#define OFF_B(q,p) ((uint32_t)(147456 + ((q)*2+(p))*B_TSZ))
#define OFF_CONST  221184u
#define ATTN_SMEM  (221184 + 3072)

extern __shared__ __align__(128) unsigned char dynsmem[];

__device__ __forceinline__ void fill_B(int bh, int jt, uint32_t sb, int q, int tid) {
    const int c0 = jt >> 5;
    const size_t base = ((size_t)bh*(Sv/32) + c0) * Dv * 32;
    #pragma unroll
    for (int t = 0; t < 2; t++) {
        int cidx = tid + t*512;                 // 1024 chunks (hi)
        int d  = cidx >> 3;
        int jc = (cidx >> 2) & 1;
        int s8 = (cidx & 3) * 8;
        CP16(sb + OFF_B(q,0) + (uint32_t)(d*LDB + (jc*32 + s8)*2),
             g_hpT_hi + base + ((size_t)jc*Dv + d)*32 + s8);
    }
    #pragma unroll
    for (int t = 0; t < 2; t++) {
        int cidx = tid + t*512;                 // 1024 chunks (lo)
        int d  = cidx >> 3;
        int jc = (cidx >> 2) & 1;
        int s8 = (cidx & 3) * 8;
        CP16(sb + OFF_B(q,1) + (uint32_t)(d*LDB + (jc*32 + s8)*2),
             g_hpT_lo + base + ((size_t)jc*Dv + d)*32 + s8);
    }
}

__global__ __launch_bounds__(512, 1) void k_attn(float* __restrict__ attn_out) {
    const int bh = blockIdx.y;
    const int i0 = blockIdx.x * 256;
    const int tid = threadIdx.x;
    const int w = tid >> 5;
    const int lane = tid & 31;
    const uint32_t sb = smem_u32(dynsmem);

    float* sTh = (float*)(dynsmem + OFF_CONST);
    float* sAn = sTh + 256;
    float* sBn = sAn + 256;

    fill_B(bh, 0, sb, 0, tid);
    CP_COMMIT();
    if (tid < 256) {
        sTh[tid] = g_th[bh*Sv + i0 + tid];
        sAn[tid] = g_An[bh*Sv + i0 + tid];
        sBn[tid] = g_Bn[bh*Sv + i0 + tid];
    }
    __syncthreads();

    // p-phase mapping: warp w -> rows w*16..+15; lane -> j pair
    const int j0 = lane * 2;
    // MMA mapping: 4x4 warp grid
    const int wm = w >> 2, wn = w & 3;
    const uint32_t aoff = (uint32_t)((wm*64 + (lane & 15))*LDB + ((lane >> 4)*8)*2);
    const uint32_t boff = (uint32_t)(((lane & 7) + ((lane >> 4) << 3))*LDB + (((lane >> 3) & 1)*8)*2);

    float c[4][4][4] = {};
    float* attn_base = attn_out + ((size_t)(bh*Sv + i0)) * Sv;

    // prologue p-phase for iter 0 into A[0]
    {
        float2 e2v = *(const float2*)(g_e2  + bh*Sv + j0);
        float2 epv = *(const float2*)(g_E2p + bh*Sv + j0);
        float2 env = *(const float2*)(g_E2n + bh*Sv + j0);
        unsigned char* Aqh = dynsmem + OFF_A(0,0);
        unsigned char* Aql = dynsmem + OFF_A(0,1);
        #pragma unroll
        for (int rr = 0; rr < 16; rr++) {
            int r = w*16 + rr;
            float th = sTh[r], An = sAn[r], Bn = sBn[r];
            float p0 = (e2v.x > th) ? An*epv.x : Bn*env.x;
            float p1 = (e2v.y > th) ? An*epv.y : Bn*env.y;
            *(float2*)(attn_base + (size_t)r*Sv + j0) = make_float2(p0, p1);
            __nv_bfloat16 h0 = __float2bfloat16_rn(p0);
            __nv_bfloat16 h1 = __float2bfloat16_rn(p1);
            __nv_bfloat16 l0 = __float2bfloat16_rn(p0 - __bfloat162float(h0));
            __nv_bfloat16 l1 = __float2bfloat16_rn(p1 - __bfloat162float(h1));
            *(uint32_t*)(Aqh + r*LDB + j0*2) = ((uint32_t)__bfloat16_as_ushort(h1) << 16) | __bfloat16_as_ushort(h0);
            *(uint32_t*)(Aql + r*LDB + j0*2) = ((uint32_t)__bfloat16_as_ushort(l1) << 16) | __bfloat16_as_ushort(l0);
        }
    }

    #pragma unroll 1
    for (int iter = 0; iter < Sv/KT; iter++) {
        const int q = iter & 1;

        CP_WAIT0();          // B[q] (committed last iter / prologue) complete
        __syncthreads();     // A[q] p-writes + B[q] visible; prev MMA done

        if (iter < Sv/KT - 1) {
            fill_B(bh, (iter+1)*KT, sb, q^1, tid);   // safe: prev MMA (reader of B[q^1]) retired
            CP_COMMIT();
            // ---- p-phase for iter+1 into A[q^1] (interleaves with MMA below) ----
            const int jt1 = (iter+1)*KT;
            float2 e2v = *(const float2*)(g_e2  + bh*Sv + jt1 + j0);
            float2 epv = *(const float2*)(g_E2p + bh*Sv + jt1 + j0);
            float2 env = *(const float2*)(g_E2n + bh*Sv + jt1 + j0);
            unsigned char* Aqh = dynsmem + OFF_A(q^1,0);
            unsigned char* Aql = dynsmem + OFF_A(q^1,1);
            #pragma unroll
            for (int rr = 0; rr < 16; rr++) {
                int r = w*16 + rr;
                float th = sTh[r], An = sAn[r], Bn = sBn[r];
                float p0 = (e2v.x > th) ? An*epv.x : Bn*env.x;
                float p1 = (e2v.y > th) ? An*epv.y : Bn*env.y;
                *(float2*)(attn_base + (size_t)r*Sv + jt1 + j0) = make_float2(p0, p1);
                __nv_bfloat16 h0 = __float2bfloat16_rn(p0);
                __nv_bfloat16 h1 = __float2bfloat16_rn(p1);
                __nv_bfloat16 l0 = __float2bfloat16_rn(p0 - __bfloat162float(h0));
                __nv_bfloat16 l1 = __float2bfloat16_rn(p1 - __bfloat162float(h1));
                *(uint32_t*)(Aqh + r*LDB + j0*2) = ((uint32_t)__bfloat16_as_ushort(h1) << 16) | __bfloat16_as_ushort(h0);
                *(uint32_t*)(Aql + r*LDB + j0*2) = ((uint32_t)__bfloat16_as_ushort(l1) << 16) | __bfloat16_as_ushort(l0);
            }
        }

        // ---- MMA on A[q], B[q] ----
        #pragma unroll
        for (int ks = 0; ks < 4; ks++) {
            uint32_t bhf[2][4], blf[2][4];
            #pragma unroll
            for (int np = 0; np < 2; np++) {
                uint32_t bt = (uint32_t)((wn*32 + np*16)*LDB + ks*32);
                LDMX4(bhf[np][0],bhf[np][1],bhf[np][2],bhf[np][3], sb + OFF_B(q,0) + boff + bt);
                LDMX4(blf[np][0],blf[np][1],blf[np][2],blf[np][3], sb + OFF_B(q,1) + boff + bt);
            }
            #pragma unroll
            for (int mt = 0; mt < 4; mt++) {
                uint32_t ah0,ah1,ah2,ah3, al0,al1,al2,al3;
                LDMX4(ah0,ah1,ah2,ah3, sb + OFF_A(q,0) + aoff + mt*16*LDB + ks*32);
                LDMX4(al0,al1,al2,al3, sb + OFF_A(q,1) + aoff + mt*16*LDB + ks*32);
                #pragma unroll
                for (int np = 0; np < 2; np++) {
                    MMA16816(c[mt][np*2],   ah0,ah1,ah2,ah3, bhf[np][0],bhf[np][1]);
                    MMA16816(c[mt][np*2],   al0,al1,al2,al3, bhf[np][0],bhf[np][1]);
                    MMA16816(c[mt][np*2],   ah0,ah1,ah2,ah3, blf[np][0],blf[np][1]);
                    MMA16816(c[mt][np*2+1], ah0,ah1,ah2,ah3, bhf[np][2],bhf[np][3]);
                    MMA16816(c[mt][np*2+1], al0,al1,al2,al3, bhf[np][2],bhf[np][3]);
                    MMA16816(c[mt][np*2+1], ah0,ah1,ah2,ah3, blf[np][2],blf[np][3]);
                }
            }
        }
    }

    // ---- epilogue: C frags -> g_ctx ----
    {
        const int b = bh >> 2, hh = bh & 3;
        const int g = lane >> 2, tg = lane & 3;
        #pragma unroll
        for (int mt = 0; mt < 4; mt++) {
            int ibase = i0 + wm*64 + mt*16;
            #pragma unroll
            for (int nt = 0; nt < 4; nt++) {
                int d = wn*32 + nt*8 + tg*2;
                float* p0 = g_ctx + ((size_t)(b*Sv + ibase + g))*HDv + hh*Dv + d;
                p0[0] = c[mt][nt][0]; p0[1] = c[mt][nt][1];
                float* p1 = g_ctx + ((size_t)(b*Sv + ibase + g + 8))*HDv + hh*Dv + d;
                p1[0] = c[mt][nt][2]; p1[1] = c[mt][nt][3];
            }
        }
    }
}

// ---------------------------------------------------------------
// K4: out = relu(ctx @ out_w^T + out_b)
// ---------------------------------------------------------------
__global__ __launch_bounds__(256) void k_gemm2(const float* __restrict__ W,
                                               const float* __restrict__ bias,
                                               float* __restrict__ out) {
    __shared__ float As[64][65];
    __shared__ float Ws[64][65];
    const int m0 = blockIdx.x * 64;
    const int n0 = blockIdx.y * 64;
    const int tid = threadIdx.x;
    const int tm = tid >> 4, tn = tid & 15;
    const int mm = tm << 2, nn = tn << 2;
    float acc[4][4] = {};

    for (int kk = 0; kk < HDv; kk += 64) {
        for (int i = tid; i < 64*16; i += 256) {
            int r = i >> 4, c4 = (i & 15) << 2;
            float4 va = *(const float4*)(g_ctx + (size_t)(m0+r)*HDv + kk + c4);
            As[r][c4+0]=va.x; As[r][c4+1]=va.y; As[r][c4+2]=va.z; As[r][c4+3]=va.w;
            float4 vw = *(const float4*)(W + (size_t)(n0+r)*HDv + kk + c4);
            Ws[r][c4+0]=vw.x; Ws[r][c4+1]=vw.y; Ws[r][c4+2]=vw.z; Ws[r][c4+3]=vw.w;
        }
        __syncthreads();
        #pragma unroll 4
        for (int k = 0; k < 64; k++) {
            float a0=As[mm+0][k], a1=As[mm+1][k], a2=As[mm+2][k], a3=As[mm+3][k];
            float b0=Ws[nn+0][k], b1=Ws[nn+1][k], b2=Ws[nn+2][k], b3=Ws[nn+3][k];
            acc[0][0]+=a0*b0; acc[0][1]+=a0*b1; acc[0][2]+=a0*b2; acc[0][3]+=a0*b3;
            acc[1][0]+=a1*b0; acc[1][1]+=a1*b1; acc[1][2]+=a1*b2; acc[1][3]+=a1*b3;
            acc[2][0]+=a2*b0; acc[2][1]+=a2*b1; acc[2][2]+=a2*b2; acc[2][3]+=a2*b3;
            acc[3][0]+=a3*b0; acc[3][1]+=a3*b1; acc[3][2]+=a3*b2; acc[3][3]+=a3*b3;
        }
        __syncthreads();
    }
    #pragma unroll
    for (int i = 0; i < 4; i++) {
        int m = m0 + mm + i;
        #pragma unroll
        for (int j = 0; j < 4; j++) {
            int n = n0 + nn + j;
            float v = acc[i][j] + bias[n];
            out[(size_t)m*OUTv + n] = v > 0.f ? v : 0.f;
        }
    }
}

// ---------------------------------------------------------------
extern "C" void kernel_launch(void* const* d_in, const int* in_sizes, int n_in,
                              void* d_out, int out_size) {
    const float* h     = (const float*)d_in[0];
    const void*  mask  = d_in[1];
    const float* W_w   = (const float*)d_in[2];
    const float* W_b   = (const float*)d_in[3];
    const float* a_w   = (const float*)d_in[4];
    const float* a_b   = (const float*)d_in[5];
    const float* out_w = (const float*)d_in[6];
    const float* out_b = (const float*)d_in[7];

    float* out  = (float*)d_out;
    float* attn = out + (size_t)Bv*Sv*OUTv;

    static int attr_set = 0;
    if (!attr_set) {
        cudaFuncSetAttribute(k_attn, cudaFuncAttributeMaxDynamicSharedMemorySize, ATTN_SMEM);
        attr_set = 1;
    }

    k_mask <<<1, 256>>>(mask);
    k_gemm1<<<dim3(128, 8), 256>>>(h, W_w, W_b);
    k_e12  <<<NSv/8, 256>>>(a_w);
    k_prep <<<BHv, 1024>>>(a_b);
    k_attn <<<dim3(Sv/256, BHv), 512, ATTN_SMEM>>>(attn);
    k_gemm2<<<dim3(128, 2), 256>>>(out_w, out_b, out);
}

// round 6
// speedup vs baseline: 2.3261x; 1.2157x over previous
#include <cuda_runtime.h>
#include <cuda_bf16.h>
#include <math.h>
#include <stdint.h>

#define Bv 4
#define Sv 2048
#define Fv 128
#define Hv 4
#define Dv 128
#define HDv 512
#define OUTv 128
#define BHv 16
#define NSv (BHv*Sv)
#define NEG 0.01f

// ---- device scratch ----
__device__ float g_e1[NSv];
__device__ float g_e2[NSv];
__device__ float g_An[NSv];
__device__ float g_Bn[NSv];
__device__ float g_th[NSv];
__device__ float g_E2p[NSv];
__device__ float g_E2n[NSv];
__device__ int   g_masked[Bv*Sv];
// hp transposed+chunked: [bh][s/32][d][s%32], bf16 hi/lo
__device__ __nv_bfloat16 g_hpT_hi[BHv*Dv*Sv];
__device__ __nv_bfloat16 g_hpT_lo[BHv*Dv*Sv];
// ctx in bf16 hi/lo, k-major [b][s][h*D+d]
__device__ __nv_bfloat16 g_ctxb_hi[Bv*Sv*HDv];
__device__ __nv_bfloat16 g_ctxb_lo[Bv*Sv*HDv];
// out_w bf16 hi/lo [n][k]
__device__ __nv_bfloat16 g_wb_hi[OUTv*HDv];
__device__ __nv_bfloat16 g_wb_lo[OUTv*HDv];

__device__ __forceinline__ uint32_t smem_u32(const void* p) {
    uint32_t a;
    asm("{ .reg .u64 t; cvta.to.shared.u64 t, %1; cvt.u32.u64 %0, t; }" : "=r"(a) : "l"(p));
    return a;
}
#define LDMX4(r0,r1,r2,r3,addr) \
    asm volatile("ldmatrix.sync.aligned.m8n8.x4.shared.b16 {%0,%1,%2,%3}, [%4];" \
        : "=r"(r0),"=r"(r1),"=r"(r2),"=r"(r3) : "r"(addr))
#define MMA16816(c,a0,a1,a2,a3,b0,b1) \
    asm volatile("mma.sync.aligned.m16n8k16.row.col.f32.bf16.bf16.f32 " \
        "{%0,%1,%2,%3}, {%4,%5,%6,%7}, {%8,%9}, {%0,%1,%2,%3};" \
        : "+f"((c)[0]),"+f"((c)[1]),"+f"((c)[2]),"+f"((c)[3]) \
        : "r"(a0),"r"(a1),"r"(a2),"r"(a3), "r"(b0),"r"(b1))
#define CP16(dst, src) \
    asm volatile("cp.async.cg.shared.global [%0], [%1], 16;" :: "r"(dst), "l"(src) : "memory")
#define CP_COMMIT() asm volatile("cp.async.commit_group;" ::: "memory")
#define CP_WAIT1()  asm volatile("cp.async.wait_group 1;" ::: "memory")
#define CP_WAIT0()  asm volatile("cp.async.wait_group 0;" ::: "memory")

__device__ __forceinline__ uint32_t pack_hi2(float a, float b) {
    __nv_bfloat16 ha = __float2bfloat16_rn(a), hb = __float2bfloat16_rn(b);
    return ((uint32_t)__bfloat16_as_ushort(hb) << 16) | __bfloat16_as_ushort(ha);
}
__device__ __forceinline__ uint32_t pack_lo2(float a, float b) {
    __nv_bfloat16 ha = __float2bfloat16_rn(a), hb = __float2bfloat16_rn(b);
    float ra = a - __bfloat162float(ha), rb = b - __bfloat162float(hb);
    __nv_bfloat16 la = __float2bfloat16_rn(ra), lb = __float2bfloat16_rn(rb);
    return ((uint32_t)__bfloat16_as_ushort(lb) << 16) | __bfloat16_as_ushort(la);
}

extern __shared__ __align__(128) unsigned char dynsmem[];

// ---------------------------------------------------------------
// K0: decode mask buffer (u8 vs i32 by byte sum)
// ---------------------------------------------------------------
__global__ void k_mask(const void* mraw) {
    __shared__ int ssum[256];
    __shared__ int fmt;
    const unsigned char* mb = (const unsigned char*)mraw;
    int tid = threadIdx.x;
    int s = 0;
    for (int i = tid; i < Bv*Sv; i += 256) s += mb[i];
    ssum[tid] = s;
    __syncthreads();
    for (int st = 128; st > 0; st >>= 1) {
        if (tid < st) ssum[tid] += ssum[tid + st];
        __syncthreads();
    }
    if (tid == 0) fmt = (ssum[0] > (Bv*Sv*5/16)) ? 1 : 0;
    __syncthreads();
    if (fmt) {
        for (int i = tid; i < Bv*Sv; i += 256) g_masked[i] = (mb[i] != 0);
    } else {
        const int* mi = (const int*)mraw;
        for (int i = tid; i < Bv*Sv; i += 256) g_masked[i] = (mi[i] != 0);
    }
}

// ---------------------------------------------------------------
// K0b: convert out_w to bf16 hi/lo (independent of everything else)
// ---------------------------------------------------------------
__global__ void k_wcvt(const float* __restrict__ W) {
    int i = blockIdx.x * 256 + threadIdx.x;    // 16384 float4
    float4 v = *(const float4*)(W + (size_t)i*4);
    uint32_t h0 = pack_hi2(v.x, v.y), h1 = pack_hi2(v.z, v.w);
    uint32_t l0 = pack_lo2(v.x, v.y), l1 = pack_lo2(v.z, v.w);
    *(uint2*)(g_wb_hi + (size_t)i*4) = make_uint2(h0, h1);
    *(uint2*)(g_wb_lo + (size_t)i*4) = make_uint2(l0, l1);
}

// ---------------------------------------------------------------
// K1: hp = h @ W_w^T + W_b via bf16 3-split mma.sync.
// Block = 128 m (one b, 128 s) x 128 n (one h, full d). K=128 one-shot.
// Epilogue: stage bf16 hi/lo in smem -> coalesced hpT writes.
// smem: 4 op tiles 128x136 bf16 (136 KB), staging reuses it.
// ---------------------------------------------------------------
#define G1_LDK 136
#define G1_T  (128*G1_LDK*2)            /* 34816 */
#define G1_AH 0u
#define G1_AL ((uint32_t)G1_T)
#define G1_BH ((uint32_t)(2*G1_T))
#define G1_BL ((uint32_t)(3*G1_T))
#define G1_SMEM (4*G1_T)                /* 139264 */
#define ST_STRIDE 40                    /* staging: [p][ch][d][40] elems */

__global__ __launch_bounds__(256, 1) void k_gemm1t(const float* __restrict__ A,
                                                   const float* __restrict__ W,
                                                   const float* __restrict__ bias) {
    const int m0 = blockIdx.x * 128;
    const int n0 = blockIdx.y * 128;
    const int tid = threadIdx.x;
    const int w = tid >> 5, lane = tid & 31;
    const uint32_t sb = smem_u32(dynsmem);

    // ---- load + convert A(h) and B(W_w) tiles ----
    #pragma unroll
    for (int t = 0; t < 16; t++) {
        int idx = tid + t*256;            // 4096 float4
        int r = idx >> 5, c4 = (idx & 31) << 2;
        float4 v = *(const float4*)(A + (size_t)(m0+r)*Fv + c4);
        uint32_t boff = (uint32_t)(r*G1_LDK + c4) * 2;
        *(uint2*)(dynsmem + G1_AH + boff) = make_uint2(pack_hi2(v.x,v.y), pack_hi2(v.z,v.w));
        *(uint2*)(dynsmem + G1_AL + boff) = make_uint2(pack_lo2(v.x,v.y), pack_lo2(v.z,v.w));
    }
    #pragma unroll
    for (int t = 0; t < 16; t++) {
        int idx = tid + t*256;
        int r = idx >> 5, c4 = (idx & 31) << 2;
        float4 v = *(const float4*)(W + (size_t)(n0+r)*Fv + c4);
        uint32_t boff = (uint32_t)(r*G1_LDK + c4) * 2;
        *(uint2*)(dynsmem + G1_BH + boff) = make_uint2(pack_hi2(v.x,v.y), pack_hi2(v.z,v.w));
        *(uint2*)(dynsmem + G1_BL + boff) = make_uint2(pack_lo2(v.x,v.y), pack_lo2(v.z,v.w));
    }
    __syncthreads();

    const int wm = w >> 2, wn = w & 3;
    const uint32_t arow = (uint32_t)((wm*64 + (lane & 15))*G1_LDK + (lane >> 4)*8) * 2;
    const uint32_t brow = (uint32_t)(((lane & 7) + ((lane >> 4) << 3))*G1_LDK
                                     + (((lane >> 3) & 1)*8)) * 2;
    float c[4][4][4] = {};

    #pragma unroll
    for (int ks = 0; ks < 8; ks++) {
        uint32_t bhf[2][4], blf[2][4];
        #pragma unroll
        for (int np = 0; np < 2; np++) {
            uint32_t bt = (uint32_t)((wn*32 + np*16)*G1_LDK)*2 + (uint32_t)(ks*16)*2;
            LDMX4(bhf[np][0],bhf[np][1],bhf[np][2],bhf[np][3], sb + G1_BH + brow + bt);
            LDMX4(blf[np][0],blf[np][1],blf[np][2],blf[np][3], sb + G1_BL + brow + bt);
        }
        #pragma unroll
        for (int mt = 0; mt < 4; mt++) {
            uint32_t at = (uint32_t)(mt*16*G1_LDK)*2 + (uint32_t)(ks*16)*2;
            uint32_t ah0,ah1,ah2,ah3, al0,al1,al2,al3;
            LDMX4(ah0,ah1,ah2,ah3, sb + G1_AH + arow + at);
            LDMX4(al0,al1,al2,al3, sb + G1_AL + arow + at);
            #pragma unroll
            for (int np = 0; np < 2; np++) {
                MMA16816(c[mt][np*2],   ah0,ah1,ah2,ah3, bhf[np][0],bhf[np][1]);
                MMA16816(c[mt][np*2],   al0,al1,al2,al3, bhf[np][0],bhf[np][1]);
                MMA16816(c[mt][np*2],   ah0,ah1,ah2,ah3, blf[np][0],blf[np][1]);
                MMA16816(c[mt][np*2+1], ah0,ah1,ah2,ah3, bhf[np][2],bhf[np][3]);
                MMA16816(c[mt][np*2+1], al0,al1,al2,al3, bhf[np][2],bhf[np][3]);
                MMA16816(c[mt][np*2+1], ah0,ah1,ah2,ah3, blf[np][2],blf[np][3]);
            }
        }
    }
    __syncthreads();   // done with operand tiles; reuse as staging

    // ---- stage bf16 hi/lo: [p][ch 4][d 128][ST_STRIDE] (only [0..31] used) ----
    {
        const int g = lane >> 2, tg = lane & 3;
        #pragma unroll
        for (int mt = 0; mt < 4; mt++) {
            int r0 = wm*64 + mt*16 + g;
            #pragma unroll
            for (int nt = 0; nt < 4; nt++) {
                int d = wn*32 + nt*8 + tg*2;
                float b0 = bias[n0 + d], b1 = bias[n0 + d + 1];
                #pragma unroll
                for (int half = 0; half < 2; half++) {
                    int r = r0 + half*8;
                    float v0 = c[mt][nt][half*2]   + b0;
                    float v1 = c[mt][nt][half*2+1] + b1;
                    __nv_bfloat16 h0 = __float2bfloat16_rn(v0);
                    __nv_bfloat16 h1 = __float2bfloat16_rn(v1);
                    __nv_bfloat16 l0 = __float2bfloat16_rn(v0 - __bfloat162float(h0));
                    __nv_bfloat16 l1 = __float2bfloat16_rn(v1 - __bfloat162float(h1));
                    int ch = r >> 5, sl = r & 31;
                    uint32_t o0 = (uint32_t)((ch*128 + d)*ST_STRIDE + sl)*2;
                    uint32_t o1 = (uint32_t)((ch*128 + d + 1)*ST_STRIDE + sl)*2;
                    *(__nv_bfloat16*)(dynsmem + o0) = h0;
                    *(__nv_bfloat16*)(dynsmem + o1) = h1;
                    *(__nv_bfloat16*)(dynsmem + 40960u + o0) = l0;
                    *(__nv_bfloat16*)(dynsmem + 40960u + o1) = l1;
                }
            }
        }
    }
    __syncthreads();

    // ---- coalesced flush: 4096 uint4 ----
    {
        const int b = m0 >> 11, s0 = m0 & (Sv-1), hh = n0 >> 7;
        const int bh = b*Hv + hh;
        #pragma unroll
        for (int t = 0; t < 16; t++) {
            int cidx = tid + t*256;
            int p   = cidx >> 11;
            int rem = cidx & 2047;
            int ch  = rem >> 9;
            int d   = (rem >> 2) & 127;
            int s8  = (rem & 3) << 3;
            uint4 v = *(const uint4*)(dynsmem + (uint32_t)p*40960u
                        + (uint32_t)((ch*128 + d)*ST_STRIDE + s8)*2);
            __nv_bfloat16* dst = (p ? g_hpT_lo : g_hpT_hi)
                + (((size_t)bh*(Sv/32) + (s0 >> 5) + ch)*Dv + d)*32 + s8;
            *(uint4*)dst = v;
        }
    }
}

// ---------------------------------------------------------------
// K2a: e1,e2 per row from hpT (hi+lo), + exp tables.
// Block = 512 s of one bh; thread handles 2 consecutive s.
// ---------------------------------------------------------------
__global__ __launch_bounds__(256) void k_e12(const float* __restrict__ aw) {
    __shared__ float sa1[128], sa2[128];
    const int bh = blockIdx.x >> 2;
    const int s0 = (blockIdx.x & 3) * 512;
    const int tid = threadIdx.x;
    if (tid < 128) { sa1[tid] = aw[tid]; sa2[tid] = aw[Dv + tid]; }
    __syncthreads();

    const int s = s0 + tid*2;
    const int ch = s >> 5, sl = s & 31;
    const __nv_bfloat16* baseH = g_hpT_hi + (((size_t)bh*(Sv/32) + ch)*Dv)*32 + sl;
    const __nv_bfloat16* baseL = g_hpT_lo + (((size_t)bh*(Sv/32) + ch)*Dv)*32 + sl;

    float e1a=0.f, e1b=0.f, e2a=0.f, e2b=0.f;
    #pragma unroll 8
    for (int d = 0; d < Dv; d++) {
        __nv_bfloat162 hv = *(const __nv_bfloat162*)(baseH + (size_t)d*32);
        __nv_bfloat162 lv = *(const __nv_bfloat162*)(baseL + (size_t)d*32);
        float x0 = __low2float(hv) + __low2float(lv);
        float x1 = __high2float(hv) + __high2float(lv);
        float a1 = sa1[d], a2 = sa2[d];
        e1a += x0*a1; e1b += x1*a1;
        e2a += x0*a2; e2b += x1*a2;
    }
    const int row = bh*Sv + s;
    *(float2*)(g_e1 + row) = make_float2(e1a, e1b);
    *(float2*)(g_e2 + row) = make_float2(e2a, e2b);
    const int b = bh >> 2;
    int m0 = g_masked[b*Sv + s], m1 = g_masked[b*Sv + s + 1];
    *(float2*)(g_E2p + row) = make_float2(m0 ? 0.f : expf(e2a), m1 ? 0.f : expf(e2b));
    *(float2*)(g_E2n + row) = make_float2(m0 ? 0.f : expf(NEG*e2a), m1 ? 0.f : expf(NEG*e2b));
}

// ---------------------------------------------------------------
// K2b: per (b,h) softmax prep (key-only bitonic sort + scans + bsearch)
// ---------------------------------------------------------------
__global__ __launch_bounds__(1024) void k_prep(const float* __restrict__ ab_p) {
    __shared__ float key[Sv];
    __shared__ float v1[Sv];
    __shared__ float v2[Sv];
    __shared__ float pren[Sv+1];
    __shared__ float sufp[Sv+1];
    __shared__ float ch1[64], ch2[64];

    const int bh = blockIdx.x;
    const int b  = bh >> 2;
    const int tid = threadIdx.x;
    const float ab = ab_p[0];

    for (int j = tid; j < Sv; j += 1024) {
        float e2 = g_e2[bh*Sv + j];
        key[j] = g_masked[b*Sv + j] ? -1e30f : e2;
    }
    __syncthreads();

    for (int k = 2; k <= Sv; k <<= 1) {
        for (int j = k >> 1; j > 0; j >>= 1) {
            #pragma unroll 2
            for (int i = tid; i < Sv; i += 1024) {
                int ixj = i ^ j;
                if (ixj > i) {
                    bool up = ((i & k) == 0);
                    float ki = key[i], kj = key[ixj];
                    if ((ki > kj) == up) { key[i] = kj; key[ixj] = ki; }
                }
            }
            __syncthreads();
        }
    }

    const float M2 = key[Sv-1];
    for (int j = tid; j < Sv; j += 1024) {
        float kk = key[j];
        v1[j] = expf(kk);
        v2[j] = expf(NEG*kk);
    }
    __syncthreads();

    if (tid < 64) {
        int base = tid * 32;
        float s1 = 0.f, s2 = 0.f;
        for (int t = 0; t < 32; t++) { s1 += v1[base+t]; s2 += v2[base+t]; }
        ch1[tid] = s1; ch2[tid] = s2;
    }
    __syncthreads();
    if (tid == 0) {
        float r = 0.f;
        for (int c = 0; c < 64; c++) { float t = ch2[c]; ch2[c] = r; r += t; }
        pren[Sv] = r;
        r = 0.f;
        for (int c = 63; c >= 0; c--) { float t = ch1[c]; ch1[c] = r; r += t; }
    }
    __syncthreads();
    if (tid < 64) {
        int base = tid * 32;
        float run = ch2[tid];
        for (int t = 0; t < 32; t++) { pren[base+t] = run; run += v2[base+t]; }
        float runs = ch1[tid];
        for (int t = 31; t >= 0; t--) { runs += v1[base+t]; sufp[base+t] = runs; }
    }
    if (tid == 0) sufp[Sv] = 0.f;
    __syncthreads();

    for (int i = tid; i < Sv; i += 1024) {
        float e1 = g_e1[bh*Sv + i];
        float eb = e1 + ab;
        float pre = eb + M2;
        float m = (pre > 0.f) ? pre : NEG*pre;
        float th = -eb;
        float A  = expf(eb - m);
        float Bc = expf(NEG*eb - m);
        int lo = 0, hi = Sv;
        while (lo < hi) {
            int mid = (lo + hi) >> 1;
            if (key[mid] <= th) lo = mid + 1; else hi = mid;
        }
        float rowsum = A*sufp[lo] + Bc*pren[lo];
        float inv = 1.0f / rowsum;
        g_An[bh*Sv + i] = A * inv;
        g_Bn[bh*Sv + i] = Bc * inv;
        g_th[bh*Sv + i] = th;
    }
}

// ---------------------------------------------------------------
// K3: mma.sync bf16 3-split, single-wave, single-sync pipeline.
// Same as R5 except epilogue writes ctx as bf16 hi/lo.
// ---------------------------------------------------------------
#define KT 64
#define LDB 144
#define A_TSZ (256*LDB)
#define B_TSZ (128*LDB)
#define OFF_A(q,p) ((uint32_t)(((q)*2+(p))*A_TSZ))
#define OFF_B(q,p) ((uint32_t)(147456 + ((q)*2+(p))*B_TSZ))
#define OFF_CONST  221184u
#define ATTN_SMEM  (221184 + 3072)

__device__ __forceinline__ void fill_B(int bh, int jt, uint32_t sb, int q, int tid) {
    const int c0 = jt >> 5;
    const size_t base = ((size_t)bh*(Sv/32) + c0) * Dv * 32;
    #pragma unroll
    for (int t = 0; t < 2; t++) {
        int cidx = tid + t*512;
        int d  = cidx >> 3;
        int jc = (cidx >> 2) & 1;
        int s8 = (cidx & 3) * 8;
        CP16(sb + OFF_B(q,0) + (uint32_t)(d*LDB + (jc*32 + s8)*2),
             g_hpT_hi + base + ((size_t)jc*Dv + d)*32 + s8);
    }
    #pragma unroll
    for (int t = 0; t < 2; t++) {
        int cidx = tid + t*512;
        int d  = cidx >> 3;
        int jc = (cidx >> 2) & 1;
        int s8 = (cidx & 3) * 8;
        CP16(sb + OFF_B(q,1) + (uint32_t)(d*LDB + (jc*32 + s8)*2),
             g_hpT_lo + base + ((size_t)jc*Dv + d)*32 + s8);
    }
}

__global__ __launch_bounds__(512, 1) void k_attn(float* __restrict__ attn_out) {
    const int bh = blockIdx.y;
    const int i0 = blockIdx.x * 256;
    const int tid = threadIdx.x;
    const int w = tid >> 5;
    const int lane = tid & 31;
    const uint32_t sb = smem_u32(dynsmem);

    float* sTh = (float*)(dynsmem + OFF_CONST);
    float* sAn = sTh + 256;
    float* sBn = sAn + 256;

    fill_B(bh, 0, sb, 0, tid);
    CP_COMMIT();
    if (tid < 256) {
        sTh[tid] = g_th[bh*Sv + i0 + tid];
        sAn[tid] = g_An[bh*Sv + i0 + tid];
        sBn[tid] = g_Bn[bh*Sv + i0 + tid];
    }
    __syncthreads();

    const int j0 = lane * 2;
    const int wm = w >> 2, wn = w & 3;
    const uint32_t aoff = (uint32_t)((wm*64 + (lane & 15))*LDB + ((lane >> 4)*8)*2);
    const uint32_t boff = (uint32_t)(((lane & 7) + ((lane >> 4) << 3))*LDB + (((lane >> 3) & 1)*8)*2);

    float c[4][4][4] = {};
    float* attn_base = attn_out + ((size_t)(bh*Sv + i0)) * Sv;

    {
        float2 e2v = *(const float2*)(g_e2  + bh*Sv + j0);
        float2 epv = *(const float2*)(g_E2p + bh*Sv + j0);
        float2 env = *(const float2*)(g_E2n + bh*Sv + j0);
        unsigned char* Aqh = dynsmem + OFF_A(0,0);
        unsigned char* Aql = dynsmem + OFF_A(0,1);
        #pragma unroll
        for (int rr = 0; rr < 16; rr++) {
            int r = w*16 + rr;
            float th = sTh[r], An = sAn[r], Bn = sBn[r];
            float p0 = (e2v.x > th) ? An*epv.x : Bn*env.x;
            float p1 = (e2v.y > th) ? An*epv.y : Bn*env.y;
            *(float2*)(attn_base + (size_t)r*Sv + j0) = make_float2(p0, p1);
            *(uint32_t*)(Aqh + r*LDB + j0*2) = pack_hi2(p0, p1);
            *(uint32_t*)(Aql + r*LDB + j0*2) = pack_lo2(p0, p1);
        }
    }

    #pragma unroll 1
    for (int iter = 0; iter < Sv/KT; iter++) {
        const int q = iter & 1;

        CP_WAIT0();
        __syncthreads();

        if (iter < Sv/KT - 1) {
            fill_B(bh, (iter+1)*KT, sb, q^1, tid);
            CP_COMMIT();
            const int jt1 = (iter+1)*KT;
            float2 e2v = *(const float2*)(g_e2  + bh*Sv + jt1 + j0);
            float2 epv = *(const float2*)(g_E2p + bh*Sv + jt1 + j0);
            float2 env = *(const float2*)(g_E2n + bh*Sv + jt1 + j0);
            unsigned char* Aqh = dynsmem + OFF_A(q^1,0);
            unsigned char* Aql = dynsmem + OFF_A(q^1,1);
            #pragma unroll
            for (int rr = 0; rr < 16; rr++) {
                int r = w*16 + rr;
                float th = sTh[r], An = sAn[r], Bn = sBn[r];
                float p0 = (e2v.x > th) ? An*epv.x : Bn*env.x;
                float p1 = (e2v.y > th) ? An*epv.y : Bn*env.y;
                *(float2*)(attn_base + (size_t)r*Sv + jt1 + j0) = make_float2(p0, p1);
                *(uint32_t*)(Aqh + r*LDB + j0*2) = pack_hi2(p0, p1);
                *(uint32_t*)(Aql + r*LDB + j0*2) = pack_lo2(p0, p1);
            }
        }

        #pragma unroll
        for (int ks = 0; ks < 4; ks++) {
            uint32_t bhf[2][4], blf[2][4];
            #pragma unroll
            for (int np = 0; np < 2; np++) {
                uint32_t bt = (uint32_t)((wn*32 + np*16)*LDB + ks*32);
                LDMX4(bhf[np][0],bhf[np][1],bhf[np][2],bhf[np][3], sb + OFF_B(q,0) + boff + bt);
                LDMX4(blf[np][0],blf[np][1],blf[np][2],blf[np][3], sb + OFF_B(q,1) + boff + bt);
            }
            #pragma unroll
            for (int mt = 0; mt < 4; mt++) {
                uint32_t ah0,ah1,ah2,ah3, al0,al1,al2,al3;
                LDMX4(ah0,ah1,ah2,ah3, sb + OFF_A(q,0) + aoff + mt*16*LDB + ks*32);
                LDMX4(al0,al1,al2,al3, sb + OFF_A(q,1) + aoff + mt*16*LDB + ks*32);
                #pragma unroll
                for (int np = 0; np < 2; np++) {
                    MMA16816(c[mt][np*2],   ah0,ah1,ah2,ah3, bhf[np][0],bhf[np][1]);
                    MMA16816(c[mt][np*2],   al0,al1,al2,al3, bhf[np][0],bhf[np][1]);
                    MMA16816(c[mt][np*2],   ah0,ah1,ah2,ah3, blf[np][0],blf[np][1]);
                    MMA16816(c[mt][np*2+1], ah0,ah1,ah2,ah3, bhf[np][2],bhf[np][3]);
                    MMA16816(c[mt][np*2+1], al0,al1,al2,al3, bhf[np][2],bhf[np][3]);
                    MMA16816(c[mt][np*2+1], ah0,ah1,ah2,ah3, blf[np][2],blf[np][3]);
                }
            }
        }
    }

    // ---- epilogue: C frags -> ctx bf16 hi/lo ----
    {
        const int b = bh >> 2, hh = bh & 3;
        const int g = lane >> 2, tg = lane & 3;
        #pragma unroll
        for (int mt = 0; mt < 4; mt++) {
            int ibase = i0 + wm*64 + mt*16;
            #pragma unroll
            for (int nt = 0; nt < 4; nt++) {
                int d = wn*32 + nt*8 + tg*2;
                size_t o0 = ((size_t)(b*Sv + ibase + g))*HDv + hh*Dv + d;
                size_t o1 = ((size_t)(b*Sv + ibase + g + 8))*HDv + hh*Dv + d;
                *(uint32_t*)(g_ctxb_hi + o0) = pack_hi2(c[mt][nt][0], c[mt][nt][1]);
                *(uint32_t*)(g_ctxb_lo + o0) = pack_lo2(c[mt][nt][0], c[mt][nt][1]);
                *(uint32_t*)(g_ctxb_hi + o1) = pack_hi2(c[mt][nt][2], c[mt][nt][3]);
                *(uint32_t*)(g_ctxb_lo + o1) = pack_lo2(c[mt][nt][2], c[mt][nt][3]);
            }
        }
    }
}

// ---------------------------------------------------------------
// K4: out = relu(ctx @ out_w^T + out_b) via bf16 3-split mma.sync.
// Block = 64 m x 128 n (full OUT); K=512 in 8 chunks of 64, cp.async x2 buf.
// ---------------------------------------------------------------
#define G2_LDK 72
#define G2_AT (64*G2_LDK*2)             /* 9216  */
#define G2_BT (128*G2_LDK*2)            /* 18432 */
#define G2_BUF (2*G2_AT + 2*G2_BT)      /* 55296 */
#define G2_AH(q) ((uint32_t)((q)*G2_BUF))
#define G2_AL(q) ((uint32_t)((q)*G2_BUF + G2_AT))
#define G2_BH(q) ((uint32_t)((q)*G2_BUF + 2*G2_AT))
#define G2_BL(q) ((uint32_t)((q)*G2_BUF + 2*G2_AT + G2_BT))
#define G2_SMEM (2*G2_BUF)              /* 110592 */

__device__ __forceinline__ void g2_fill(int m0, int ch, uint32_t sb, int q, int tid) {
    const int k0 = ch * 64;
    #pragma unroll
    for (int t = 0; t < 4; t++) {                 // A: 1024 cp
        int idx = tid + t*256;
        int p  = idx >> 9;
        int r  = (idx >> 3) & 63;
        int c8 = (idx & 7) * 8;
        const __nv_bfloat16* src = (p ? g_ctxb_lo : g_ctxb_hi)
            + (size_t)(m0 + r)*HDv + k0 + c8;
        CP16(sb + (p ? G2_AL(q) : G2_AH(q)) + (uint32_t)(r*G2_LDK + c8)*2, src);
    }
    #pragma unroll
    for (int t = 0; t < 8; t++) {                 // B: 2048 cp
        int idx = tid + t*256;
        int p  = idx >> 10;
        int r  = (idx >> 3) & 127;
        int c8 = (idx & 7) * 8;
        const __nv_bfloat16* src = (p ? g_wb_lo : g_wb_hi)
            + (size_t)r*HDv + k0 + c8;
        CP16(sb + (p ? G2_BL(q) : G2_BH(q)) + (uint32_t)(r*G2_LDK + c8)*2, src);
    }
}

__global__ __launch_bounds__(256, 1) void k_gemm2t(const float* __restrict__ bias,
                                                   float* __restrict__ out) {
    const int m0 = blockIdx.x * 64;
    const int tid = threadIdx.x;
    const int w = tid >> 5, lane = tid & 31;
    const uint32_t sb = smem_u32(dynsmem);

    g2_fill(m0, 0, sb, 0, tid);
    CP_COMMIT();

    const int wm = w >> 2, wn = w & 3;
    const uint32_t arow = (uint32_t)((wm*32 + (lane & 15))*G2_LDK + (lane >> 4)*8) * 2;
    const uint32_t brow = (uint32_t)(((lane & 7) + ((lane >> 4) << 3))*G2_LDK
                                     + (((lane >> 3) & 1)*8)) * 2;
    float c[2][4][4] = {};

    #pragma unroll 1
    for (int ch = 0; ch < 8; ch++) {
        const int q = ch & 1;
        if (ch < 7) { g2_fill(m0, ch+1, sb, q^1, tid); CP_COMMIT(); CP_WAIT1(); }
        else        { CP_WAIT0(); }
        __syncthreads();

        #pragma unroll
        for (int ks = 0; ks < 4; ks++) {
            uint32_t bhf[2][4], blf[2][4];
            #pragma unroll
            for (int np = 0; np < 2; np++) {
                uint32_t bt = (uint32_t)((wn*32 + np*16)*G2_LDK)*2 + (uint32_t)(ks*16)*2;
                LDMX4(bhf[np][0],bhf[np][1],bhf[np][2],bhf[np][3], sb + G2_BH(q) + brow + bt);
                LDMX4(blf[np][0],blf[np][1],blf[np][2],blf[np][3], sb + G2_BL(q) + brow + bt);
            }
            #pragma unroll
            for (int mt = 0; mt < 2; mt++) {
                uint32_t at = (uint32_t)(mt*16*G2_LDK)*2 + (uint32_t)(ks*16)*2;
                uint32_t ah0,ah1,ah2,ah3, al0,al1,al2,al3;
                LDMX4(ah0,ah1,ah2,ah3, sb + G2_AH(q) + arow + at);
                LDMX4(al0,al1,al2,al3, sb + G2_AL(q) + arow + at);
                #pragma unroll
                for (int np = 0; np < 2; np++) {
                    MMA16816(c[mt][np*2],   ah0,ah1,ah2,ah3, bhf[np][0],bhf[np][1]);
                    MMA16816(c[mt][np*2],   al0,al1,al2,al3, bhf[np][0],bhf[np][1]);
                    MMA16816(c[mt][np*2],   ah0,ah1,ah2,ah3, blf[np][0],blf[np][1]);
                    MMA16816(c[mt][np*2+1], ah0,ah1,ah2,ah3, bhf[np][2],bhf[np][3]);
                    MMA16816(c[mt][np*2+1], al0,al1,al2,al3, bhf[np][2],bhf[np][3]);
                    MMA16816(c[mt][np*2+1], ah0,ah1,ah2,ah3, blf[np][2],blf[np][3]);
                }
            }
        }
        __syncthreads();
    }

    // ---- epilogue: bias + relu -> out ----
    {
        const int g = lane >> 2, tg = lane & 3;
        #pragma unroll
        for (int mt = 0; mt < 2; mt++) {
            int r0 = m0 + wm*32 + mt*16 + g;
            #pragma unroll
            for (int nt = 0; nt < 4; nt++) {
                int n = wn*32 + nt*8 + tg*2;
                float b0 = bias[n], b1 = bias[n+1];
                float v0 = c[mt][nt][0] + b0, v1 = c[mt][nt][1] + b1;
                float v2 = c[mt][nt][2] + b0, v3 = c[mt][nt][3] + b1;
                *(float2*)(out + (size_t)r0*OUTv + n) =
                    make_float2(v0 > 0.f ? v0 : 0.f, v1 > 0.f ? v1 : 0.f);
                *(float2*)(out + (size_t)(r0+8)*OUTv + n) =
                    make_float2(v2 > 0.f ? v2 : 0.f, v3 > 0.f ? v3 : 0.f);
            }
        }
    }
}

// ---------------------------------------------------------------
extern "C" void kernel_launch(void* const* d_in, const int* in_sizes, int n_in,
                              void* d_out, int out_size) {
    const float* h     = (const float*)d_in[0];
    const void*  mask  = d_in[1];
    const float* W_w   = (const float*)d_in[2];
    const float* W_b   = (const float*)d_in[3];
    const float* a_w   = (const float*)d_in[4];
    const float* a_b   = (const float*)d_in[5];
    const float* out_w = (const float*)d_in[6];
    const float* out_b = (const float*)d_in[7];

    float* out  = (float*)d_out;
    float* attn = out + (size_t)Bv*Sv*OUTv;

    static int attr_set = 0;
    if (!attr_set) {
        cudaFuncSetAttribute(k_attn,   cudaFuncAttributeMaxDynamicSharedMemorySize, ATTN_SMEM);
        cudaFuncSetAttribute(k_gemm1t, cudaFuncAttributeMaxDynamicSharedMemorySize, G1_SMEM);
        cudaFuncSetAttribute(k_gemm2t, cudaFuncAttributeMaxDynamicSharedMemorySize, G2_SMEM);
        attr_set = 1;
    }

    k_mask  <<<1, 256>>>(mask);
    k_wcvt  <<<64, 256>>>(out_w);
    k_gemm1t<<<dim3(64, 4), 256, G1_SMEM>>>(h, W_w, W_b);
    k_e12   <<<64, 256>>>(a_w);
    k_prep  <<<BHv, 1024>>>(a_b);
    k_attn  <<<dim3(Sv/256, BHv), 512, ATTN_SMEM>>>(attn);
    k_gemm2t<<<128, 256, G2_SMEM>>>(out_b, out);
}

// round 7
// speedup vs baseline: 3.0083x; 1.2933x over previous
#include <cuda_runtime.h>
#include <cuda_bf16.h>
#include <math.h>
#include <stdint.h>

#define Bv 4
#define Sv 2048
#define Fv 128
#define Hv 4
#define Dv 128
#define HDv 512
#define OUTv 128
#define BHv 16
#define NSv (BHv*Sv)
#define NEG 0.01f

// ---- device scratch ----
__device__ float g_hp[NSv*Dv];          // fp32 [bh][s][d]
__device__ float g_e1[NSv];
__device__ float g_e2[NSv];
__device__ float g_An[NSv];
__device__ float g_Bn[NSv];
__device__ float g_th[NSv];
__device__ float g_E2p[NSv];
__device__ float g_E2n[NSv];
__device__ int   g_lo[NSv];
__device__ int   g_perm[NSv];
__device__ float g_sEp[NSv];
__device__ float g_sEn[NSv];
__device__ int   g_masked[Bv*Sv];
__device__ float g_pre[BHv*2049*Dv];    // prefix of En*hp over sorted order
__device__ float g_suf[BHv*2049*Dv];    // suffix of Ep*hp over sorted order
// ctx in bf16 hi/lo, k-major [b][s][h*D+d]
__device__ __nv_bfloat16 g_ctxb_hi[Bv*Sv*HDv];
__device__ __nv_bfloat16 g_ctxb_lo[Bv*Sv*HDv];
// out_w bf16 hi/lo [n][k]
__device__ __nv_bfloat16 g_wb_hi[OUTv*HDv];
__device__ __nv_bfloat16 g_wb_lo[OUTv*HDv];

__device__ __forceinline__ uint32_t smem_u32(const void* p) {
    uint32_t a;
    asm("{ .reg .u64 t; cvta.to.shared.u64 t, %1; cvt.u32.u64 %0, t; }" : "=r"(a) : "l"(p));
    return a;
}
#define LDMX4(r0,r1,r2,r3,addr) \
    asm volatile("ldmatrix.sync.aligned.m8n8.x4.shared.b16 {%0,%1,%2,%3}, [%4];" \
        : "=r"(r0),"=r"(r1),"=r"(r2),"=r"(r3) : "r"(addr))
#define MMA16816(c,a0,a1,a2,a3,b0,b1) \
    asm volatile("mma.sync.aligned.m16n8k16.row.col.f32.bf16.bf16.f32 " \
        "{%0,%1,%2,%3}, {%4,%5,%6,%7}, {%8,%9}, {%0,%1,%2,%3};" \
        : "+f"((c)[0]),"+f"((c)[1]),"+f"((c)[2]),"+f"((c)[3]) \
        : "r"(a0),"r"(a1),"r"(a2),"r"(a3), "r"(b0),"r"(b1))
#define CP16(dst, src) \
    asm volatile("cp.async.cg.shared.global [%0], [%1], 16;" :: "r"(dst), "l"(src) : "memory")
#define CP_COMMIT() asm volatile("cp.async.commit_group;" ::: "memory")
#define CP_WAIT1()  asm volatile("cp.async.wait_group 1;" ::: "memory")
#define CP_WAIT0()  asm volatile("cp.async.wait_group 0;" ::: "memory")

__device__ __forceinline__ uint32_t pack_hi2(float a, float b) {
    __nv_bfloat16 ha = __float2bfloat16_rn(a), hb = __float2bfloat16_rn(b);
    return ((uint32_t)__bfloat16_as_ushort(hb) << 16) | __bfloat16_as_ushort(ha);
}
__device__ __forceinline__ uint32_t pack_lo2(float a, float b) {
    __nv_bfloat16 ha = __float2bfloat16_rn(a), hb = __float2bfloat16_rn(b);
    float ra = a - __bfloat162float(ha), rb = b - __bfloat162float(hb);
    __nv_bfloat16 la = __float2bfloat16_rn(ra), lb = __float2bfloat16_rn(rb);
    return ((uint32_t)__bfloat16_as_ushort(lb) << 16) | __bfloat16_as_ushort(la);
}

extern __shared__ __align__(128) unsigned char dynsmem[];

// ---------------------------------------------------------------
// K0: decode mask buffer (u8 vs i32 by byte sum)
// ---------------------------------------------------------------
__global__ void k_mask(const void* mraw) {
    __shared__ int ssum[256];
    __shared__ int fmt;
    const unsigned char* mb = (const unsigned char*)mraw;
    int tid = threadIdx.x;
    int s = 0;
    for (int i = tid; i < Bv*Sv; i += 256) s += mb[i];
    ssum[tid] = s;
    __syncthreads();
    for (int st = 128; st > 0; st >>= 1) {
        if (tid < st) ssum[tid] += ssum[tid + st];
        __syncthreads();
    }
    if (tid == 0) fmt = (ssum[0] > (Bv*Sv*5/16)) ? 1 : 0;
    __syncthreads();
    if (fmt) {
        for (int i = tid; i < Bv*Sv; i += 256) g_masked[i] = (mb[i] != 0);
    } else {
        const int* mi = (const int*)mraw;
        for (int i = tid; i < Bv*Sv; i += 256) g_masked[i] = (mi[i] != 0);
    }
}

// ---------------------------------------------------------------
// K0b: convert out_w to bf16 hi/lo
// ---------------------------------------------------------------
__global__ void k_wcvt(const float* __restrict__ W) {
    int i = blockIdx.x * 256 + threadIdx.x;
    float4 v = *(const float4*)(W + (size_t)i*4);
    *(uint2*)(g_wb_hi + (size_t)i*4) = make_uint2(pack_hi2(v.x,v.y), pack_hi2(v.z,v.w));
    *(uint2*)(g_wb_lo + (size_t)i*4) = make_uint2(pack_lo2(v.x,v.y), pack_lo2(v.z,v.w));
}

// ---------------------------------------------------------------
// K1: hp = h @ W_w^T + W_b via bf16 3-split mma.sync.
// Block = 128 m x 128 n (one head's full D). Epilogue writes g_hp fp32
// and fuses the e1/e2 row reductions + exp tables (block owns full D).
// ---------------------------------------------------------------
#define G1_LDK 136
#define G1_T  (128*G1_LDK*2)
#define G1_AH 0u
#define G1_AL ((uint32_t)G1_T)
#define G1_BH ((uint32_t)(2*G1_T))
#define G1_BL ((uint32_t)(3*G1_T))
#define G1_RED ((uint32_t)(4*G1_T))          /* 4096 B: red[128][4][2] */
#define G1_SA  ((uint32_t)(4*G1_T + 4096))   /* 1024 B: a1[128], a2[128] */
#define G1_SMEM (4*G1_T + 4096 + 1024)

__global__ __launch_bounds__(256, 1) void k_gemm1t(const float* __restrict__ A,
                                                   const float* __restrict__ W,
                                                   const float* __restrict__ bias,
                                                   const float* __restrict__ aw) {
    const int m0 = blockIdx.x * 128;
    const int n0 = blockIdx.y * 128;
    const int tid = threadIdx.x;
    const int w = tid >> 5, lane = tid & 31;
    const uint32_t sb = smem_u32(dynsmem);

    if (tid < 256) ((float*)(dynsmem + G1_SA))[tid] = aw[tid];

    #pragma unroll
    for (int t = 0; t < 16; t++) {
        int idx = tid + t*256;
        int r = idx >> 5, c4 = (idx & 31) << 2;
        float4 v = *(const float4*)(A + (size_t)(m0+r)*Fv + c4);
        uint32_t boff = (uint32_t)(r*G1_LDK + c4) * 2;
        *(uint2*)(dynsmem + G1_AH + boff) = make_uint2(pack_hi2(v.x,v.y), pack_hi2(v.z,v.w));
        *(uint2*)(dynsmem + G1_AL + boff) = make_uint2(pack_lo2(v.x,v.y), pack_lo2(v.z,v.w));
    }
    #pragma unroll
    for (int t = 0; t < 16; t++) {
        int idx = tid + t*256;
        int r = idx >> 5, c4 = (idx & 31) << 2;
        float4 v = *(const float4*)(W + (size_t)(n0+r)*Fv + c4);
        uint32_t boff = (uint32_t)(r*G1_LDK + c4) * 2;
        *(uint2*)(dynsmem + G1_BH + boff) = make_uint2(pack_hi2(v.x,v.y), pack_hi2(v.z,v.w));
        *(uint2*)(dynsmem + G1_BL + boff) = make_uint2(pack_lo2(v.x,v.y), pack_lo2(v.z,v.w));
    }
    __syncthreads();

    const int wm = w >> 2, wn = w & 3;
    const uint32_t arow = (uint32_t)((wm*64 + (lane & 15))*G1_LDK + (lane >> 4)*8) * 2;
    const uint32_t brow = (uint32_t)(((lane & 7) + ((lane >> 4) << 3))*G1_LDK
                                     + (((lane >> 3) & 1)*8)) * 2;
    float c[4][4][4] = {};

    #pragma unroll
    for (int ks = 0; ks < 8; ks++) {
        uint32_t bhf[2][4], blf[2][4];
        #pragma unroll
        for (int np = 0; np < 2; np++) {
            uint32_t bt = (uint32_t)((wn*32 + np*16)*G1_LDK)*2 + (uint32_t)(ks*16)*2;
            LDMX4(bhf[np][0],bhf[np][1],bhf[np][2],bhf[np][3], sb + G1_BH + brow + bt);
            LDMX4(blf[np][0],blf[np][1],blf[np][2],blf[np][3], sb + G1_BL + brow + bt);
        }
        #pragma unroll
        for (int mt = 0; mt < 4; mt++) {
            uint32_t at = (uint32_t)(mt*16*G1_LDK)*2 + (uint32_t)(ks*16)*2;
            uint32_t ah0,ah1,ah2,ah3, al0,al1,al2,al3;
            LDMX4(ah0,ah1,ah2,ah3, sb + G1_AH + arow + at);
            LDMX4(al0,al1,al2,al3, sb + G1_AL + arow + at);
            #pragma unroll
            for (int np = 0; np < 2; np++) {
                MMA16816(c[mt][np*2],   ah0,ah1,ah2,ah3, bhf[np][0],bhf[np][1]);
                MMA16816(c[mt][np*2],   al0,al1,al2,al3, bhf[np][0],bhf[np][1]);
                MMA16816(c[mt][np*2],   ah0,ah1,ah2,ah3, blf[np][0],blf[np][1]);
                MMA16816(c[mt][np*2+1], ah0,ah1,ah2,ah3, bhf[np][2],bhf[np][3]);
                MMA16816(c[mt][np*2+1], al0,al1,al2,al3, bhf[np][2],bhf[np][3]);
                MMA16816(c[mt][np*2+1], ah0,ah1,ah2,ah3, blf[np][2],blf[np][3]);
            }
        }
    }

    // ---- epilogue: g_hp fp32 + fused e1/e2 reduction ----
    const int bb = m0 >> 11, s0 = m0 & (Sv-1), hh = n0 >> 7;
    const int bh = bb*Hv + hh;
    const int g = lane >> 2, tg = lane & 3;
    float* red = (float*)(dynsmem + G1_RED);
    const float* sa1 = (const float*)(dynsmem + G1_SA);
    const float* sa2 = sa1 + 128;

    float pe1[4][2] = {}, pe2[4][2] = {};
    #pragma unroll
    for (int mt = 0; mt < 4; mt++) {
        #pragma unroll
        for (int nt = 0; nt < 4; nt++) {
            int d = wn*32 + nt*8 + tg*2;
            float b0 = bias[n0 + d], b1 = bias[n0 + d + 1];
            float a10 = sa1[d], a11 = sa1[d+1];
            float a20 = sa2[d], a21 = sa2[d+1];
            #pragma unroll
            for (int half = 0; half < 2; half++) {
                int r = wm*64 + mt*16 + half*8 + g;
                float v0 = c[mt][nt][half*2]   + b0;
                float v1 = c[mt][nt][half*2+1] + b1;
                *(float2*)(g_hp + ((size_t)bh*Sv + s0 + r)*Dv + d) = make_float2(v0, v1);
                pe1[mt][half] += v0*a10 + v1*a11;
                pe2[mt][half] += v0*a20 + v1*a21;
            }
        }
    }
    #pragma unroll
    for (int mt = 0; mt < 4; mt++) {
        #pragma unroll
        for (int half = 0; half < 2; half++) {
            float e1 = pe1[mt][half], e2 = pe2[mt][half];
            e1 += __shfl_xor_sync(0xffffffffu, e1, 1);
            e1 += __shfl_xor_sync(0xffffffffu, e1, 2);
            e2 += __shfl_xor_sync(0xffffffffu, e2, 1);
            e2 += __shfl_xor_sync(0xffffffffu, e2, 2);
            if (tg == 0) {
                int r = wm*64 + mt*16 + half*8 + g;
                red[(r*4 + wn)*2 + 0] = e1;
                red[(r*4 + wn)*2 + 1] = e2;
            }
        }
    }
    __syncthreads();
    if (tid < 128) {
        int r = tid;
        float e1 = red[(r*4+0)*2] + red[(r*4+1)*2] + red[(r*4+2)*2] + red[(r*4+3)*2];
        float e2 = red[(r*4+0)*2+1] + red[(r*4+1)*2+1] + red[(r*4+2)*2+1] + red[(r*4+3)*2+1];
        int s = s0 + r;
        int row = bh*Sv + s;
        g_e1[row] = e1;
        g_e2[row] = e2;
        int msk = g_masked[bb*Sv + s];
        g_E2p[row] = msk ? 0.f : expf(e2);
        g_E2n[row] = msk ? 0.f : expf(NEG*e2);
    }
}

// ---------------------------------------------------------------
// K2: per (b,h) softmax prep. uint64 (key|idx) bitonic sort, then
// exp tables, perm/sorted-exp output, scalar scans, per-row bsearch
// -> An, Bn, th, lo. Dynamic smem.
// ---------------------------------------------------------------
#define P_SKEY 0u
#define P_KEYF 16384u
#define P_V1   24576u
#define P_V2   32768u
#define P_PREN 40960u
#define P_SUFP 49408u
#define P_CH1  57856u
#define P_CH2  58112u
#define PREP_SMEM 58880

__device__ __forceinline__ uint32_t f2sort(float f) {
    uint32_t u = __float_as_uint(f);
    return (u & 0x80000000u) ? ~u : (u | 0x80000000u);
}
__device__ __forceinline__ float sort2f(uint32_t s) {
    uint32_t u = (s & 0x80000000u) ? (s ^ 0x80000000u) : ~s;
    return __uint_as_float(u);
}

__global__ __launch_bounds__(1024) void k_prep(const float* __restrict__ ab_p) {
    unsigned long long* skey = (unsigned long long*)(dynsmem + P_SKEY);
    float* keyf = (float*)(dynsmem + P_KEYF);
    float* v1   = (float*)(dynsmem + P_V1);
    float* v2   = (float*)(dynsmem + P_V2);
    float* pren = (float*)(dynsmem + P_PREN);
    float* sufp = (float*)(dynsmem + P_SUFP);
    float* ch1  = (float*)(dynsmem + P_CH1);
    float* ch2  = (float*)(dynsmem + P_CH2);

    const int bh = blockIdx.x;
    const int b  = bh >> 2;
    const int tid = threadIdx.x;
    const float ab = ab_p[0];

    for (int j = tid; j < Sv; j += 1024) {
        float e2 = g_e2[bh*Sv + j];
        float kf = g_masked[b*Sv + j] ? -1e30f : e2;
        skey[j] = ((unsigned long long)f2sort(kf) << 32) | (unsigned)j;
    }
    __syncthreads();

    for (int k = 2; k <= Sv; k <<= 1) {
        for (int j = k >> 1; j > 0; j >>= 1) {
            #pragma unroll 2
            for (int i = tid; i < Sv; i += 1024) {
                int ixj = i ^ j;
                if (ixj > i) {
                    bool up = ((i & k) == 0);
                    unsigned long long ki = skey[i], kj = skey[ixj];
                    if ((ki > kj) == up) { skey[i] = kj; skey[ixj] = ki; }
                }
            }
            __syncthreads();
        }
    }

    for (int n = tid; n < Sv; n += 1024) {
        unsigned long long kv = skey[n];
        float kf = sort2f((uint32_t)(kv >> 32));
        int jj = (int)(kv & 0xffffffffu);
        float ep = expf(kf), en = expf(NEG*kf);
        keyf[n] = kf; v1[n] = ep; v2[n] = en;
        g_perm[bh*Sv + n] = jj;
        g_sEp[bh*Sv + n] = ep;
        g_sEn[bh*Sv + n] = en;
    }
    __syncthreads();

    const float M2 = keyf[Sv-1];

    if (tid < 64) {
        int base = tid * 32;
        float s1 = 0.f, s2 = 0.f;
        for (int t = 0; t < 32; t++) { s1 += v1[base+t]; s2 += v2[base+t]; }
        ch1[tid] = s1; ch2[tid] = s2;
    }
    __syncthreads();
    if (tid == 0) {
        float r = 0.f;
        for (int c = 0; c < 64; c++) { float t = ch2[c]; ch2[c] = r; r += t; }
        pren[Sv] = r;
        r = 0.f;
        for (int c = 63; c >= 0; c--) { float t = ch1[c]; ch1[c] = r; r += t; }
    }
    __syncthreads();
    if (tid < 64) {
        int base = tid * 32;
        float run = ch2[tid];
        for (int t = 0; t < 32; t++) { pren[base+t] = run; run += v2[base+t]; }
        float runs = ch1[tid];
        for (int t = 31; t >= 0; t--) { runs += v1[base+t]; sufp[base+t] = runs; }
    }
    if (tid == 0) sufp[Sv] = 0.f;
    __syncthreads();

    for (int i = tid; i < Sv; i += 1024) {
        float e1 = g_e1[bh*Sv + i];
        float eb = e1 + ab;
        float pre = eb + M2;
        float m = (pre > 0.f) ? pre : NEG*pre;
        float th = -eb;
        float A  = expf(eb - m);
        float Bc = expf(NEG*eb - m);
        int lo = 0, hi = Sv;
        while (lo < hi) {
            int mid = (lo + hi) >> 1;
            if (keyf[mid] <= th) lo = mid + 1; else hi = mid;
        }
        float rowsum = A*sufp[lo] + Bc*pren[lo];
        float inv = 1.0f / rowsum;
        g_An[bh*Sv + i] = A * inv;
        g_Bn[bh*Sv + i] = Bc * inv;
        g_th[bh*Sv + i] = th;
        g_lo[bh*Sv + i] = lo;
    }
}

// ---------------------------------------------------------------
// K3a: build PRE/SUF tables. Block = (bh, dir); 128 threads = d.
// ---------------------------------------------------------------
__global__ __launch_bounds__(128) void k_scan() {
    __shared__ float wv[Sv];
    __shared__ int pm[Sv];
    const int bh  = blockIdx.x >> 1;
    const int dir = blockIdx.x & 1;
    const int d = threadIdx.x;
    const float* src = dir ? (g_sEp + bh*Sv) : (g_sEn + bh*Sv);
    for (int n = d; n < Sv; n += 128) { wv[n] = src[n]; pm[n] = g_perm[bh*Sv + n]; }
    __syncthreads();

    const float* hp = g_hp + (size_t)bh*Sv*Dv;
    float acc = 0.f;
    if (dir == 0) {
        float* pre = g_pre + (size_t)bh*2049*Dv;
        for (int base = 0; base < Sv; base += 8) {
            float vals[8];
            #pragma unroll
            for (int k = 0; k < 8; k++) vals[k] = hp[(size_t)pm[base+k]*Dv + d];
            #pragma unroll
            for (int k = 0; k < 8; k++) {
                pre[(size_t)(base+k)*Dv + d] = acc;
                acc += wv[base+k]*vals[k];
            }
        }
        pre[(size_t)Sv*Dv + d] = acc;
    } else {
        float* suf = g_suf + (size_t)bh*2049*Dv;
        suf[(size_t)Sv*Dv + d] = 0.f;
        for (int base = Sv-8; base >= 0; base -= 8) {
            float vals[8];
            #pragma unroll
            for (int k = 7; k >= 0; k--) vals[k] = hp[(size_t)pm[base+k]*Dv + d];
            #pragma unroll
            for (int k = 7; k >= 0; k--) {
                acc += wv[base+k]*vals[k];
                suf[(size_t)(base+k)*Dv + d] = acc;
            }
        }
    }
}

// ---------------------------------------------------------------
// K3b: attn write: p_ij streamed, pure bandwidth.
// Block = one row (bh,i), 256 threads x 2 float4.
// ---------------------------------------------------------------
__global__ __launch_bounds__(256) void k_attnw(float* __restrict__ attn_out) {
    const int row = blockIdx.x;
    const int bh = row >> 11;
    const int tid = threadIdx.x;
    const float th = g_th[row], An = g_An[row], Bn = g_Bn[row];
    const float* e2b = g_e2  + bh*Sv;
    const float* epb = g_E2p + bh*Sv;
    const float* enb = g_E2n + bh*Sv;
    float* dst = attn_out + (size_t)row * Sv;
    #pragma unroll
    for (int t = 0; t < 2; t++) {
        int j = (tid + t*256) * 4;
        float4 e2v = *(const float4*)(e2b + j);
        float4 epv = *(const float4*)(epb + j);
        float4 env = *(const float4*)(enb + j);
        float4 p;
        p.x = (e2v.x > th) ? An*epv.x : Bn*env.x;
        p.y = (e2v.y > th) ? An*epv.y : Bn*env.y;
        p.z = (e2v.z > th) ? An*epv.z : Bn*env.z;
        p.w = (e2v.w > th) ? An*epv.w : Bn*env.w;
        *(float4*)(dst + j) = p;
    }
}

// ---------------------------------------------------------------
// K3c: ctx gather: ctx_i = An*SUF[lo] + Bn*PRE[lo] -> bf16 hi/lo.
// Warp per row.
// ---------------------------------------------------------------
__global__ __launch_bounds__(256) void k_gather() {
    const int row = blockIdx.x * 8 + (threadIdx.x >> 5);
    const int lane = threadIdx.x & 31;
    const int bh = row >> 11, i = row & (Sv-1);
    const int b = bh >> 2, hh = bh & 3;
    const int lo = g_lo[row];
    const float An = g_An[row], Bn = g_Bn[row];
    const float* sufr = g_suf + ((size_t)bh*2049 + lo)*Dv + lane*4;
    const float* prer = g_pre + ((size_t)bh*2049 + lo)*Dv + lane*4;
    float4 sv = *(const float4*)sufr;
    float4 pv = *(const float4*)prer;
    float x = An*sv.x + Bn*pv.x;
    float y = An*sv.y + Bn*pv.y;
    float z = An*sv.z + Bn*pv.z;
    float ww = An*sv.w + Bn*pv.w;
    size_t o = ((size_t)(b*Sv + i))*HDv + hh*Dv + lane*4;
    *(uint2*)(g_ctxb_hi + o) = make_uint2(pack_hi2(x,y), pack_hi2(z,ww));
    *(uint2*)(g_ctxb_lo + o) = make_uint2(pack_lo2(x,y), pack_lo2(z,ww));
}

// ---------------------------------------------------------------
// K4: out = relu(ctx @ out_w^T + out_b) via bf16 3-split mma.sync.
// ---------------------------------------------------------------
#define G2_LDK 72
#define G2_AT (64*G2_LDK*2)
#define G2_BT (128*G2_LDK*2)
#define G2_BUF (2*G2_AT + 2*G2_BT)
#define G2_AH(q) ((uint32_t)((q)*G2_BUF))
#define G2_AL(q) ((uint32_t)((q)*G2_BUF + G2_AT))
#define G2_BH(q) ((uint32_t)((q)*G2_BUF + 2*G2_AT))
#define G2_BL(q) ((uint32_t)((q)*G2_BUF + 2*G2_AT + G2_BT))
#define G2_SMEM (2*G2_BUF)

__device__ __forceinline__ void g2_fill(int m0, int ch, uint32_t sb, int q, int tid) {
    const int k0 = ch * 64;
    #pragma unroll
    for (int t = 0; t < 4; t++) {
        int idx = tid + t*256;
        int p  = idx >> 9;
        int r  = (idx >> 3) & 63;
        int c8 = (idx & 7) * 8;
        const __nv_bfloat16* src = (p ? g_ctxb_lo : g_ctxb_hi)
            + (size_t)(m0 + r)*HDv + k0 + c8;
        CP16(sb + (p ? G2_AL(q) : G2_AH(q)) + (uint32_t)(r*G2_LDK + c8)*2, src);
    }
    #pragma unroll
    for (int t = 0; t < 8; t++) {
        int idx = tid + t*256;
        int p  = idx >> 10;
        int r  = (idx >> 3) & 127;
        int c8 = (idx & 7) * 8;
        const __nv_bfloat16* src = (p ? g_wb_lo : g_wb_hi)
            + (size_t)r*HDv + k0 + c8;
        CP16(sb + (p ? G2_BL(q) : G2_BH(q)) + (uint32_t)(r*G2_LDK + c8)*2, src);
    }
}

__global__ __launch_bounds__(256, 1) void k_gemm2t(const float* __restrict__ bias,
                                                   float* __restrict__ out) {
    const int m0 = blockIdx.x * 64;
    const int tid = threadIdx.x;
    const int w = tid >> 5, lane = tid & 31;
    const uint32_t sb = smem_u32(dynsmem);

    g2_fill(m0, 0, sb, 0, tid);
    CP_COMMIT();

    const int wm = w >> 2, wn = w & 3;
    const uint32_t arow = (uint32_t)((wm*32 + (lane & 15))*G2_LDK + (lane >> 4)*8) * 2;
    const uint32_t brow = (uint32_t)(((lane & 7) + ((lane >> 4) << 3))*G2_LDK
                                     + (((lane >> 3) & 1)*8)) * 2;
    float c[2][4][4] = {};

    #pragma unroll 1
    for (int ch = 0; ch < 8; ch++) {
        const int q = ch & 1;
        if (ch < 7) { g2_fill(m0, ch+1, sb, q^1, tid); CP_COMMIT(); CP_WAIT1(); }
        else        { CP_WAIT0(); }
        __syncthreads();

        #pragma unroll
        for (int ks = 0; ks < 4; ks++) {
            uint32_t bhf[2][4], blf[2][4];
            #pragma unroll
            for (int np = 0; np < 2; np++) {
                uint32_t bt = (uint32_t)((wn*32 + np*16)*G2_LDK)*2 + (uint32_t)(ks*16)*2;
                LDMX4(bhf[np][0],bhf[np][1],bhf[np][2],bhf[np][3], sb + G2_BH(q) + brow + bt);
                LDMX4(blf[np][0],blf[np][1],blf[np][2],blf[np][3], sb + G2_BL(q) + brow + bt);
            }
            #pragma unroll
            for (int mt = 0; mt < 2; mt++) {
                uint32_t at = (uint32_t)(mt*16*G2_LDK)*2 + (uint32_t)(ks*16)*2;
                uint32_t ah0,ah1,ah2,ah3, al0,al1,al2,al3;
                LDMX4(ah0,ah1,ah2,ah3, sb + G2_AH(q) + arow + at);
                LDMX4(al0,al1,al2,al3, sb + G2_AL(q) + arow + at);
                #pragma unroll
                for (int np = 0; np < 2; np++) {
                    MMA16816(c[mt][np*2],   ah0,ah1,ah2,ah3, bhf[np][0],bhf[np][1]);
                    MMA16816(c[mt][np*2],   al0,al1,al2,al3, bhf[np][0],bhf[np][1]);
                    MMA16816(c[mt][np*2],   ah0,ah1,ah2,ah3, blf[np][0],blf[np][1]);
                    MMA16816(c[mt][np*2+1], ah0,ah1,ah2,ah3, bhf[np][2],bhf[np][3]);
                    MMA16816(c[mt][np*2+1], al0,al1,al2,al3, bhf[np][2],bhf[np][3]);
                    MMA16816(c[mt][np*2+1], ah0,ah1,ah2,ah3, blf[np][2],blf[np][3]);
                }
            }
        }
        __syncthreads();
    }

    {
        const int g = lane >> 2, tg = lane & 3;
        #pragma unroll
        for (int mt = 0; mt < 2; mt++) {
            int r0 = m0 + wm*32 + mt*16 + g;
            #pragma unroll
            for (int nt = 0; nt < 4; nt++) {
                int n = wn*32 + nt*8 + tg*2;
                float b0 = bias[n], b1 = bias[n+1];
                float v0 = c[mt][nt][0] + b0, v1 = c[mt][nt][1] + b1;
                float v2 = c[mt][nt][2] + b0, v3 = c[mt][nt][3] + b1;
                *(float2*)(out + (size_t)r0*OUTv + n) =
                    make_float2(v0 > 0.f ? v0 : 0.f, v1 > 0.f ? v1 : 0.f);
                *(float2*)(out + (size_t)(r0+8)*OUTv + n) =
                    make_float2(v2 > 0.f ? v2 : 0.f, v3 > 0.f ? v3 : 0.f);
            }
        }
    }
}

// ---------------------------------------------------------------
extern "C" void kernel_launch(void* const* d_in, const int* in_sizes, int n_in,
                              void* d_out, int out_size) {
    const float* h     = (const float*)d_in[0];
    const void*  mask  = d_in[1];
    const float* W_w   = (const float*)d_in[2];
    const float* W_b   = (const float*)d_in[3];
    const float* a_w   = (const float*)d_in[4];
    const float* a_b   = (const float*)d_in[5];
    const float* out_w = (const float*)d_in[6];
    const float* out_b = (const float*)d_in[7];

    float* out  = (float*)d_out;
    float* attn = out + (size_t)Bv*Sv*OUTv;

    static int attr_set = 0;
    if (!attr_set) {
        cudaFuncSetAttribute(k_gemm1t, cudaFuncAttributeMaxDynamicSharedMemorySize, G1_SMEM);
        cudaFuncSetAttribute(k_prep,   cudaFuncAttributeMaxDynamicSharedMemorySize, PREP_SMEM);
        cudaFuncSetAttribute(k_gemm2t, cudaFuncAttributeMaxDynamicSharedMemorySize, G2_SMEM);
        attr_set = 1;
    }

    k_mask  <<<1, 256>>>(mask);
    k_wcvt  <<<64, 256>>>(out_w);
    k_gemm1t<<<dim3(64, 4), 256, G1_SMEM>>>(h, W_w, W_b, a_w);
    k_prep  <<<BHv, 1024, PREP_SMEM>>>(a_b);
    k_scan  <<<32, 128>>>();
    k_attnw <<<NSv, 256>>>(attn);
    k_gather<<<NSv/8, 256>>>();
    k_gemm2t<<<128, 256, G2_SMEM>>>(out_b, out);
}

// round 8
// speedup vs baseline: 3.8945x; 1.2946x over previous
#include <cuda_runtime.h>
#include <cuda_bf16.h>
#include <math.h>
#include <stdint.h>

#define Bv 4
#define Sv 2048
#define Fv 128
#define Hv 4
#define Dv 128
#define HDv 512
#define OUTv 128
#define BHv 16
#define NSv (BHv*Sv)
#define NEG 0.01f

// ---- device scratch ----
__device__ float g_hp[NSv*Dv];          // fp32 [bh][s][d]
__device__ float g_e1[NSv];
__device__ float g_e2[NSv];
__device__ float g_An[NSv];
__device__ float g_Bn[NSv];
__device__ float g_th[NSv];
__device__ float g_E2p[NSv];
__device__ float g_E2n[NSv];
__device__ int   g_lo[NSv];
__device__ int   g_perm[NSv];
__device__ float g_sEp[NSv];
__device__ float g_sEn[NSv];
__device__ int   g_masked[Bv*Sv];
__device__ float g_pre[BHv*2049*Dv];    // prefix of En*hp over sorted order
__device__ float g_suf[BHv*2049*Dv];    // suffix of Ep*hp over sorted order
__device__ float g_segsum[BHv*2*8*Dv];  // [bh][dir][seg][d]
// ctx in bf16 hi/lo, k-major [b][s][h*D+d]
__device__ __nv_bfloat16 g_ctxb_hi[Bv*Sv*HDv];
__device__ __nv_bfloat16 g_ctxb_lo[Bv*Sv*HDv];
// out_w bf16 hi/lo [n][k]
__device__ __nv_bfloat16 g_wb_hi[OUTv*HDv];
__device__ __nv_bfloat16 g_wb_lo[OUTv*HDv];

__device__ __forceinline__ uint32_t smem_u32(const void* p) {
    uint32_t a;
    asm("{ .reg .u64 t; cvta.to.shared.u64 t, %1; cvt.u32.u64 %0, t; }" : "=r"(a) : "l"(p));
    return a;
}
#define LDMX4(r0,r1,r2,r3,addr) \
    asm volatile("ldmatrix.sync.aligned.m8n8.x4.shared.b16 {%0,%1,%2,%3}, [%4];" \
        : "=r"(r0),"=r"(r1),"=r"(r2),"=r"(r3) : "r"(addr))
#define MMA16816(c,a0,a1,a2,a3,b0,b1) \
    asm volatile("mma.sync.aligned.m16n8k16.row.col.f32.bf16.bf16.f32 " \
        "{%0,%1,%2,%3}, {%4,%5,%6,%7}, {%8,%9}, {%0,%1,%2,%3};" \
        : "+f"((c)[0]),"+f"((c)[1]),"+f"((c)[2]),"+f"((c)[3]) \
        : "r"(a0),"r"(a1),"r"(a2),"r"(a3), "r"(b0),"r"(b1))
#define CP16(dst, src) \
    asm volatile("cp.async.cg.shared.global [%0], [%1], 16;" :: "r"(dst), "l"(src) : "memory")
#define CP_COMMIT() asm volatile("cp.async.commit_group;" ::: "memory")
#define CP_WAIT1()  asm volatile("cp.async.wait_group 1;" ::: "memory")
#define CP_WAIT0()  asm volatile("cp.async.wait_group 0;" ::: "memory")

__device__ __forceinline__ uint32_t pack_hi2(float a, float b) {
    __nv_bfloat16 ha = __float2bfloat16_rn(a), hb = __float2bfloat16_rn(b);
    return ((uint32_t)__bfloat16_as_ushort(hb) << 16) | __bfloat16_as_ushort(ha);
}
__device__ __forceinline__ uint32_t pack_lo2(float a, float b) {
    __nv_bfloat16 ha = __float2bfloat16_rn(a), hb = __float2bfloat16_rn(b);
    float ra = a - __bfloat162float(ha), rb = b - __bfloat162float(hb);
    __nv_bfloat16 la = __float2bfloat16_rn(ra), lb = __float2bfloat16_rn(rb);
    return ((uint32_t)__bfloat16_as_ushort(lb) << 16) | __bfloat16_as_ushort(la);
}

extern __shared__ __align__(128) unsigned char dynsmem[];

// ---------------------------------------------------------------
// K0: decode mask buffer (u8 vs i32 by byte sum)
// ---------------------------------------------------------------
__global__ void k_mask(const void* mraw) {
    __shared__ int ssum[256];
    __shared__ int fmt;
    const unsigned char* mb = (const unsigned char*)mraw;
    int tid = threadIdx.x;
    int s = 0;
    for (int i = tid; i < Bv*Sv; i += 256) s += mb[i];
    ssum[tid] = s;
    __syncthreads();
    for (int st = 128; st > 0; st >>= 1) {
        if (tid < st) ssum[tid] += ssum[tid + st];
        __syncthreads();
    }
    if (tid == 0) fmt = (ssum[0] > (Bv*Sv*5/16)) ? 1 : 0;
    __syncthreads();
    if (fmt) {
        for (int i = tid; i < Bv*Sv; i += 256) g_masked[i] = (mb[i] != 0);
    } else {
        const int* mi = (const int*)mraw;
        for (int i = tid; i < Bv*Sv; i += 256) g_masked[i] = (mi[i] != 0);
    }
}

// ---------------------------------------------------------------
// K0b: convert out_w to bf16 hi/lo
// ---------------------------------------------------------------
__global__ void k_wcvt(const float* __restrict__ W) {
    int i = blockIdx.x * 256 + threadIdx.x;
    float4 v = *(const float4*)(W + (size_t)i*4);
    *(uint2*)(g_wb_hi + (size_t)i*4) = make_uint2(pack_hi2(v.x,v.y), pack_hi2(v.z,v.w));
    *(uint2*)(g_wb_lo + (size_t)i*4) = make_uint2(pack_lo2(v.x,v.y), pack_lo2(v.z,v.w));
}

// ---------------------------------------------------------------
// K1: hp = h @ W_w^T + W_b via bf16 3-split mma.sync, fused e1/e2.
// ---------------------------------------------------------------
#define G1_LDK 136
#define G1_T  (128*G1_LDK*2)
#define G1_AH 0u
#define G1_AL ((uint32_t)G1_T)
#define G1_BH ((uint32_t)(2*G1_T))
#define G1_BL ((uint32_t)(3*G1_T))
#define G1_RED ((uint32_t)(4*G1_T))
#define G1_SA  ((uint32_t)(4*G1_T + 4096))
#define G1_SMEM (4*G1_T + 4096 + 1024)

__global__ __launch_bounds__(256, 1) void k_gemm1t(const float* __restrict__ A,
                                                   const float* __restrict__ W,
                                                   const float* __restrict__ bias,
                                                   const float* __restrict__ aw) {
    const int m0 = blockIdx.x * 128;
    const int n0 = blockIdx.y * 128;
    const int tid = threadIdx.x;
    const int w = tid >> 5, lane = tid & 31;
    const uint32_t sb = smem_u32(dynsmem);

    if (tid < 256) ((float*)(dynsmem + G1_SA))[tid] = aw[tid];

    #pragma unroll
    for (int t = 0; t < 16; t++) {
        int idx = tid + t*256;
        int r = idx >> 5, c4 = (idx & 31) << 2;
        float4 v = *(const float4*)(A + (size_t)(m0+r)*Fv + c4);
        uint32_t boff = (uint32_t)(r*G1_LDK + c4) * 2;
        *(uint2*)(dynsmem + G1_AH + boff) = make_uint2(pack_hi2(v.x,v.y), pack_hi2(v.z,v.w));
        *(uint2*)(dynsmem + G1_AL + boff) = make_uint2(pack_lo2(v.x,v.y), pack_lo2(v.z,v.w));
    }
    #pragma unroll
    for (int t = 0; t < 16; t++) {
        int idx = tid + t*256;
        int r = idx >> 5, c4 = (idx & 31) << 2;
        float4 v = *(const float4*)(W + (size_t)(n0+r)*Fv + c4);
        uint32_t boff = (uint32_t)(r*G1_LDK + c4) * 2;
        *(uint2*)(dynsmem + G1_BH + boff) = make_uint2(pack_hi2(v.x,v.y), pack_hi2(v.z,v.w));
        *(uint2*)(dynsmem + G1_BL + boff) = make_uint2(pack_lo2(v.x,v.y), pack_lo2(v.z,v.w));
    }
    __syncthreads();

    const int wm = w >> 2, wn = w & 3;
    const uint32_t arow = (uint32_t)((wm*64 + (lane & 15))*G1_LDK + (lane >> 4)*8) * 2;
    const uint32_t brow = (uint32_t)(((lane & 7) + ((lane >> 4) << 3))*G1_LDK
                                     + (((lane >> 3) & 1)*8)) * 2;
    float c[4][4][4] = {};

    #pragma unroll
    for (int ks = 0; ks < 8; ks++) {
        uint32_t bhf[2][4], blf[2][4];
        #pragma unroll
        for (int np = 0; np < 2; np++) {
            uint32_t bt = (uint32_t)((wn*32 + np*16)*G1_LDK)*2 + (uint32_t)(ks*16)*2;
            LDMX4(bhf[np][0],bhf[np][1],bhf[np][2],bhf[np][3], sb + G1_BH + brow + bt);
            LDMX4(blf[np][0],blf[np][1],blf[np][2],blf[np][3], sb + G1_BL + brow + bt);
        }
        #pragma unroll
        for (int mt = 0; mt < 4; mt++) {
            uint32_t at = (uint32_t)(mt*16*G1_LDK)*2 + (uint32_t)(ks*16)*2;
            uint32_t ah0,ah1,ah2,ah3, al0,al1,al2,al3;
            LDMX4(ah0,ah1,ah2,ah3, sb + G1_AH + arow + at);
            LDMX4(al0,al1,al2,al3, sb + G1_AL + arow + at);
            #pragma unroll
            for (int np = 0; np < 2; np++) {
                MMA16816(c[mt][np*2],   ah0,ah1,ah2,ah3, bhf[np][0],bhf[np][1]);
                MMA16816(c[mt][np*2],   al0,al1,al2,al3, bhf[np][0],bhf[np][1]);
                MMA16816(c[mt][np*2],   ah0,ah1,ah2,ah3, blf[np][0],blf[np][1]);
                MMA16816(c[mt][np*2+1], ah0,ah1,ah2,ah3, bhf[np][2],bhf[np][3]);
                MMA16816(c[mt][np*2+1], al0,al1,al2,al3, bhf[np][2],bhf[np][3]);
                MMA16816(c[mt][np*2+1], ah0,ah1,ah2,ah3, blf[np][2],blf[np][3]);
            }
        }
    }

    const int bb = m0 >> 11, s0 = m0 & (Sv-1), hh = n0 >> 7;
    const int bh = bb*Hv + hh;
    const int g = lane >> 2, tg = lane & 3;
    float* red = (float*)(dynsmem + G1_RED);
    const float* sa1 = (const float*)(dynsmem + G1_SA);
    const float* sa2 = sa1 + 128;

    float pe1[4][2] = {}, pe2[4][2] = {};
    #pragma unroll
    for (int mt = 0; mt < 4; mt++) {
        #pragma unroll
        for (int nt = 0; nt < 4; nt++) {
            int d = wn*32 + nt*8 + tg*2;
            float b0 = bias[n0 + d], b1 = bias[n0 + d + 1];
            float a10 = sa1[d], a11 = sa1[d+1];
            float a20 = sa2[d], a21 = sa2[d+1];
            #pragma unroll
            for (int half = 0; half < 2; half++) {
                int r = wm*64 + mt*16 + half*8 + g;
                float v0 = c[mt][nt][half*2]   + b0;
                float v1 = c[mt][nt][half*2+1] + b1;
                *(float2*)(g_hp + ((size_t)bh*Sv + s0 + r)*Dv + d) = make_float2(v0, v1);
                pe1[mt][half] += v0*a10 + v1*a11;
                pe2[mt][half] += v0*a20 + v1*a21;
            }
        }
    }
    #pragma unroll
    for (int mt = 0; mt < 4; mt++) {
        #pragma unroll
        for (int half = 0; half < 2; half++) {
            float e1 = pe1[mt][half], e2 = pe2[mt][half];
            e1 += __shfl_xor_sync(0xffffffffu, e1, 1);
            e1 += __shfl_xor_sync(0xffffffffu, e1, 2);
            e2 += __shfl_xor_sync(0xffffffffu, e2, 1);
            e2 += __shfl_xor_sync(0xffffffffu, e2, 2);
            if (tg == 0) {
                int r = wm*64 + mt*16 + half*8 + g;
                red[(r*4 + wn)*2 + 0] = e1;
                red[(r*4 + wn)*2 + 1] = e2;
            }
        }
    }
    __syncthreads();
    if (tid < 128) {
        int r = tid;
        float e1 = red[(r*4+0)*2] + red[(r*4+1)*2] + red[(r*4+2)*2] + red[(r*4+3)*2];
        float e2 = red[(r*4+0)*2+1] + red[(r*4+1)*2+1] + red[(r*4+2)*2+1] + red[(r*4+3)*2+1];
        int s = s0 + r;
        int row = bh*Sv + s;
        g_e1[row] = e1;
        g_e2[row] = e2;
        int msk = g_masked[bb*Sv + s];
        g_E2p[row] = msk ? 0.f : expf(e2);
        g_E2n[row] = msk ? 0.f : expf(NEG*e2);
    }
}

// ---------------------------------------------------------------
// K2: per (b,h) softmax prep (uint64 payload sort + scans + bsearch)
// ---------------------------------------------------------------
#define P_SKEY 0u
#define P_KEYF 16384u
#define P_V1   24576u
#define P_V2   32768u
#define P_PREN 40960u
#define P_SUFP 49408u
#define P_CH1  57856u
#define P_CH2  58112u
#define PREP_SMEM 58880

__device__ __forceinline__ uint32_t f2sort(float f) {
    uint32_t u = __float_as_uint(f);
    return (u & 0x80000000u) ? ~u : (u | 0x80000000u);
}
__device__ __forceinline__ float sort2f(uint32_t s) {
    uint32_t u = (s & 0x80000000u) ? (s ^ 0x80000000u) : ~s;
    return __uint_as_float(u);
}

__global__ __launch_bounds__(1024) void k_prep(const float* __restrict__ ab_p) {
    unsigned long long* skey = (unsigned long long*)(dynsmem + P_SKEY);
    float* keyf = (float*)(dynsmem + P_KEYF);
    float* v1   = (float*)(dynsmem + P_V1);
    float* v2   = (float*)(dynsmem + P_V2);
    float* pren = (float*)(dynsmem + P_PREN);
    float* sufp = (float*)(dynsmem + P_SUFP);
    float* ch1  = (float*)(dynsmem + P_CH1);
    float* ch2  = (float*)(dynsmem + P_CH2);

    const int bh = blockIdx.x;
    const int b  = bh >> 2;
    const int tid = threadIdx.x;
    const float ab = ab_p[0];

    for (int j = tid; j < Sv; j += 1024) {
        float e2 = g_e2[bh*Sv + j];
        float kf = g_masked[b*Sv + j] ? -1e30f : e2;
        skey[j] = ((unsigned long long)f2sort(kf) << 32) | (unsigned)j;
    }
    __syncthreads();

    for (int k = 2; k <= Sv; k <<= 1) {
        for (int j = k >> 1; j > 0; j >>= 1) {
            #pragma unroll 2
            for (int i = tid; i < Sv; i += 1024) {
                int ixj = i ^ j;
                if (ixj > i) {
                    bool up = ((i & k) == 0);
                    unsigned long long ki = skey[i], kj = skey[ixj];
                    if ((ki > kj) == up) { skey[i] = kj; skey[ixj] = ki; }
                }
            }
            __syncthreads();
        }
    }

    for (int n = tid; n < Sv; n += 1024) {
        unsigned long long kv = skey[n];
        float kf = sort2f((uint32_t)(kv >> 32));
        int jj = (int)(kv & 0xffffffffu);
        float ep = expf(kf), en = expf(NEG*kf);
        keyf[n] = kf; v1[n] = ep; v2[n] = en;
        g_perm[bh*Sv + n] = jj;
        g_sEp[bh*Sv + n] = ep;
        g_sEn[bh*Sv + n] = en;
    }
    __syncthreads();

    const float M2 = keyf[Sv-1];

    if (tid < 64) {
        int base = tid * 32;
        float s1 = 0.f, s2 = 0.f;
        for (int t = 0; t < 32; t++) { s1 += v1[base+t]; s2 += v2[base+t]; }
        ch1[tid] = s1; ch2[tid] = s2;
    }
    __syncthreads();
    if (tid == 0) {
        float r = 0.f;
        for (int c = 0; c < 64; c++) { float t = ch2[c]; ch2[c] = r; r += t; }
        pren[Sv] = r;
        r = 0.f;
        for (int c = 63; c >= 0; c--) { float t = ch1[c]; ch1[c] = r; r += t; }
    }
    __syncthreads();
    if (tid < 64) {
        int base = tid * 32;
        float run = ch2[tid];
        for (int t = 0; t < 32; t++) { pren[base+t] = run; run += v2[base+t]; }
        float runs = ch1[tid];
        for (int t = 31; t >= 0; t--) { runs += v1[base+t]; sufp[base+t] = runs; }
    }
    if (tid == 0) sufp[Sv] = 0.f;
    __syncthreads();

    for (int i = tid; i < Sv; i += 1024) {
        float e1 = g_e1[bh*Sv + i];
        float eb = e1 + ab;
        float pre = eb + M2;
        float m = (pre > 0.f) ? pre : NEG*pre;
        float th = -eb;
        float A  = expf(eb - m);
        float Bc = expf(NEG*eb - m);
        int lo = 0, hi = Sv;
        while (lo < hi) {
            int mid = (lo + hi) >> 1;
            if (keyf[mid] <= th) lo = mid + 1; else hi = mid;
        }
        float rowsum = A*sufp[lo] + Bc*pren[lo];
        float inv = 1.0f / rowsum;
        g_An[bh*Sv + i] = A * inv;
        g_Bn[bh*Sv + i] = Bc * inv;
        g_th[bh*Sv + i] = th;
        g_lo[bh*Sv + i] = lo;
    }
}

// ---------------------------------------------------------------
// K3a-1: segment sums. Block = (bh, dir, seg of 256 rows); 128 thr = d.
// Pure reduction, 4 independent accumulators -> latency-hidden.
// ---------------------------------------------------------------
__global__ __launch_bounds__(128) void k_scan1() {
    __shared__ float wv[256];
    __shared__ int pm[256];
    const int blk = blockIdx.x;
    const int seg = blk & 7;
    const int dir = (blk >> 3) & 1;
    const int bh  = blk >> 4;
    const int d = threadIdx.x;
    const int n0 = seg * 256;
    const float* src = dir ? (g_sEp + bh*Sv) : (g_sEn + bh*Sv);
    for (int t = d; t < 256; t += 128) {
        wv[t] = src[n0 + t];
        pm[t] = g_perm[bh*Sv + n0 + t];
    }
    __syncthreads();
    const float* hp = g_hp + (size_t)bh*Sv*Dv;
    float a0=0.f, a1=0.f, a2=0.f, a3=0.f;
    for (int t = 0; t < 256; t += 4) {
        a0 += wv[t+0]*hp[(size_t)pm[t+0]*Dv + d];
        a1 += wv[t+1]*hp[(size_t)pm[t+1]*Dv + d];
        a2 += wv[t+2]*hp[(size_t)pm[t+2]*Dv + d];
        a3 += wv[t+3]*hp[(size_t)pm[t+3]*Dv + d];
    }
    g_segsum[(size_t)blk*Dv + d] = (a0 + a1) + (a2 + a3);
}

// ---------------------------------------------------------------
// K3a-2: local scan with segment offsets -> PRE/SUF tables.
// ---------------------------------------------------------------
__global__ __launch_bounds__(128) void k_scan2() {
    __shared__ float wv[256];
    __shared__ int pm[256];
    const int blk = blockIdx.x;
    const int seg = blk & 7;
    const int dir = (blk >> 3) & 1;
    const int bh  = blk >> 4;
    const int d = threadIdx.x;
    const int n0 = seg * 256;
    const float* src = dir ? (g_sEp + bh*Sv) : (g_sEn + bh*Sv);
    for (int t = d; t < 256; t += 128) {
        wv[t] = src[n0 + t];
        pm[t] = g_perm[bh*Sv + n0 + t];
    }
    __syncthreads();
    const float* hp = g_hp + (size_t)bh*Sv*Dv;
    const int base = (bh*2 + dir) * 8;
    float acc = 0.f;
    if (dir == 0) {
        for (int ss = 0; ss < seg; ss++) acc += g_segsum[(size_t)(base+ss)*Dv + d];
        float* pre = g_pre + (size_t)bh*2049*Dv;
        for (int t = 0; t < 256; t += 8) {
            float vals[8];
            #pragma unroll
            for (int k = 0; k < 8; k++) vals[k] = hp[(size_t)pm[t+k]*Dv + d];
            #pragma unroll
            for (int k = 0; k < 8; k++) {
                pre[(size_t)(n0+t+k)*Dv + d] = acc;
                acc += wv[t+k]*vals[k];
            }
        }
        if (seg == 7) pre[(size_t)Sv*Dv + d] = acc;
    } else {
        for (int ss = seg+1; ss < 8; ss++) acc += g_segsum[(size_t)(base+ss)*Dv + d];
        float* suf = g_suf + (size_t)bh*2049*Dv;
        if (seg == 7) suf[(size_t)Sv*Dv + d] = 0.f;
        for (int t = 248; t >= 0; t -= 8) {
            float vals[8];
            #pragma unroll
            for (int k = 7; k >= 0; k--) vals[k] = hp[(size_t)pm[t+k]*Dv + d];
            #pragma unroll
            for (int k = 7; k >= 0; k--) {
                acc += wv[t+k]*vals[k];
                suf[(size_t)(n0+t+k)*Dv + d] = acc;
            }
        }
    }
}

// ---------------------------------------------------------------
// K3b: attn write: pure bandwidth (runs on side stream, overlapped)
// ---------------------------------------------------------------
__global__ __launch_bounds__(256) void k_attnw(float* __restrict__ attn_out) {
    const int row = blockIdx.x;
    const int bh = row >> 11;
    const int tid = threadIdx.x;
    const float th = g_th[row], An = g_An[row], Bn = g_Bn[row];
    const float* e2b = g_e2  + bh*Sv;
    const float* epb = g_E2p + bh*Sv;
    const float* enb = g_E2n + bh*Sv;
    float* dst = attn_out + (size_t)row * Sv;
    #pragma unroll
    for (int t = 0; t < 2; t++) {
        int j = (tid + t*256) * 4;
        float4 e2v = *(const float4*)(e2b + j);
        float4 epv = *(const float4*)(epb + j);
        float4 env = *(const float4*)(enb + j);
        float4 p;
        p.x = (e2v.x > th) ? An*epv.x : Bn*env.x;
        p.y = (e2v.y > th) ? An*epv.y : Bn*env.y;
        p.z = (e2v.z > th) ? An*epv.z : Bn*env.z;
        p.w = (e2v.w > th) ? An*epv.w : Bn*env.w;
        *(float4*)(dst + j) = p;
    }
}

// ---------------------------------------------------------------
// K3c: ctx gather: ctx_i = An*SUF[lo] + Bn*PRE[lo] -> bf16 hi/lo.
// ---------------------------------------------------------------
__global__ __launch_bounds__(256) void k_gather() {
    const int row = blockIdx.x * 8 + (threadIdx.x >> 5);
    const int lane = threadIdx.x & 31;
    const int bh = row >> 11, i = row & (Sv-1);
    const int b = bh >> 2, hh = bh & 3;
    const int lo = g_lo[row];
    const float An = g_An[row], Bn = g_Bn[row];
    float4 sv = *(const float4*)(g_suf + ((size_t)bh*2049 + lo)*Dv + lane*4);
    float4 pv = *(const float4*)(g_pre + ((size_t)bh*2049 + lo)*Dv + lane*4);
    float x = An*sv.x + Bn*pv.x;
    float y = An*sv.y + Bn*pv.y;
    float z = An*sv.z + Bn*pv.z;
    float ww = An*sv.w + Bn*pv.w;
    size_t o = ((size_t)(b*Sv + i))*HDv + hh*Dv + lane*4;
    *(uint2*)(g_ctxb_hi + o) = make_uint2(pack_hi2(x,y), pack_hi2(z,ww));
    *(uint2*)(g_ctxb_lo + o) = make_uint2(pack_lo2(x,y), pack_lo2(z,ww));
}

// ---------------------------------------------------------------
// K4: out = relu(ctx @ out_w^T + out_b) via bf16 3-split mma.sync.
// ---------------------------------------------------------------
#define G2_LDK 72
#define G2_AT (64*G2_LDK*2)
#define G2_BT (128*G2_LDK*2)
#define G2_BUF (2*G2_AT + 2*G2_BT)
#define G2_AH(q) ((uint32_t)((q)*G2_BUF))
#define G2_AL(q) ((uint32_t)((q)*G2_BUF + G2_AT))
#define G2_BH(q) ((uint32_t)((q)*G2_BUF + 2*G2_AT))
#define G2_BL(q) ((uint32_t)((q)*G2_BUF + 2*G2_AT + G2_BT))
#define G2_SMEM (2*G2_BUF)

__device__ __forceinline__ void g2_fill(int m0, int ch, uint32_t sb, int q, int tid) {
    const int k0 = ch * 64;
    #pragma unroll
    for (int t = 0; t < 4; t++) {
        int idx = tid + t*256;
        int p  = idx >> 9;
        int r  = (idx >> 3) & 63;
        int c8 = (idx & 7) * 8;
        const __nv_bfloat16* src = (p ? g_ctxb_lo : g_ctxb_hi)
            + (size_t)(m0 + r)*HDv + k0 + c8;
        CP16(sb + (p ? G2_AL(q) : G2_AH(q)) + (uint32_t)(r*G2_LDK + c8)*2, src);
    }
    #pragma unroll
    for (int t = 0; t < 8; t++) {
        int idx = tid + t*256;
        int p  = idx >> 10;
        int r  = (idx >> 3) & 127;
        int c8 = (idx & 7) * 8;
        const __nv_bfloat16* src = (p ? g_wb_lo : g_wb_hi)
            + (size_t)r*HDv + k0 + c8;
        CP16(sb + (p ? G2_BL(q) : G2_BH(q)) + (uint32_t)(r*G2_LDK + c8)*2, src);
    }
}

__global__ __launch_bounds__(256, 1) void k_gemm2t(const float* __restrict__ bias,
                                                   float* __restrict__ out) {
    const int m0 = blockIdx.x * 64;
    const int tid = threadIdx.x;
    const int w = tid >> 5, lane = tid & 31;
    const uint32_t sb = smem_u32(dynsmem);

    g2_fill(m0, 0, sb, 0, tid);
    CP_COMMIT();

    const int wm = w >> 2, wn = w & 3;
    const uint32_t arow = (uint32_t)((wm*32 + (lane & 15))*G2_LDK + (lane >> 4)*8) * 2;
    const uint32_t brow = (uint32_t)(((lane & 7) + ((lane >> 4) << 3))*G2_LDK
                                     + (((lane >> 3) & 1)*8)) * 2;
    float c[2][4][4] = {};

    #pragma unroll 1
    for (int ch = 0; ch < 8; ch++) {
        const int q = ch & 1;
        if (ch < 7) { g2_fill(m0, ch+1, sb, q^1, tid); CP_COMMIT(); CP_WAIT1(); }
        else        { CP_WAIT0(); }
        __syncthreads();

        #pragma unroll
        for (int ks = 0; ks < 4; ks++) {
            uint32_t bhf[2][4], blf[2][4];
            #pragma unroll
            for (int np = 0; np < 2; np++) {
                uint32_t bt = (uint32_t)((wn*32 + np*16)*G2_LDK)*2 + (uint32_t)(ks*16)*2;
                LDMX4(bhf[np][0],bhf[np][1],bhf[np][2],bhf[np][3], sb + G2_BH(q) + brow + bt);
                LDMX4(blf[np][0],blf[np][1],blf[np][2],blf[np][3], sb + G2_BL(q) + brow + bt);
            }
            #pragma unroll
            for (int mt = 0; mt < 2; mt++) {
                uint32_t at = (uint32_t)(mt*16*G2_LDK)*2 + (uint32_t)(ks*16)*2;
                uint32_t ah0,ah1,ah2,ah3, al0,al1,al2,al3;
                LDMX4(ah0,ah1,ah2,ah3, sb + G2_AH(q) + arow + at);
                LDMX4(al0,al1,al2,al3, sb + G2_AL(q) + arow + at);
                #pragma unroll
                for (int np = 0; np < 2; np++) {
                    MMA16816(c[mt][np*2],   ah0,ah1,ah2,ah3, bhf[np][0],bhf[np][1]);
                    MMA16816(c[mt][np*2],   al0,al1,al2,al3, bhf[np][0],bhf[np][1]);
                    MMA16816(c[mt][np*2],   ah0,ah1,ah2,ah3, blf[np][0],blf[np][1]);
                    MMA16816(c[mt][np*2+1], ah0,ah1,ah2,ah3, bhf[np][2],bhf[np][3]);
                    MMA16816(c[mt][np*2+1], al0,al1,al2,al3, bhf[np][2],bhf[np][3]);
                    MMA16816(c[mt][np*2+1], ah0,ah1,ah2,ah3, blf[np][2],blf[np][3]);
                }
            }
        }
        __syncthreads();
    }

    {
        const int g = lane >> 2, tg = lane & 3;
        #pragma unroll
        for (int mt = 0; mt < 2; mt++) {
            int r0 = m0 + wm*32 + mt*16 + g;
            #pragma unroll
            for (int nt = 0; nt < 4; nt++) {
                int n = wn*32 + nt*8 + tg*2;
                float b0 = bias[n], b1 = bias[n+1];
                float v0 = c[mt][nt][0] + b0, v1 = c[mt][nt][1] + b1;
                float v2 = c[mt][nt][2] + b0, v3 = c[mt][nt][3] + b1;
                *(float2*)(out + (size_t)r0*OUTv + n) =
                    make_float2(v0 > 0.f ? v0 : 0.f, v1 > 0.f ? v1 : 0.f);
                *(float2*)(out + (size_t)(r0+8)*OUTv + n) =
                    make_float2(v2 > 0.f ? v2 : 0.f, v3 > 0.f ? v3 : 0.f);
            }
        }
    }
}

// ---------------------------------------------------------------
extern "C" void kernel_launch(void* const* d_in, const int* in_sizes, int n_in,
                              void* d_out, int out_size) {
    const float* h     = (const float*)d_in[0];
    const void*  mask  = d_in[1];
    const float* W_w   = (const float*)d_in[2];
    const float* W_b   = (const float*)d_in[3];
    const float* a_w   = (const float*)d_in[4];
    const float* a_b   = (const float*)d_in[5];
    const float* out_w = (const float*)d_in[6];
    const float* out_b = (const float*)d_in[7];

    float* out  = (float*)d_out;
    float* attn = out + (size_t)Bv*Sv*OUTv;

    static int init_done = 0;
    static cudaStream_t s2;
    static cudaEvent_t evFork, evJoin;
    if (!init_done) {
        cudaFuncSetAttribute(k_gemm1t, cudaFuncAttributeMaxDynamicSharedMemorySize, G1_SMEM);
        cudaFuncSetAttribute(k_prep,   cudaFuncAttributeMaxDynamicSharedMemorySize, PREP_SMEM);
        cudaFuncSetAttribute(k_gemm2t, cudaFuncAttributeMaxDynamicSharedMemorySize, G2_SMEM);
        cudaStreamCreateWithFlags(&s2, cudaStreamNonBlocking);
        cudaEventCreateWithFlags(&evFork, cudaEventDisableTiming);
        cudaEventCreateWithFlags(&evJoin, cudaEventDisableTiming);
        init_done = 1;
    }

    k_mask  <<<1, 256>>>(mask);
    k_wcvt  <<<64, 256>>>(out_w);
    k_gemm1t<<<dim3(64, 4), 256, G1_SMEM>>>(h, W_w, W_b, a_w);
    k_prep  <<<BHv, 1024, PREP_SMEM>>>(a_b);

    // fork: attn write (pure BW) overlaps scan/gather/gemm2 branch
    cudaEventRecord(evFork, 0);
    cudaStreamWaitEvent(s2, evFork, 0);
    k_attnw <<<NSv, 256, 0, s2>>>(attn);

    k_scan1 <<<256, 128>>>();
    k_scan2 <<<256, 128>>>();
    k_gather<<<NSv/8, 256>>>();
    k_gemm2t<<<128, 256, G2_SMEM>>>(out_b, out);

    // join
    cudaEventRecord(evJoin, s2);
    cudaStreamWaitEvent(0, evJoin, 0);
}

// round 9
// speedup vs baseline: 4.6194x; 1.1861x over previous
#include <cuda_runtime.h>
#include <cuda_bf16.h>
#include <math.h>
#include <stdint.h>

#define Bv 4
#define Sv 2048
#define Fv 128
#define Hv 4
#define Dv 128
#define HDv 512
#define OUTv 128
#define BHv 16
#define NSv (BHv*Sv)
#define NEG 0.01f

// ---- device scratch ----
__device__ float g_hp[NSv*Dv];          // fp32 [bh][s][d]
__device__ float g_e1[NSv];
__device__ float g_e2[NSv];
__device__ float g_An[NSv];
__device__ float g_Bn[NSv];
__device__ float g_th[NSv];
__device__ float g_E2p[NSv];
__device__ float g_E2n[NSv];
__device__ int   g_lo[NSv];
__device__ int   g_perm[NSv];
__device__ float g_sEp[NSv];
__device__ float g_sEn[NSv];
__device__ int   g_masked[Bv*Sv];
__device__ float g_pre[BHv*2049*Dv];
__device__ float g_suf[BHv*2049*Dv];
__device__ float g_segsum[BHv*2*8*Dv];
__device__ __nv_bfloat16 g_ctxb_hi[Bv*Sv*HDv];
__device__ __nv_bfloat16 g_ctxb_lo[Bv*Sv*HDv];
__device__ __nv_bfloat16 g_wb_hi[OUTv*HDv];
__device__ __nv_bfloat16 g_wb_lo[OUTv*HDv];

__device__ __forceinline__ uint32_t smem_u32(const void* p) {
    uint32_t a;
    asm("{ .reg .u64 t; cvta.to.shared.u64 t, %1; cvt.u32.u64 %0, t; }" : "=r"(a) : "l"(p));
    return a;
}
#define LDMX4(r0,r1,r2,r3,addr) \
    asm volatile("ldmatrix.sync.aligned.m8n8.x4.shared.b16 {%0,%1,%2,%3}, [%4];" \
        : "=r"(r0),"=r"(r1),"=r"(r2),"=r"(r3) : "r"(addr))
#define MMA16816(c,a0,a1,a2,a3,b0,b1) \
    asm volatile("mma.sync.aligned.m16n8k16.row.col.f32.bf16.bf16.f32 " \
        "{%0,%1,%2,%3}, {%4,%5,%6,%7}, {%8,%9}, {%0,%1,%2,%3};" \
        : "+f"((c)[0]),"+f"((c)[1]),"+f"((c)[2]),"+f"((c)[3]) \
        : "r"(a0),"r"(a1),"r"(a2),"r"(a3), "r"(b0),"r"(b1))
#define CP16(dst, src) \
    asm volatile("cp.async.cg.shared.global [%0], [%1], 16;" :: "r"(dst), "l"(src) : "memory")
#define CP_COMMIT() asm volatile("cp.async.commit_group;" ::: "memory")
#define CP_WAIT1()  asm volatile("cp.async.wait_group 1;" ::: "memory")
#define CP_WAIT0()  asm volatile("cp.async.wait_group 0;" ::: "memory")

__device__ __forceinline__ uint32_t pack_hi2(float a, float b) {
    __nv_bfloat16 ha = __float2bfloat16_rn(a), hb = __float2bfloat16_rn(b);
    return ((uint32_t)__bfloat16_as_ushort(hb) << 16) | __bfloat16_as_ushort(ha);
}
__device__ __forceinline__ uint32_t pack_lo2(float a, float b) {
    __nv_bfloat16 ha = __float2bfloat16_rn(a), hb = __float2bfloat16_rn(b);
    float ra = a - __bfloat162float(ha), rb = b - __bfloat162float(hb);
    __nv_bfloat16 la = __float2bfloat16_rn(ra), lb = __float2bfloat16_rn(rb);
    return ((uint32_t)__bfloat16_as_ushort(lb) << 16) | __bfloat16_as_ushort(la);
}

extern __shared__ __align__(128) unsigned char dynsmem[];

// ---------------------------------------------------------------
// K0: decode mask buffer
// ---------------------------------------------------------------
__global__ void k_mask(const void* mraw) {
    __shared__ int ssum[256];
    __shared__ int fmt;
    const unsigned char* mb = (const unsigned char*)mraw;
    int tid = threadIdx.x;
    int s = 0;
    for (int i = tid; i < Bv*Sv; i += 256) s += mb[i];
    ssum[tid] = s;
    __syncthreads();
    for (int st = 128; st > 0; st >>= 1) {
        if (tid < st) ssum[tid] += ssum[tid + st];
        __syncthreads();
    }
    if (tid == 0) fmt = (ssum[0] > (Bv*Sv*5/16)) ? 1 : 0;
    __syncthreads();
    if (fmt) {
        for (int i = tid; i < Bv*Sv; i += 256) g_masked[i] = (mb[i] != 0);
    } else {
        const int* mi = (const int*)mraw;
        for (int i = tid; i < Bv*Sv; i += 256) g_masked[i] = (mi[i] != 0);
    }
}

// ---------------------------------------------------------------
// K0b: convert out_w to bf16 hi/lo (side stream, overlaps gemm1t)
// ---------------------------------------------------------------
__global__ void k_wcvt(const float* __restrict__ W) {
    int i = blockIdx.x * 256 + threadIdx.x;
    float4 v = *(const float4*)(W + (size_t)i*4);
    *(uint2*)(g_wb_hi + (size_t)i*4) = make_uint2(pack_hi2(v.x,v.y), pack_hi2(v.z,v.w));
    *(uint2*)(g_wb_lo + (size_t)i*4) = make_uint2(pack_lo2(v.x,v.y), pack_lo2(v.z,v.w));
}

// ---------------------------------------------------------------
// K1: hp = h @ W_w^T + W_b via bf16 3-split mma.sync, fused e1/e2.
// 512 threads (16 warps, 4x4), 1 block/SM.
// ---------------------------------------------------------------
#define G1_LDK 136
#define G1_T  (128*G1_LDK*2)
#define G1_AH 0u
#define G1_AL ((uint32_t)G1_T)
#define G1_BH ((uint32_t)(2*G1_T))
#define G1_BL ((uint32_t)(3*G1_T))
#define G1_RED ((uint32_t)(4*G1_T))
#define G1_SA  ((uint32_t)(4*G1_T + 4096))
#define G1_SMEM (4*G1_T + 4096 + 1024)

__global__ __launch_bounds__(512, 1) void k_gemm1t(const float* __restrict__ A,
                                                   const float* __restrict__ W,
                                                   const float* __restrict__ bias,
                                                   const float* __restrict__ aw) {
    const int m0 = blockIdx.x * 128;
    const int n0 = blockIdx.y * 128;
    const int tid = threadIdx.x;
    const int w = tid >> 5, lane = tid & 31;
    const uint32_t sb = smem_u32(dynsmem);

    if (tid < 256) ((float*)(dynsmem + G1_SA))[tid] = aw[tid];

    #pragma unroll
    for (int t = 0; t < 8; t++) {
        int idx = tid + t*512;
        int r = idx >> 5, c4 = (idx & 31) << 2;
        float4 v = *(const float4*)(A + (size_t)(m0+r)*Fv + c4);
        uint32_t boff = (uint32_t)(r*G1_LDK + c4) * 2;
        *(uint2*)(dynsmem + G1_AH + boff) = make_uint2(pack_hi2(v.x,v.y), pack_hi2(v.z,v.w));
        *(uint2*)(dynsmem + G1_AL + boff) = make_uint2(pack_lo2(v.x,v.y), pack_lo2(v.z,v.w));
    }
    #pragma unroll
    for (int t = 0; t < 8; t++) {
        int idx = tid + t*512;
        int r = idx >> 5, c4 = (idx & 31) << 2;
        float4 v = *(const float4*)(W + (size_t)(n0+r)*Fv + c4);
        uint32_t boff = (uint32_t)(r*G1_LDK + c4) * 2;
        *(uint2*)(dynsmem + G1_BH + boff) = make_uint2(pack_hi2(v.x,v.y), pack_hi2(v.z,v.w));
        *(uint2*)(dynsmem + G1_BL + boff) = make_uint2(pack_lo2(v.x,v.y), pack_lo2(v.z,v.w));
    }
    __syncthreads();

    const int wm = w >> 2, wn = w & 3;
    const uint32_t arow = (uint32_t)((wm*32 + (lane & 15))*G1_LDK + (lane >> 4)*8) * 2;
    const uint32_t brow = (uint32_t)(((lane & 7) + ((lane >> 4) << 3))*G1_LDK
                                     + (((lane >> 3) & 1)*8)) * 2;
    float c[2][4][4] = {};

    #pragma unroll
    for (int ks = 0; ks < 8; ks++) {
        uint32_t bhf[2][4], blf[2][4];
        #pragma unroll
        for (int np = 0; np < 2; np++) {
            uint32_t bt = (uint32_t)((wn*32 + np*16)*G1_LDK)*2 + (uint32_t)(ks*16)*2;
            LDMX4(bhf[np][0],bhf[np][1],bhf[np][2],bhf[np][3], sb + G1_BH + brow + bt);
            LDMX4(blf[np][0],blf[np][1],blf[np][2],blf[np][3], sb + G1_BL + brow + bt);
        }
        #pragma unroll
        for (int mt = 0; mt < 2; mt++) {
            uint32_t at = (uint32_t)(mt*16*G1_LDK)*2 + (uint32_t)(ks*16)*2;
            uint32_t ah0,ah1,ah2,ah3, al0,al1,al2,al3;
            LDMX4(ah0,ah1,ah2,ah3, sb + G1_AH + arow + at);
            LDMX4(al0,al1,al2,al3, sb + G1_AL + arow + at);
            #pragma unroll
            for (int np = 0; np < 2; np++) {
                MMA16816(c[mt][np*2],   ah0,ah1,ah2,ah3, bhf[np][0],bhf[np][1]);
                MMA16816(c[mt][np*2],   al0,al1,al2,al3, bhf[np][0],bhf[np][1]);
                MMA16816(c[mt][np*2],   ah0,ah1,ah2,ah3, blf[np][0],blf[np][1]);
                MMA16816(c[mt][np*2+1], ah0,ah1,ah2,ah3, bhf[np][2],bhf[np][3]);
                MMA16816(c[mt][np*2+1], al0,al1,al2,al3, bhf[np][2],bhf[np][3]);
                MMA16816(c[mt][np*2+1], ah0,ah1,ah2,ah3, blf[np][2],blf[np][3]);
            }
        }
    }

    const int bb = m0 >> 11, s0 = m0 & (Sv-1), hh = n0 >> 7;
    const int bh = bb*Hv + hh;
    const int g = lane >> 2, tg = lane & 3;
    float* red = (float*)(dynsmem + G1_RED);
    const float* sa1 = (const float*)(dynsmem + G1_SA);
    const float* sa2 = sa1 + 128;

    float pe1[2][2] = {}, pe2[2][2] = {};
    #pragma unroll
    for (int mt = 0; mt < 2; mt++) {
        #pragma unroll
        for (int nt = 0; nt < 4; nt++) {
            int d = wn*32 + nt*8 + tg*2;
            float b0 = bias[n0 + d], b1 = bias[n0 + d + 1];
            float a10 = sa1[d], a11 = sa1[d+1];
            float a20 = sa2[d], a21 = sa2[d+1];
            #pragma unroll
            for (int half = 0; half < 2; half++) {
                int r = wm*32 + mt*16 + half*8 + g;
                float v0 = c[mt][nt][half*2]   + b0;
                float v1 = c[mt][nt][half*2+1] + b1;
                *(float2*)(g_hp + ((size_t)bh*Sv + s0 + r)*Dv + d) = make_float2(v0, v1);
                pe1[mt][half] += v0*a10 + v1*a11;
                pe2[mt][half] += v0*a20 + v1*a21;
            }
        }
    }
    #pragma unroll
    for (int mt = 0; mt < 2; mt++) {
        #pragma unroll
        for (int half = 0; half < 2; half++) {
            float e1 = pe1[mt][half], e2 = pe2[mt][half];
            e1 += __shfl_xor_sync(0xffffffffu, e1, 1);
            e1 += __shfl_xor_sync(0xffffffffu, e1, 2);
            e2 += __shfl_xor_sync(0xffffffffu, e2, 1);
            e2 += __shfl_xor_sync(0xffffffffu, e2, 2);
            if (tg == 0) {
                int r = wm*32 + mt*16 + half*8 + g;
                red[(r*4 + wn)*2 + 0] = e1;
                red[(r*4 + wn)*2 + 1] = e2;
            }
        }
    }
    __syncthreads();
    if (tid < 128) {
        int r = tid;
        float e1 = red[(r*4+0)*2] + red[(r*4+1)*2] + red[(r*4+2)*2] + red[(r*4+3)*2];
        float e2 = red[(r*4+0)*2+1] + red[(r*4+1)*2+1] + red[(r*4+2)*2+1] + red[(r*4+3)*2+1];
        int s = s0 + r;
        int row = bh*Sv + s;
        g_e1[row] = e1;
        g_e2[row] = e2;
        int msk = g_masked[bb*Sv + s];
        g_E2p[row] = msk ? 0.f : expf(e2);
        g_E2n[row] = msk ? 0.f : expf(NEG*e2);
    }
}

// ---------------------------------------------------------------
// K2: per (b,h) softmax prep. Hybrid register/shfl/smem bitonic
// sort of (key|idx) u64, then scans + bsearch.
// ---------------------------------------------------------------
#define P_SKEY 0u
#define P_KEYF 16384u
#define P_V1   24576u
#define P_V2   32768u
#define P_PREN 40960u
#define P_SUFP 49408u
#define P_CH1  57856u
#define P_CH2  58112u
#define PREP_SMEM 58880

__device__ __forceinline__ uint32_t f2sort(float f) {
    uint32_t u = __float_as_uint(f);
    return (u & 0x80000000u) ? ~u : (u | 0x80000000u);
}
__device__ __forceinline__ float sort2f(uint32_t s) {
    uint32_t u = (s & 0x80000000u) ? (s ^ 0x80000000u) : ~s;
    return __uint_as_float(u);
}
__device__ __forceinline__ unsigned long long bsel(
    unsigned long long a, unsigned long long p, bool up, bool lower) {
    unsigned long long mn = a < p ? a : p;
    unsigned long long mx = a < p ? p : a;
    return (up == lower) ? mn : mx;
}

__global__ __launch_bounds__(1024) void k_prep(const float* __restrict__ ab_p) {
    unsigned long long* skey = (unsigned long long*)(dynsmem + P_SKEY);
    float* keyf = (float*)(dynsmem + P_KEYF);
    float* v1   = (float*)(dynsmem + P_V1);
    float* v2   = (float*)(dynsmem + P_V2);
    float* pren = (float*)(dynsmem + P_PREN);
    float* sufp = (float*)(dynsmem + P_SUFP);
    float* ch1  = (float*)(dynsmem + P_CH1);
    float* ch2  = (float*)(dynsmem + P_CH2);

    const int bh = blockIdx.x;
    const int b  = bh >> 2;
    const int tid = threadIdx.x;
    const float ab = ab_p[0];

    // each thread owns elements 2*tid, 2*tid+1 in registers
    unsigned long long r0, r1;
    {
        int j0 = 2*tid, j1 = 2*tid + 1;
        float e20 = g_e2[bh*Sv + j0], e21 = g_e2[bh*Sv + j1];
        float k0 = g_masked[b*Sv + j0] ? -1e30f : e20;
        float k1 = g_masked[b*Sv + j1] ? -1e30f : e21;
        r0 = ((unsigned long long)f2sort(k0) << 32) | (unsigned)j0;
        r1 = ((unsigned long long)f2sort(k1) << 32) | (unsigned)j1;
    }

    // bitonic: j==1 in-thread, j<=32 shfl, j>=64 smem
    for (int k = 2; k <= Sv; k <<= 1) {
        const bool up = (((2*tid) & k) == 0);
        for (int j = k >> 1; j > 0; j >>= 1) {
            if (j == 1) {
                if ((r0 > r1) == up) { unsigned long long t = r0; r0 = r1; r1 = t; }
            } else if (j <= 32) {
                int m = j >> 1;
                unsigned long long p0 = __shfl_xor_sync(0xffffffffu, r0, m);
                unsigned long long p1 = __shfl_xor_sync(0xffffffffu, r1, m);
                bool lower = ((tid & m) == 0);
                r0 = bsel(r0, p0, up, lower);
                r1 = bsel(r1, p1, up, lower);
            } else {
                __syncthreads();
                skey[2*tid] = r0; skey[2*tid+1] = r1;
                __syncthreads();
                int pt = tid ^ (j >> 1);
                unsigned long long p0 = skey[2*pt];
                unsigned long long p1 = skey[2*pt+1];
                bool lower = ((tid & (j >> 1)) == 0);
                r0 = bsel(r0, p0, up, lower);
                r1 = bsel(r1, p1, up, lower);
            }
        }
    }
    __syncthreads();
    skey[2*tid] = r0; skey[2*tid+1] = r1;
    __syncthreads();

    for (int n = tid; n < Sv; n += 1024) {
        unsigned long long kv = skey[n];
        float kf = sort2f((uint32_t)(kv >> 32));
        int jj = (int)(kv & 0xffffffffu);
        float ep = expf(kf), en = expf(NEG*kf);
        keyf[n] = kf; v1[n] = ep; v2[n] = en;
        g_perm[bh*Sv + n] = jj;
        g_sEp[bh*Sv + n] = ep;
        g_sEn[bh*Sv + n] = en;
    }
    __syncthreads();

    const float M2 = keyf[Sv-1];

    if (tid < 64) {
        int base = tid * 32;
        float s1 = 0.f, s2 = 0.f;
        for (int t = 0; t < 32; t++) { s1 += v1[base+t]; s2 += v2[base+t]; }
        ch1[tid] = s1; ch2[tid] = s2;
    }
    __syncthreads();
    if (tid == 0) {
        float r = 0.f;
        for (int c = 0; c < 64; c++) { float t = ch2[c]; ch2[c] = r; r += t; }
        pren[Sv] = r;
        r = 0.f;
        for (int c = 63; c >= 0; c--) { float t = ch1[c]; ch1[c] = r; r += t; }
    }
    __syncthreads();
    if (tid < 64) {
        int base = tid * 32;
        float run = ch2[tid];
        for (int t = 0; t < 32; t++) { pren[base+t] = run; run += v2[base+t]; }
        float runs = ch1[tid];
        for (int t = 31; t >= 0; t--) { runs += v1[base+t]; sufp[base+t] = runs; }
    }
    if (tid == 0) sufp[Sv] = 0.f;
    __syncthreads();

    for (int i = tid; i < Sv; i += 1024) {
        float e1 = g_e1[bh*Sv + i];
        float eb = e1 + ab;
        float pre = eb + M2;
        float m = (pre > 0.f) ? pre : NEG*pre;
        float th = -eb;
        float A  = expf(eb - m);
        float Bc = expf(NEG*eb - m);
        int lo = 0, hi = Sv;
        while (lo < hi) {
            int mid = (lo + hi) >> 1;
            if (keyf[mid] <= th) lo = mid + 1; else hi = mid;
        }
        float rowsum = A*sufp[lo] + Bc*pren[lo];
        float inv = 1.0f / rowsum;
        g_An[bh*Sv + i] = A * inv;
        g_Bn[bh*Sv + i] = Bc * inv;
        g_th[bh*Sv + i] = th;
        g_lo[bh*Sv + i] = lo;
    }
}

// ---------------------------------------------------------------
// K3a-1: segment sums
// ---------------------------------------------------------------
__global__ __launch_bounds__(128) void k_scan1() {
    __shared__ float wv[256];
    __shared__ int pm[256];
    const int blk = blockIdx.x;
    const int seg = blk & 7;
    const int dir = (blk >> 3) & 1;
    const int bh  = blk >> 4;
    const int d = threadIdx.x;
    const int n0 = seg * 256;
    const float* src = dir ? (g_sEp + bh*Sv) : (g_sEn + bh*Sv);
    for (int t = d; t < 256; t += 128) {
        wv[t] = src[n0 + t];
        pm[t] = g_perm[bh*Sv + n0 + t];
    }
    __syncthreads();
    const float* hp = g_hp + (size_t)bh*Sv*Dv;
    float a0=0.f, a1=0.f, a2=0.f, a3=0.f;
    for (int t = 0; t < 256; t += 4) {
        a0 += wv[t+0]*hp[(size_t)pm[t+0]*Dv + d];
        a1 += wv[t+1]*hp[(size_t)pm[t+1]*Dv + d];
        a2 += wv[t+2]*hp[(size_t)pm[t+2]*Dv + d];
        a3 += wv[t+3]*hp[(size_t)pm[t+3]*Dv + d];
    }
    g_segsum[(size_t)blk*Dv + d] = (a0 + a1) + (a2 + a3);
}

// ---------------------------------------------------------------
// K3a-2: local scan with segment offsets -> PRE/SUF
// ---------------------------------------------------------------
__global__ __launch_bounds__(128) void k_scan2() {
    __shared__ float wv[256];
    __shared__ int pm[256];
    const int blk = blockIdx.x;
    const int seg = blk & 7;
    const int dir = (blk >> 3) & 1;
    const int bh  = blk >> 4;
    const int d = threadIdx.x;
    const int n0 = seg * 256;
    const float* src = dir ? (g_sEp + bh*Sv) : (g_sEn + bh*Sv);
    for (int t = d; t < 256; t += 128) {
        wv[t] = src[n0 + t];
        pm[t] = g_perm[bh*Sv + n0 + t];
    }
    __syncthreads();
    const float* hp = g_hp + (size_t)bh*Sv*Dv;
    const int base = (bh*2 + dir) * 8;
    float acc = 0.f;
    if (dir == 0) {
        for (int ss = 0; ss < seg; ss++) acc += g_segsum[(size_t)(base+ss)*Dv + d];
        float* pre = g_pre + (size_t)bh*2049*Dv;
        for (int t = 0; t < 256; t += 8) {
            float vals[8];
            #pragma unroll
            for (int k = 0; k < 8; k++) vals[k] = hp[(size_t)pm[t+k]*Dv + d];
            #pragma unroll
            for (int k = 0; k < 8; k++) {
                pre[(size_t)(n0+t+k)*Dv + d] = acc;
                acc += wv[t+k]*vals[k];
            }
        }
        if (seg == 7) pre[(size_t)Sv*Dv + d] = acc;
    } else {
        for (int ss = seg+1; ss < 8; ss++) acc += g_segsum[(size_t)(base+ss)*Dv + d];
        float* suf = g_suf + (size_t)bh*2049*Dv;
        if (seg == 7) suf[(size_t)Sv*Dv + d] = 0.f;
        for (int t = 248; t >= 0; t -= 8) {
            float vals[8];
            #pragma unroll
            for (int k = 7; k >= 0; k--) vals[k] = hp[(size_t)pm[t+k]*Dv + d];
            #pragma unroll
            for (int k = 7; k >= 0; k--) {
                acc += wv[t+k]*vals[k];
                suf[(size_t)(n0+t+k)*Dv + d] = acc;
            }
        }
    }
}

// ---------------------------------------------------------------
// K3b: attn write — streaming stores (evict-first), side stream
// ---------------------------------------------------------------
__global__ __launch_bounds__(256) void k_attnw(float* __restrict__ attn_out) {
    const int row = blockIdx.x;
    const int bh = row >> 11;
    const int tid = threadIdx.x;
    const float th = g_th[row], An = g_An[row], Bn = g_Bn[row];
    const float* e2b = g_e2  + bh*Sv;
    const float* epb = g_E2p + bh*Sv;
    const float* enb = g_E2n + bh*Sv;
    float* dst = attn_out + (size_t)row * Sv;
    #pragma unroll
    for (int t = 0; t < 2; t++) {
        int j = (tid + t*256) * 4;
        float4 e2v = *(const float4*)(e2b + j);
        float4 epv = *(const float4*)(epb + j);
        float4 env = *(const float4*)(enb + j);
        float4 p;
        p.x = (e2v.x > th) ? An*epv.x : Bn*env.x;
        p.y = (e2v.y > th) ? An*epv.y : Bn*env.y;
        p.z = (e2v.z > th) ? An*epv.z : Bn*env.z;
        p.w = (e2v.w > th) ? An*epv.w : Bn*env.w;
        __stcs((float4*)(dst + j), p);
    }
}

// ---------------------------------------------------------------
// K3c: ctx gather -> bf16 hi/lo
// ---------------------------------------------------------------
__global__ __launch_bounds__(256) void k_gather() {
    const int row = blockIdx.x * 8 + (threadIdx.x >> 5);
    const int lane = threadIdx.x & 31;
    const int bh = row >> 11, i = row & (Sv-1);
    const int b = bh >> 2, hh = bh & 3;
    const int lo = g_lo[row];
    const float An = g_An[row], Bn = g_Bn[row];
    float4 sv = *(const float4*)(g_suf + ((size_t)bh*2049 + lo)*Dv + lane*4);
    float4 pv = *(const float4*)(g_pre + ((size_t)bh*2049 + lo)*Dv + lane*4);
    float x = An*sv.x + Bn*pv.x;
    float y = An*sv.y + Bn*pv.y;
    float z = An*sv.z + Bn*pv.z;
    float ww = An*sv.w + Bn*pv.w;
    size_t o = ((size_t)(b*Sv + i))*HDv + hh*Dv + lane*4;
    *(uint2*)(g_ctxb_hi + o) = make_uint2(pack_hi2(x,y), pack_hi2(z,ww));
    *(uint2*)(g_ctxb_lo + o) = make_uint2(pack_lo2(x,y), pack_lo2(z,ww));
}

// ---------------------------------------------------------------
// K4: out = relu(ctx @ out_w^T + out_b) via bf16 3-split mma.sync.
// ---------------------------------------------------------------
#define G2_LDK 72
#define G2_AT (64*G2_LDK*2)
#define G2_BT (128*G2_LDK*2)
#define G2_BUF (2*G2_AT + 2*G2_BT)
#define G2_AH(q) ((uint32_t)((q)*G2_BUF))
#define G2_AL(q) ((uint32_t)((q)*G2_BUF + G2_AT))
#define G2_BH(q) ((uint32_t)((q)*G2_BUF + 2*G2_AT))
#define G2_BL(q) ((uint32_t)((q)*G2_BUF + 2*G2_AT + G2_BT))
#define G2_SMEM (2*G2_BUF)

__device__ __forceinline__ void g2_fill(int m0, int ch, uint32_t sb, int q, int tid) {
    const int k0 = ch * 64;
    #pragma unroll
    for (int t = 0; t < 4; t++) {
        int idx = tid + t*256;
        int p  = idx >> 9;
        int r  = (idx >> 3) & 63;
        int c8 = (idx & 7) * 8;
        const __nv_bfloat16* src = (p ? g_ctxb_lo : g_ctxb_hi)
            + (size_t)(m0 + r)*HDv + k0 + c8;
        CP16(sb + (p ? G2_AL(q) : G2_AH(q)) + (uint32_t)(r*G2_LDK + c8)*2, src);
    }
    #pragma unroll
    for (int t = 0; t < 8; t++) {
        int idx = tid + t*256;
        int p  = idx >> 10;
        int r  = (idx >> 3) & 127;
        int c8 = (idx & 7) * 8;
        const __nv_bfloat16* src = (p ? g_wb_lo : g_wb_hi)
            + (size_t)r*HDv + k0 + c8;
        CP16(sb + (p ? G2_BL(q) : G2_BH(q)) + (uint32_t)(r*G2_LDK + c8)*2, src);
    }
}

__global__ __launch_bounds__(256, 1) void k_gemm2t(const float* __restrict__ bias,
                                                   float* __restrict__ out) {
    const int m0 = blockIdx.x * 64;
    const int tid = threadIdx.x;
    const int w = tid >> 5, lane = tid & 31;
    const uint32_t sb = smem_u32(dynsmem);

    g2_fill(m0, 0, sb, 0, tid);
    CP_COMMIT();

    const int wm = w >> 2, wn = w & 3;
    const uint32_t arow = (uint32_t)((wm*32 + (lane & 15))*G2_LDK + (lane >> 4)*8) * 2;
    const uint32_t brow = (uint32_t)(((lane & 7) + ((lane >> 4) << 3))*G2_LDK
                                     + (((lane >> 3) & 1)*8)) * 2;
    float c[2][4][4] = {};

    #pragma unroll 1
    for (int ch = 0; ch < 8; ch++) {
        const int q = ch & 1;
        if (ch < 7) { g2_fill(m0, ch+1, sb, q^1, tid); CP_COMMIT(); CP_WAIT1(); }
        else        { CP_WAIT0(); }
        __syncthreads();

        #pragma unroll
        for (int ks = 0; ks < 4; ks++) {
            uint32_t bhf[2][4], blf[2][4];
            #pragma unroll
            for (int np = 0; np < 2; np++) {
                uint32_t bt = (uint32_t)((wn*32 + np*16)*G2_LDK)*2 + (uint32_t)(ks*16)*2;
                LDMX4(bhf[np][0],bhf[np][1],bhf[np][2],bhf[np][3], sb + G2_BH(q) + brow + bt);
                LDMX4(blf[np][0],blf[np][1],blf[np][2],blf[np][3], sb + G2_BL(q) + brow + bt);
            }
            #pragma unroll
            for (int mt = 0; mt < 2; mt++) {
                uint32_t at = (uint32_t)(mt*16*G2_LDK)*2 + (uint32_t)(ks*16)*2;
                uint32_t ah0,ah1,ah2,ah3, al0,al1,al2,al3;
                LDMX4(ah0,ah1,ah2,ah3, sb + G2_AH(q) + arow + at);
                LDMX4(al0,al1,al2,al3, sb + G2_AL(q) + arow + at);
                #pragma unroll
                for (int np = 0; np < 2; np++) {
                    MMA16816(c[mt][np*2],   ah0,ah1,ah2,ah3, bhf[np][0],bhf[np][1]);
                    MMA16816(c[mt][np*2],   al0,al1,al2,al3, bhf[np][0],bhf[np][1]);
                    MMA16816(c[mt][np*2],   ah0,ah1,ah2,ah3, blf[np][0],blf[np][1]);
                    MMA16816(c[mt][np*2+1], ah0,ah1,ah2,ah3, bhf[np][2],bhf[np][3]);
                    MMA16816(c[mt][np*2+1], al0,al1,al2,al3, bhf[np][2],bhf[np][3]);
                    MMA16816(c[mt][np*2+1], ah0,ah1,ah2,ah3, blf[np][2],blf[np][3]);
                }
            }
        }
        __syncthreads();
    }

    {
        const int g = lane >> 2, tg = lane & 3;
        #pragma unroll
        for (int mt = 0; mt < 2; mt++) {
            int r0 = m0 + wm*32 + mt*16 + g;
            #pragma unroll
            for (int nt = 0; nt < 4; nt++) {
                int n = wn*32 + nt*8 + tg*2;
                float b0 = bias[n], b1 = bias[n+1];
                float v0 = c[mt][nt][0] + b0, v1 = c[mt][nt][1] + b1;
                float v2 = c[mt][nt][2] + b0, v3 = c[mt][nt][3] + b1;
                *(float2*)(out + (size_t)r0*OUTv + n) =
                    make_float2(v0 > 0.f ? v0 : 0.f, v1 > 0.f ? v1 : 0.f);
                *(float2*)(out + (size_t)(r0+8)*OUTv + n) =
                    make_float2(v2 > 0.f ? v2 : 0.f, v3 > 0.f ? v3 : 0.f);
            }
        }
    }
}

// ---------------------------------------------------------------
extern "C" void kernel_launch(void* const* d_in, const int* in_sizes, int n_in,
                              void* d_out, int out_size) {
    const float* h     = (const float*)d_in[0];
    const void*  mask  = d_in[1];
    const float* W_w   = (const float*)d_in[2];
    const float* W_b   = (const float*)d_in[3];
    const float* a_w   = (const float*)d_in[4];
    const float* a_b   = (const float*)d_in[5];
    const float* out_w = (const float*)d_in[6];
    const float* out_b = (const float*)d_in[7];

    float* out  = (float*)d_out;
    float* attn = out + (size_t)Bv*Sv*OUTv;

    static int init_done = 0;
    static cudaStream_t s2;
    static cudaEvent_t evF0, evW, evF2, evJoin;
    if (!init_done) {
        cudaFuncSetAttribute(k_gemm1t, cudaFuncAttributeMaxDynamicSharedMemorySize, G1_SMEM);
        cudaFuncSetAttribute(k_prep,   cudaFuncAttributeMaxDynamicSharedMemorySize, PREP_SMEM);
        cudaFuncSetAttribute(k_gemm2t, cudaFuncAttributeMaxDynamicSharedMemorySize, G2_SMEM);
        cudaStreamCreateWithFlags(&s2, cudaStreamNonBlocking);
        cudaEventCreateWithFlags(&evF0,   cudaEventDisableTiming);
        cudaEventCreateWithFlags(&evW,    cudaEventDisableTiming);
        cudaEventCreateWithFlags(&evF2,   cudaEventDisableTiming);
        cudaEventCreateWithFlags(&evJoin, cudaEventDisableTiming);
        init_done = 1;
    }

    // fork 0: out_w conversion overlaps mask + gemm1t
    cudaEventRecord(evF0, 0);
    cudaStreamWaitEvent(s2, evF0, 0);
    k_wcvt  <<<64, 256, 0, s2>>>(out_w);
    cudaEventRecord(evW, s2);

    k_mask  <<<1, 256>>>(mask);
    k_gemm1t<<<dim3(64, 4), 512, G1_SMEM>>>(h, W_w, W_b, a_w);
    k_prep  <<<BHv, 1024, PREP_SMEM>>>(a_b);

    // fork 2: attn write overlaps scan/gather/gemm2 branch
    cudaEventRecord(evF2, 0);
    cudaStreamWaitEvent(s2, evF2, 0);
    k_attnw <<<NSv, 256, 0, s2>>>(attn);
    cudaEventRecord(evJoin, s2);

    k_scan1 <<<256, 128>>>();
    k_scan2 <<<256, 128>>>();
    k_gather<<<NSv/8, 256>>>();
    cudaStreamWaitEvent(0, evW, 0);      // gemm2t needs wcvt only
    k_gemm2t<<<128, 256, G2_SMEM>>>(out_b, out);

    // join attnw
    cudaStreamWaitEvent(0, evJoin, 0);
}